// round 7
// baseline (speedup 1.0000x reference)
#include <cuda_runtime.h>
#include <cuda_bf16.h>
#include <cuda_fp16.h>
#include <cstdint>
#include <math.h>

#define NN 100000
#define HH 20000
#define EE 1600000
#define DD 64
#define FF 256
#define LL 3

typedef unsigned short u16;

// ---------------- helpers ----------------------------------------------------
__device__ __forceinline__ uint32_t smem_u32(const void* p) {
    uint32_t a;
    asm("{ .reg .u64 t; cvta.to.shared.u64 t, %1; cvt.u32.u64 %0, t; }" : "=r"(a) : "l"(p));
    return a;
}
__device__ __forceinline__ void ldsm_x4(uint32_t* r, uint32_t addr) {
    asm volatile("ldmatrix.sync.aligned.m8n8.x4.shared.b16 {%0,%1,%2,%3}, [%4];"
                 : "=r"(r[0]), "=r"(r[1]), "=r"(r[2]), "=r"(r[3]) : "r"(addr));
}
// DT 0 = bf16, 1 = fp16
template<int DT>
__device__ __forceinline__ void mma16816(float* d, const uint32_t* a, const uint32_t* b) {
    if (DT == 0)
        asm volatile("mma.sync.aligned.m16n8k16.row.col.f32.bf16.bf16.f32 "
                     "{%0,%1,%2,%3}, {%4,%5,%6,%7}, {%8,%9}, {%0,%1,%2,%3};"
                     : "+f"(d[0]), "+f"(d[1]), "+f"(d[2]), "+f"(d[3])
                     : "r"(a[0]), "r"(a[1]), "r"(a[2]), "r"(a[3]), "r"(b[0]), "r"(b[1]));
    else
        asm volatile("mma.sync.aligned.m16n8k16.row.col.f32.f16.f16.f32 "
                     "{%0,%1,%2,%3}, {%4,%5,%6,%7}, {%8,%9}, {%0,%1,%2,%3};"
                     : "+f"(d[0]), "+f"(d[1]), "+f"(d[2]), "+f"(d[3])
                     : "r"(a[0]), "r"(a[1]), "r"(a[2]), "r"(a[3]), "r"(b[0]), "r"(b[1]));
}
__device__ __forceinline__ void split2(float a, float b, uint32_t& hi, uint32_t& lo) {
    __nv_bfloat16 ha = __float2bfloat16(a), hb = __float2bfloat16(b);
    float ra = a - __bfloat162float(ha);
    float rb = b - __bfloat162float(hb);
    __nv_bfloat16 la = __float2bfloat16(ra), lb = __float2bfloat16(rb);
    hi = (uint32_t)__bfloat16_as_ushort(ha) | ((uint32_t)__bfloat16_as_ushort(hb) << 16);
    lo = (uint32_t)__bfloat16_as_ushort(la) | ((uint32_t)__bfloat16_as_ushort(lb) << 16);
}
__device__ __forceinline__ uint32_t pack_bf16(float lo, float hi) {
    uint32_t r;
    asm("cvt.rn.bf16x2.f32 %0, %1, %2;" : "=r"(r) : "f"(hi), "f"(lo));
    return r;
}
__device__ __forceinline__ uint32_t pack_f16(float lo, float hi) {
    __half2 h = __floats2half2_rn(lo, hi);
    return *(uint32_t*)&h;
}

// ---------------- scratch ----------------------------------------------------
__device__ __align__(16) float g_h  [NN * DD];
__device__ __align__(16) float g_b1 [NN * DD];
__device__ __align__(16) float g_b2 [NN * DD];
__device__ __align__(16) float g_ha [HH * DD];
__device__ __align__(16) float g_hb [HH * DD];
__device__ __align__(16) u16 g_yhi [HH * DD];    // y split planes (bf16)
__device__ __align__(16) u16 g_ylo [HH * DD];
__device__ __align__(16) u16 g_thi [NN * FF];    // FFN hidden (fp16, single plane)
// pre-split transposed weights [N][K]
__device__ __align__(16) u16 g_wa_hi[LL * DD * DD];   // bf16
__device__ __align__(16) u16 g_wa_lo[LL * DD * DD];
__device__ __align__(16) u16 g_wb_hi[LL * DD * DD];   // bf16
__device__ __align__(16) u16 g_wb_lo[LL * DD * DD];
__device__ __align__(16) u16 g_w1_hi[LL * DD * FF];   // fp16
__device__ __align__(16) u16 g_w1_lo[LL * DD * FF];
__device__ __align__(16) u16 g_w2_hi[LL * FF * DD];   // fp16
__device__ __align__(16) u16 g_w2_lo[LL * FF * DD];
__device__ __align__(16) u16 g_wo_hi[DD * DD];        // bf16
__device__ __align__(16) u16 g_wo_lo[DD * DD];
__device__ float g_invn[NN];
__device__ float g_invh[HH];
__device__ int g_cntH [HH];
__device__ int g_cntN [NN];
__device__ int g_startH[HH];
__device__ int g_startN[NN];
__device__ int g_curH [HH];
__device__ int g_curN [NN];
__device__ int g_csrH [EE];
__device__ int g_csrN [EE];

// ---------------- weight prep: fp32 [l][K][N] -> hi/lo [l][N][K] ------------
template<int DT>
__global__ void k_prep(const float* __restrict__ src, int K, int N, int total,
                       u16* __restrict__ hi, u16* __restrict__ lo) {
    int idx = blockIdx.x * blockDim.x + threadIdx.x;
    if (idx >= total) return;
    int KN = K * N;
    int l = idx / KN;
    int r = idx - l * KN;
    int k = r / N, n = r - k * N;
    float v = src[idx];
    u16 h_bits, l_bits;
    if (DT == 0) {
        __nv_bfloat16 h = __float2bfloat16(v);
        float res = v - __bfloat162float(h);
        h_bits = __bfloat16_as_ushort(h);
        l_bits = __bfloat16_as_ushort(__float2bfloat16(res));
    } else {
        __half h = __float2half_rn(v);
        float res = v - __half2float(h);
        h_bits = __half_as_ushort(h);
        l_bits = __half_as_ushort(__float2half_rn(res));
    }
    size_t o = (size_t)l * KN + (size_t)n * K + k;
    hi[o] = h_bits;
    lo[o] = l_bits;
}

// ---------------- CSR build --------------------------------------------------
__global__ void k_zeroi(int* __restrict__ p, int n) {
    int i = blockIdx.x * blockDim.x + threadIdx.x;
    int stride = gridDim.x * blockDim.x;
    for (; i < n; i += stride) p[i] = 0;
}

__global__ void k_hist(const int* __restrict__ src, const int* __restrict__ dst,
                       int* __restrict__ cntN, int* __restrict__ cntH) {
    int e = blockIdx.x * blockDim.x + threadIdx.x;
    if (e < EE) {
        atomicAdd(&cntN[src[e]], 1);
        atomicAdd(&cntH[dst[e]], 1);
    }
}

__global__ void k_scan(const int* __restrict__ cnt, int* __restrict__ start, int n) {
    __shared__ int shw[33];
    __shared__ int sh_carry;
    const int tid = threadIdx.x;
    const int lane = tid & 31, warp = tid >> 5;
    if (tid == 0) sh_carry = 0;
    __syncthreads();
    for (int base = 0; base < n; base += 1024) {
        int i = base + tid;
        int v = (i < n) ? cnt[i] : 0;
        int inc = v;
        #pragma unroll
        for (int o = 1; o < 32; o <<= 1) {
            int t = __shfl_up_sync(0xffffffffu, inc, o);
            if (lane >= o) inc += t;
        }
        if (lane == 31) shw[warp] = inc;
        __syncthreads();
        if (warp == 0) {
            int t = shw[lane];
            int winc = t;
            #pragma unroll
            for (int o = 1; o < 32; o <<= 1) {
                int u = __shfl_up_sync(0xffffffffu, winc, o);
                if (lane >= o) winc += u;
            }
            shw[lane] = winc - t;
            if (lane == 31) shw[32] = winc;
        }
        __syncthreads();
        int carry = sh_carry;
        if (i < n) start[i] = carry + shw[warp] + inc - v;
        __syncthreads();
        if (tid == 0) sh_carry = carry + shw[32];
        __syncthreads();
    }
}

__global__ void k_fill(const int* __restrict__ src, const int* __restrict__ dst,
                       const int* __restrict__ startH, const int* __restrict__ startN,
                       int* __restrict__ curH, int* __restrict__ curN,
                       int* __restrict__ csrH, int* __restrict__ csrN) {
    int e = blockIdx.x * blockDim.x + threadIdx.x;
    if (e < EE) {
        int s = src[e], d = dst[e];
        int p = atomicAdd(&curH[d], 1);
        csrH[startH[d] + p] = s;
        int q = atomicAdd(&curN[s], 1);
        csrN[startN[s] + q] = d;
    }
}

__global__ void k_inv(const int* __restrict__ cntN, const int* __restrict__ cntH,
                      float* __restrict__ invn, float* __restrict__ invh) {
    int i = blockIdx.x * blockDim.x + threadIdx.x;
    if (i < NN) invn[i] = rsqrtf(fmaxf((float)cntN[i], 1.0f));
    if (i < HH) invh[i] = rsqrtf(fmaxf((float)cntH[i], 1.0f));
}

// ---------------- gather aggregation ----------------------------------------
__global__ void k_agg(const float* __restrict__ Y, const int* __restrict__ csr,
                      const int* __restrict__ start, const int* __restrict__ cnt,
                      const float* __restrict__ scale, float* __restrict__ out, int M) {
    const int warp = threadIdx.x >> 5;
    const int lane = threadIdx.x & 31;
    const int row = blockIdx.x * (blockDim.x >> 5) + warp;
    if (row >= M) return;
    const int half = lane >> 4;
    const int q = lane & 15;
    const int s0 = start[row];
    const int c  = cnt[row];
    const float4* __restrict__ Y4 = (const float4*)Y;

    float4 acc = make_float4(0.f, 0.f, 0.f, 0.f);
    int j = half;
    for (; j + 2 < c; j += 4) {
        int sa = __ldg(&csr[s0 + j]);
        int sb = __ldg(&csr[s0 + j + 2]);
        float4 va = Y4[(size_t)sa * 16 + q];
        float4 vb = Y4[(size_t)sb * 16 + q];
        if (scale) {
            float fa = __ldg(&scale[sa]), fb = __ldg(&scale[sb]);
            va.x *= fa; va.y *= fa; va.z *= fa; va.w *= fa;
            vb.x *= fb; vb.y *= fb; vb.z *= fb; vb.w *= fb;
        }
        acc.x += va.x; acc.y += va.y; acc.z += va.z; acc.w += va.w;
        acc.x += vb.x; acc.y += vb.y; acc.z += vb.z; acc.w += vb.w;
    }
    if (j < c) {
        int sa = __ldg(&csr[s0 + j]);
        float4 va = Y4[(size_t)sa * 16 + q];
        if (scale) {
            float fa = __ldg(&scale[sa]);
            va.x *= fa; va.y *= fa; va.z *= fa; va.w *= fa;
        }
        acc.x += va.x; acc.y += va.y; acc.z += va.z; acc.w += va.w;
    }
    acc.x += __shfl_xor_sync(0xffffffffu, acc.x, 16);
    acc.y += __shfl_xor_sync(0xffffffffu, acc.y, 16);
    acc.z += __shfl_xor_sync(0xffffffffu, acc.z, 16);
    acc.w += __shfl_xor_sync(0xffffffffu, acc.w, 16);
    if (half == 0) ((float4*)out)[(size_t)row * 16 + q] = acc;
}

// ---------------- HMMA GEMM --------------------------------------------------
// AMODE: 0 = fp32 A -> bf16 split (3-term) | 1 = pre-split bf16 planes (3-term)
//        2 = single u16 plane copy (2-term) | 3 = fp32 A -> fp16 plane (2-term)
// POST:  0 = fp32 C | 1 = fp32 C + bvec
//        3 = y=(v*rs[r]+bvec[c])*rs[r] -> bf16 split Chi/Clo
//        4 = relu(v+bvec[c]) -> fp16 Chi
// DT: 0 = bf16 mma, 1 = fp16 mma
template<int KT, int NT, int AMODE, int POST, int DT>
__global__ void __launch_bounds__(256, 1)
k_mma(const float* __restrict__ A, const u16* __restrict__ Ahi_g,
      const u16* __restrict__ Alo_g,
      const u16* __restrict__ Whi_g, const u16* __restrict__ Wlo_g,
      const float* __restrict__ rs, const float* __restrict__ bvec,
      float* __restrict__ C, u16* __restrict__ Chi_g, u16* __restrict__ Clo_g,
      int M) {
    constexpr int KP = KT + 8;
    constexpr bool THREE = (AMODE <= 1);
    constexpr int A_ELEMS = 128 * KP;
    constexpr int B_ELEMS = NT * KP;
    extern __shared__ __align__(16) u16 sm[];
    u16* Ahi = sm;
    u16* Alo = THREE ? (Ahi + A_ELEMS) : Ahi;
    u16* Bhi = (THREE ? Alo : Ahi) + A_ELEMS;
    u16* Blo = Bhi + B_ELEMS;

    const int tid = threadIdx.x;
    const int wid = tid >> 5, lane = tid & 31;
    const int row0 = blockIdx.x * 128;

    // ---- fill A ----
    if (AMODE == 0 || AMODE == 3) {
        constexpr int KH = KT / 2;
        for (int idx = tid; idx < 128 * KH; idx += 256) {
            int r = idx / KH, kp = idx - r * KH, k = kp * 2;
            int gr = row0 + r;
            float a0 = 0.f, a1 = 0.f;
            if (gr < M) {
                float2 t = ((const float2*)A)[(size_t)gr * KH + kp];
                a0 = t.x; a1 = t.y;
            }
            if (AMODE == 0) {
                uint32_t hi, lo; split2(a0, a1, hi, lo);
                *(uint32_t*)&Ahi[r * KP + k] = hi;
                *(uint32_t*)&Alo[r * KP + k] = lo;
            } else {
                *(uint32_t*)&Ahi[r * KP + k] = pack_f16(a0, a1);
            }
        }
    } else {
        constexpr int K8 = KT / 8;
        const uint4 z4 = make_uint4(0, 0, 0, 0);
        for (int idx = tid; idx < 128 * K8; idx += 256) {
            int r = idx / K8, k8 = idx - r * K8;
            int gr = row0 + r;
            uint4 vh = z4;
            if (gr < M) vh = *(const uint4*)&Ahi_g[(size_t)gr * KT + k8 * 8];
            *(uint4*)&Ahi[r * KP + k8 * 8] = vh;
            if (AMODE == 1) {
                uint4 vl = z4;
                if (gr < M) vl = *(const uint4*)&Alo_g[(size_t)gr * KT + k8 * 8];
                *(uint4*)&Alo[r * KP + k8 * 8] = vl;
            }
        }
    }
    // ---- fill B (pre-split, pre-transposed [NT][KT]) ----
    {
        constexpr int K8 = KT / 8;
        for (int idx = tid; idx < NT * K8; idx += 256) {
            int n = idx / K8, k8 = idx - n * K8;
            *(uint4*)&Bhi[n * KP + k8 * 8] = *(const uint4*)&Whi_g[(size_t)n * KT + k8 * 8];
            *(uint4*)&Blo[n * KP + k8 * 8] = *(const uint4*)&Wlo_g[(size_t)n * KT + k8 * 8];
        }
    }
    __syncthreads();

    constexpr int NW = NT / 2;
    constexpr int NF = NW / 8;
    const int wm = wid & 3, wn = wid >> 2;
    const int mrow = wm * 32;
    const int ncol = wn * NW;

    float acc[2][NF][4];
    #pragma unroll
    for (int i = 0; i < 2; i++)
        #pragma unroll
        for (int nf = 0; nf < NF; nf++)
            #pragma unroll
            for (int j = 0; j < 4; j++) acc[i][nf][j] = 0.f;

    const uint32_t ahi_b = smem_u32(Ahi), alo_b = smem_u32(Alo);
    const uint32_t bhi_b = smem_u32(Bhi), blo_b = smem_u32(Blo);
    const int la  = lane & 15;
    const int lka = (lane >> 4) << 3;
    // B x4 lane map: lanes 0-7 (n,klo), 8-15 (n,khi), 16-23 (n+8,klo), 24-31 (n+8,khi)
    const int lbn = ((lane >> 4) << 3) + (lane & 7);
    const int lbk = ((lane >> 3) & 1) << 3;

    for (int kb = 0; kb < KT; kb += 16) {
        uint32_t ah[2][4], al[2][4];
        #pragma unroll
        for (int i = 0; i < 2; i++) {
            uint32_t aoff = (uint32_t)(((mrow + i * 16 + la) * KP + kb + lka) * 2);
            ldsm_x4(ah[i], ahi_b + aoff);
            if (THREE) ldsm_x4(al[i], alo_b + aoff);
        }
        #pragma unroll
        for (int nf = 0; nf < NF; nf += 2) {
            uint32_t boff = (uint32_t)(((ncol + nf * 8 + lbn) * KP + kb + lbk) * 2);
            uint32_t bh[4], bl[4];
            ldsm_x4(bh, bhi_b + boff);
            ldsm_x4(bl, blo_b + boff);
            #pragma unroll
            for (int i = 0; i < 2; i++) {
                mma16816<DT>(acc[i][nf],     ah[i], bh);
                mma16816<DT>(acc[i][nf],     ah[i], bl);
                mma16816<DT>(acc[i][nf + 1], ah[i], bh + 2);
                mma16816<DT>(acc[i][nf + 1], ah[i], bl + 2);
                if (THREE) {
                    mma16816<DT>(acc[i][nf],     al[i], bh);
                    mma16816<DT>(acc[i][nf + 1], al[i], bh + 2);
                }
            }
        }
    }

    // ---- epilogue ----
    const int qr = lane >> 2;
    const int qc = (lane & 3) * 2;
    #pragma unroll
    for (int i = 0; i < 2; i++) {
        #pragma unroll
        for (int half = 0; half < 2; half++) {
            int gr = row0 + mrow + i * 16 + half * 8 + qr;
            if (gr < M) {
                float s = (POST == 3) ? rs[gr] : 0.f;
                #pragma unroll
                for (int nf = 0; nf < NF; nf++) {
                    int c = ncol + nf * 8 + qc;
                    float v0 = acc[i][nf][half * 2 + 0];
                    float v1 = acc[i][nf][half * 2 + 1];
                    if (POST == 1) {
                        v0 += bvec[c]; v1 += bvec[c + 1];
                        *(float2*)&C[(size_t)gr * NT + c] = make_float2(v0, v1);
                    } else if (POST == 3) {
                        float y0 = (v0 * s + bvec[c]) * s;
                        float y1 = (v1 * s + bvec[c + 1]) * s;
                        uint32_t hi, lo; split2(y0, y1, hi, lo);
                        size_t w = ((size_t)gr * NT + c) >> 1;
                        ((uint32_t*)Chi_g)[w] = hi;
                        ((uint32_t*)Clo_g)[w] = lo;
                    } else if (POST == 4) {
                        float t0 = fmaxf(v0 + bvec[c], 0.f);
                        float t1 = fmaxf(v1 + bvec[c + 1], 0.f);
                        ((uint32_t*)Chi_g)[((size_t)gr * NT + c) >> 1] = pack_f16(t0, t1);
                    } else {
                        *(float2*)&C[(size_t)gr * NT + c] = make_float2(v0, v1);
                    }
                }
            }
        }
    }
}

// ---------------- LayerNorm --------------------------------------------------
template <int MODE>
__global__ void k_ln(const float* __restrict__ base, const float* __restrict__ add,
                     const float* __restrict__ rs, const float* __restrict__ bvec,
                     const float* __restrict__ g, const float* __restrict__ b,
                     float* __restrict__ out, int M) {
    const int warp = threadIdx.x >> 5;
    const int lane = threadIdx.x & 31;
    const int row = blockIdx.x * (blockDim.x >> 5) + warp;
    if (row >= M) return;
    const int i0 = row * 64 + lane;
    const int i1 = i0 + 32;

    float x0 = base[i0], x1 = base[i1];
    if (MODE == 1) {
        float s = rs[row];
        x0 = fmaf(add[i0], s, x0) + bvec[lane];
        x1 = fmaf(add[i1], s, x1) + bvec[lane + 32];
    } else if (MODE == 2) {
        x0 += add[i0];
        x1 += add[i1];
    }
    float sum = x0 + x1;
    #pragma unroll
    for (int o = 16; o; o >>= 1) sum += __shfl_xor_sync(0xffffffffu, sum, o);
    float mu = sum * (1.0f / 64.0f);
    float d0 = x0 - mu, d1 = x1 - mu;
    float vs = d0 * d0 + d1 * d1;
    #pragma unroll
    for (int o = 16; o; o >>= 1) vs += __shfl_xor_sync(0xffffffffu, vs, o);
    float inv = rsqrtf(vs * (1.0f / 64.0f) + 1e-5f);
    out[i0] = fmaf(d0 * inv, g[lane], b[lane]);
    out[i1] = fmaf(d1 * inv, g[lane + 32], b[lane + 32]);
}

// ---------------- orchestration ----------------------------------------------
extern "C" void kernel_launch(void* const* d_in, const int* in_sizes, int n_in,
                              void* d_out, int out_size) {
    const float* x    = (const float*)d_in[0];
    const int*   esrc = (const int*)d_in[1];
    const int*   edst = (const int*)d_in[2];
    const int wi = (n_in >= 20) ? 4 : 3;
    const float* Wn2h = (const float*)d_in[wi + 0];
    const float* bn2h = (const float*)d_in[wi + 1];
    const float* Wh2n = (const float*)d_in[wi + 2];
    const float* bh2n = (const float*)d_in[wi + 3];
    const float* W1   = (const float*)d_in[wi + 4];
    const float* b1   = (const float*)d_in[wi + 5];
    const float* W2   = (const float*)d_in[wi + 6];
    const float* b2   = (const float*)d_in[wi + 7];
    const float* g1   = (const float*)d_in[wi + 8];
    const float* be1  = (const float*)d_in[wi + 9];
    const float* g2   = (const float*)d_in[wi + 10];
    const float* be2  = (const float*)d_in[wi + 11];
    const float* gF   = (const float*)d_in[wi + 12];
    const float* bF   = (const float*)d_in[wi + 13];
    const float* Wo   = (const float*)d_in[wi + 14];
    const float* bo   = (const float*)d_in[wi + 15];

    float *p_h, *p_b1, *p_b2, *p_ha, *p_hb, *p_invn, *p_invh;
    u16 *p_yhi, *p_ylo, *p_thi;
    u16 *p_wa_hi, *p_wa_lo, *p_wb_hi, *p_wb_lo, *p_w1_hi, *p_w1_lo;
    u16 *p_w2_hi, *p_w2_lo, *p_wo_hi, *p_wo_lo;
    int *p_cntH, *p_cntN, *p_stH, *p_stN, *p_cuH, *p_cuN, *p_csrH, *p_csrN;
    cudaGetSymbolAddress((void**)&p_h,    g_h);
    cudaGetSymbolAddress((void**)&p_b1,   g_b1);
    cudaGetSymbolAddress((void**)&p_b2,   g_b2);
    cudaGetSymbolAddress((void**)&p_ha,   g_ha);
    cudaGetSymbolAddress((void**)&p_hb,   g_hb);
    cudaGetSymbolAddress((void**)&p_yhi,  g_yhi);
    cudaGetSymbolAddress((void**)&p_ylo,  g_ylo);
    cudaGetSymbolAddress((void**)&p_thi,  g_thi);
    cudaGetSymbolAddress((void**)&p_wa_hi, g_wa_hi);
    cudaGetSymbolAddress((void**)&p_wa_lo, g_wa_lo);
    cudaGetSymbolAddress((void**)&p_wb_hi, g_wb_hi);
    cudaGetSymbolAddress((void**)&p_wb_lo, g_wb_lo);
    cudaGetSymbolAddress((void**)&p_w1_hi, g_w1_hi);
    cudaGetSymbolAddress((void**)&p_w1_lo, g_w1_lo);
    cudaGetSymbolAddress((void**)&p_w2_hi, g_w2_hi);
    cudaGetSymbolAddress((void**)&p_w2_lo, g_w2_lo);
    cudaGetSymbolAddress((void**)&p_wo_hi, g_wo_hi);
    cudaGetSymbolAddress((void**)&p_wo_lo, g_wo_lo);
    cudaGetSymbolAddress((void**)&p_invn, g_invn);
    cudaGetSymbolAddress((void**)&p_invh, g_invh);
    cudaGetSymbolAddress((void**)&p_cntH, g_cntH);
    cudaGetSymbolAddress((void**)&p_cntN, g_cntN);
    cudaGetSymbolAddress((void**)&p_stH,  g_startH);
    cudaGetSymbolAddress((void**)&p_stN,  g_startN);
    cudaGetSymbolAddress((void**)&p_cuH,  g_curH);
    cudaGetSymbolAddress((void**)&p_cuN,  g_curN);
    cudaGetSymbolAddress((void**)&p_csrH, g_csrH);
    cudaGetSymbolAddress((void**)&p_csrN, g_csrN);

    const int smem_conv = (2 * 128 * 72 + 2 * 64 * 72) * 2;    //  55296
    const int smem_ffn1 = (1 * 128 * 72 + 2 * 256 * 72) * 2;   //  92160
    const int smem_ffn2 = (1 * 128 * 264 + 2 * 64 * 264) * 2;  // 135168
    cudaFuncSetAttribute((const void*)k_mma<64, 64, 0, 3, 0>,  cudaFuncAttributeMaxDynamicSharedMemorySize, smem_conv);
    cudaFuncSetAttribute((const void*)k_mma<64, 64, 1, 0, 0>,  cudaFuncAttributeMaxDynamicSharedMemorySize, smem_conv);
    cudaFuncSetAttribute((const void*)k_mma<64, 64, 0, 1, 0>,  cudaFuncAttributeMaxDynamicSharedMemorySize, smem_conv);
    cudaFuncSetAttribute((const void*)k_mma<64, 256, 3, 4, 1>, cudaFuncAttributeMaxDynamicSharedMemorySize, smem_ffn1);
    cudaFuncSetAttribute((const void*)k_mma<256, 64, 2, 1, 1>, cudaFuncAttributeMaxDynamicSharedMemorySize, smem_ffn2);

    cudaMemcpyAsync(p_h, x, (size_t)NN * DD * sizeof(float), cudaMemcpyDeviceToDevice);

    // ---- weight pre-split ----
    k_prep<0><<<(LL * DD * DD + 255) / 256, 256>>>(Wn2h, DD, DD, LL * DD * DD, p_wa_hi, p_wa_lo);
    k_prep<0><<<(LL * DD * DD + 255) / 256, 256>>>(Wh2n, DD, DD, LL * DD * DD, p_wb_hi, p_wb_lo);
    k_prep<1><<<(LL * DD * FF + 255) / 256, 256>>>(W1, DD, FF, LL * DD * FF, p_w1_hi, p_w1_lo);
    k_prep<1><<<(LL * FF * DD + 255) / 256, 256>>>(W2, FF, DD, LL * FF * DD, p_w2_hi, p_w2_lo);
    k_prep<0><<<(DD * DD + 255) / 256, 256>>>(Wo, DD, DD, DD * DD, p_wo_hi, p_wo_lo);

    // ---- build CSR + degree norms ----
    k_zeroi<<<256, 256>>>(p_cntN, NN);
    k_zeroi<<<64, 256>>>(p_cntH, HH);
    k_zeroi<<<256, 256>>>(p_cuN, NN);
    k_zeroi<<<64, 256>>>(p_cuH, HH);
    k_hist<<<(EE + 255) / 256, 256>>>(esrc, edst, p_cntN, p_cntH);
    k_scan<<<1, 1024>>>(p_cntH, p_stH, HH);
    k_scan<<<1, 1024>>>(p_cntN, p_stN, NN);
    k_fill<<<(EE + 255) / 256, 256>>>(esrc, edst, p_stH, p_stN, p_cuH, p_cuN, p_csrH, p_csrN);
    k_inv<<<(NN + 255) / 256, 256>>>(p_cntN, p_cntH, p_invn, p_invh);

    const int gN  = (NN + 127) / 128;
    const int gH  = (HH + 127) / 128;
    const int gLN = (NN + 7) / 8;
    const int gAgH = (HH + 7) / 8;
    const int gAgN = (NN + 7) / 8;

    for (int l = 0; l < LL; l++) {
        const float* ba = bn2h + (size_t)l * DD;
        const float* bb = bh2n + (size_t)l * DD;
        const float* c1 = b1 + (size_t)l * FF;
        const float* c2 = b2 + (size_t)l * DD;
        const float* gg1 = g1 + (size_t)l * DD;
        const float* ee1 = be1 + (size_t)l * DD;
        const float* gg2 = g2 + (size_t)l * DD;
        const float* ee2 = be2 + (size_t)l * DD;

        // z = agg_H(h * invn[src])
        k_agg<<<gAgH, 256>>>(p_h, p_csrH, p_stH, p_cntH, p_invn, p_ha, HH);
        // y = (z@Wa * invh + ba) * invh -> bf16 split planes
        k_mma<64, 64, 0, 3, 0><<<gH, 256, smem_conv>>>(
            p_ha, nullptr, nullptr, p_wa_hi + (size_t)l * DD * DD, p_wa_lo + (size_t)l * DD * DD,
            p_invh, ba, nullptr, p_yhi, p_ylo, HH);
        // w = y @ Wb
        k_mma<64, 64, 1, 0, 0><<<gH, 256, smem_conv>>>(
            nullptr, p_yhi, p_ylo, p_wb_hi + (size_t)l * DD * DD, p_wb_lo + (size_t)l * DD * DD,
            nullptr, nullptr, p_hb, nullptr, nullptr, HH);
        // u = agg_N(w)
        k_agg<<<gAgN, 256>>>(p_hb, p_csrN, p_stN, p_cntN, nullptr, p_b2, NN);
        // h = LN(h + u*invn + bb)
        k_ln<1><<<gLN, 256>>>(p_h, p_b2, p_invn, bb, gg1, ee1, p_h, NN);
        // FFN1: T = relu(h@W1 + c1) -> fp16 plane (2-term fp16)
        k_mma<64, 256, 3, 4, 1><<<gN, 256, smem_ffn1>>>(
            p_h, nullptr, nullptr, p_w1_hi + (size_t)l * DD * FF, p_w1_lo + (size_t)l * DD * FF,
            nullptr, c1, nullptr, p_thi, nullptr, NN);
        // FFN2: U = T@W2 + c2 (2-term fp16)
        k_mma<256, 64, 2, 1, 1><<<gN, 256, smem_ffn2>>>(
            nullptr, p_thi, nullptr, p_w2_hi + (size_t)l * FF * DD, p_w2_lo + (size_t)l * FF * DD,
            nullptr, c2, p_b2, nullptr, nullptr, NN);
        // h = LN(h + U)
        k_ln<2><<<gLN, 256>>>(p_h, p_b2, nullptr, nullptr, gg2, ee2, p_h, NN);
    }

    // final LN + projection
    k_ln<0><<<gLN, 256>>>(p_h, nullptr, nullptr, nullptr, gF, bF, p_b1, NN);
    k_mma<64, 64, 0, 1, 0><<<gN, 256, smem_conv>>>(
        p_b1, nullptr, nullptr, p_wo_hi, p_wo_lo, nullptr, bo, (float*)d_out, nullptr, nullptr, NN);
}

// round 8
// speedup vs baseline: 1.2600x; 1.2600x over previous
#include <cuda_runtime.h>
#include <cuda_bf16.h>
#include <cuda_fp16.h>
#include <cstdint>
#include <math.h>

#define NN 100000
#define HH 20000
#define EE 1600000
#define DD 64
#define FF 256
#define LL 3

typedef unsigned short u16;

// ---------------- helpers ----------------------------------------------------
__device__ __forceinline__ uint32_t smem_u32(const void* p) {
    uint32_t a;
    asm("{ .reg .u64 t; cvta.to.shared.u64 t, %1; cvt.u32.u64 %0, t; }" : "=r"(a) : "l"(p));
    return a;
}
__device__ __forceinline__ void ldsm_x4(uint32_t* r, uint32_t addr) {
    asm volatile("ldmatrix.sync.aligned.m8n8.x4.shared.b16 {%0,%1,%2,%3}, [%4];"
                 : "=r"(r[0]), "=r"(r[1]), "=r"(r[2]), "=r"(r[3]) : "r"(addr));
}
// DT 0 = bf16, 1 = fp16
template<int DT>
__device__ __forceinline__ void mma16816(float* d, const uint32_t* a, const uint32_t* b) {
    if (DT == 0)
        asm volatile("mma.sync.aligned.m16n8k16.row.col.f32.bf16.bf16.f32 "
                     "{%0,%1,%2,%3}, {%4,%5,%6,%7}, {%8,%9}, {%0,%1,%2,%3};"
                     : "+f"(d[0]), "+f"(d[1]), "+f"(d[2]), "+f"(d[3])
                     : "r"(a[0]), "r"(a[1]), "r"(a[2]), "r"(a[3]), "r"(b[0]), "r"(b[1]));
    else
        asm volatile("mma.sync.aligned.m16n8k16.row.col.f32.f16.f16.f32 "
                     "{%0,%1,%2,%3}, {%4,%5,%6,%7}, {%8,%9}, {%0,%1,%2,%3};"
                     : "+f"(d[0]), "+f"(d[1]), "+f"(d[2]), "+f"(d[3])
                     : "r"(a[0]), "r"(a[1]), "r"(a[2]), "r"(a[3]), "r"(b[0]), "r"(b[1]));
}
__device__ __forceinline__ void split2(float a, float b, uint32_t& hi, uint32_t& lo) {
    __nv_bfloat16 ha = __float2bfloat16(a), hb = __float2bfloat16(b);
    float ra = a - __bfloat162float(ha);
    float rb = b - __bfloat162float(hb);
    __nv_bfloat16 la = __float2bfloat16(ra), lb = __float2bfloat16(rb);
    hi = (uint32_t)__bfloat16_as_ushort(ha) | ((uint32_t)__bfloat16_as_ushort(hb) << 16);
    lo = (uint32_t)__bfloat16_as_ushort(la) | ((uint32_t)__bfloat16_as_ushort(lb) << 16);
}
__device__ __forceinline__ uint32_t pack_f16(float lo, float hi) {
    __half2 h = __floats2half2_rn(lo, hi);
    return *(uint32_t*)&h;
}

// ---------------- scratch ----------------------------------------------------
__device__ __align__(16) float g_h  [NN * DD];
__device__ __align__(16) float g_b1 [NN * DD];
__device__ __align__(16) float g_b2 [NN * DD];
__device__ __align__(16) float g_ha [HH * DD];
__device__ __align__(16) float g_hb [HH * DD];
__device__ __align__(16) u16 g_thi [NN * FF];    // FFN hidden (fp16)
// pre-split transposed weights [N][K]
__device__ __align__(16) u16 g_wa_hi[LL * DD * DD];   // bf16
__device__ __align__(16) u16 g_wa_lo[LL * DD * DD];
__device__ __align__(16) u16 g_wb_hi[LL * DD * DD];   // bf16
__device__ __align__(16) u16 g_wb_lo[LL * DD * DD];
__device__ __align__(16) u16 g_w1_hi[LL * DD * FF];   // fp16
__device__ __align__(16) u16 g_w1_lo[LL * DD * FF];
__device__ __align__(16) u16 g_w2_hi[LL * FF * DD];   // fp16
__device__ __align__(16) u16 g_w2_lo[LL * FF * DD];
__device__ __align__(16) u16 g_wo_hi[DD * DD];        // bf16
__device__ __align__(16) u16 g_wo_lo[DD * DD];
__device__ float g_invn[NN];
__device__ float g_invh[HH];
__device__ int g_cntH [HH];
__device__ int g_cntN [NN];
__device__ int g_startH[HH];
__device__ int g_startN[NN];
__device__ int g_curH [HH];
__device__ int g_curN [NN];
__device__ int g_csrH [EE];
__device__ int g_csrN [EE];

// ---------------- weight prep ------------------------------------------------
template<int DT>
__global__ void k_prep(const float* __restrict__ src, int K, int N, int total,
                       u16* __restrict__ hi, u16* __restrict__ lo) {
    int idx = blockIdx.x * blockDim.x + threadIdx.x;
    if (idx >= total) return;
    int KN = K * N;
    int l = idx / KN;
    int r = idx - l * KN;
    int k = r / N, n = r - k * N;
    float v = src[idx];
    u16 h_bits, l_bits;
    if (DT == 0) {
        __nv_bfloat16 h = __float2bfloat16(v);
        float res = v - __bfloat162float(h);
        h_bits = __bfloat16_as_ushort(h);
        l_bits = __bfloat16_as_ushort(__float2bfloat16(res));
    } else {
        __half h = __float2half_rn(v);
        float res = v - __half2float(h);
        h_bits = __half_as_ushort(h);
        l_bits = __half_as_ushort(__float2half_rn(res));
    }
    size_t o = (size_t)l * KN + (size_t)n * K + k;
    hi[o] = h_bits;
    lo[o] = l_bits;
}

// ---------------- CSR build --------------------------------------------------
__global__ void k_zeroi(int* __restrict__ p, int n) {
    int i = blockIdx.x * blockDim.x + threadIdx.x;
    int stride = gridDim.x * blockDim.x;
    for (; i < n; i += stride) p[i] = 0;
}

__global__ void k_hist(const int* __restrict__ src, const int* __restrict__ dst,
                       int* __restrict__ cntN, int* __restrict__ cntH) {
    int e = blockIdx.x * blockDim.x + threadIdx.x;
    if (e < EE) {
        atomicAdd(&cntN[src[e]], 1);
        atomicAdd(&cntH[dst[e]], 1);
    }
}

__global__ void k_scan(const int* __restrict__ cnt, int* __restrict__ start, int n) {
    __shared__ int shw[33];
    __shared__ int sh_carry;
    const int tid = threadIdx.x;
    const int lane = tid & 31, warp = tid >> 5;
    if (tid == 0) sh_carry = 0;
    __syncthreads();
    for (int base = 0; base < n; base += 1024) {
        int i = base + tid;
        int v = (i < n) ? cnt[i] : 0;
        int inc = v;
        #pragma unroll
        for (int o = 1; o < 32; o <<= 1) {
            int t = __shfl_up_sync(0xffffffffu, inc, o);
            if (lane >= o) inc += t;
        }
        if (lane == 31) shw[warp] = inc;
        __syncthreads();
        if (warp == 0) {
            int t = shw[lane];
            int winc = t;
            #pragma unroll
            for (int o = 1; o < 32; o <<= 1) {
                int u = __shfl_up_sync(0xffffffffu, winc, o);
                if (lane >= o) winc += u;
            }
            shw[lane] = winc - t;
            if (lane == 31) shw[32] = winc;
        }
        __syncthreads();
        int carry = sh_carry;
        if (i < n) start[i] = carry + shw[warp] + inc - v;
        __syncthreads();
        if (tid == 0) sh_carry = carry + shw[32];
        __syncthreads();
    }
}

__global__ void k_fill(const int* __restrict__ src, const int* __restrict__ dst,
                       const int* __restrict__ startH, const int* __restrict__ startN,
                       int* __restrict__ curH, int* __restrict__ curN,
                       int* __restrict__ csrH, int* __restrict__ csrN) {
    int e = blockIdx.x * blockDim.x + threadIdx.x;
    if (e < EE) {
        int s = src[e], d = dst[e];
        int p = atomicAdd(&curH[d], 1);
        csrH[startH[d] + p] = s;
        int q = atomicAdd(&curN[s], 1);
        csrN[startN[s] + q] = d;
    }
}

__global__ void k_inv(const int* __restrict__ cntN, const int* __restrict__ cntH,
                      float* __restrict__ invn, float* __restrict__ invh) {
    int i = blockIdx.x * blockDim.x + threadIdx.x;
    if (i < NN) invn[i] = rsqrtf(fmaxf((float)cntN[i], 1.0f));
    if (i < HH) invh[i] = rsqrtf(fmaxf((float)cntH[i], 1.0f));
}

// ---------------- gather aggregation (scaled) --------------------------------
__global__ void k_agg(const float* __restrict__ Y, const int* __restrict__ csr,
                      const int* __restrict__ start, const int* __restrict__ cnt,
                      const float* __restrict__ scale, float* __restrict__ out, int M) {
    const int warp = threadIdx.x >> 5;
    const int lane = threadIdx.x & 31;
    const int row = blockIdx.x * (blockDim.x >> 5) + warp;
    if (row >= M) return;
    const int half = lane >> 4;
    const int q = lane & 15;
    const int s0 = start[row];
    const int c  = cnt[row];
    const float4* __restrict__ Y4 = (const float4*)Y;

    float4 acc = make_float4(0.f, 0.f, 0.f, 0.f);
    int j = half;
    for (; j + 2 < c; j += 4) {
        int sa = __ldg(&csr[s0 + j]);
        int sb = __ldg(&csr[s0 + j + 2]);
        float4 va = Y4[(size_t)sa * 16 + q];
        float4 vb = Y4[(size_t)sb * 16 + q];
        float fa = __ldg(&scale[sa]), fb = __ldg(&scale[sb]);
        acc.x = fmaf(va.x, fa, acc.x); acc.y = fmaf(va.y, fa, acc.y);
        acc.z = fmaf(va.z, fa, acc.z); acc.w = fmaf(va.w, fa, acc.w);
        acc.x = fmaf(vb.x, fb, acc.x); acc.y = fmaf(vb.y, fb, acc.y);
        acc.z = fmaf(vb.z, fb, acc.z); acc.w = fmaf(vb.w, fb, acc.w);
    }
    if (j < c) {
        int sa = __ldg(&csr[s0 + j]);
        float4 va = Y4[(size_t)sa * 16 + q];
        float fa = __ldg(&scale[sa]);
        acc.x = fmaf(va.x, fa, acc.x); acc.y = fmaf(va.y, fa, acc.y);
        acc.z = fmaf(va.z, fa, acc.z); acc.w = fmaf(va.w, fa, acc.w);
    }
    acc.x += __shfl_xor_sync(0xffffffffu, acc.x, 16);
    acc.y += __shfl_xor_sync(0xffffffffu, acc.y, 16);
    acc.z += __shfl_xor_sync(0xffffffffu, acc.z, 16);
    acc.w += __shfl_xor_sync(0xffffffffu, acc.w, 16);
    if (half == 0) ((float4*)out)[(size_t)row * 16 + q] = acc;
}

// ------ node-side aggregation fused with residual + bias + LayerNorm ---------
// u = sum_{j} W[csr[j]];  x = h[row] + u*invn[row] + bb;  h[row] = LN(x)*g + b
__global__ void k_agg_ln(const float* __restrict__ Y, const int* __restrict__ csr,
                         const int* __restrict__ start, const int* __restrict__ cnt,
                         const float* __restrict__ invn, const float* __restrict__ bb,
                         const float* __restrict__ g, const float* __restrict__ b,
                         float* __restrict__ h, int M) {
    const int warp = threadIdx.x >> 5;
    const int lane = threadIdx.x & 31;
    const int row = blockIdx.x * (blockDim.x >> 5) + warp;
    if (row >= M) return;
    const int half = lane >> 4;
    const int q = lane & 15;
    const int s0 = start[row];
    const int c  = cnt[row];
    const float4* __restrict__ Y4 = (const float4*)Y;

    float4 acc = make_float4(0.f, 0.f, 0.f, 0.f);
    int j = half;
    for (; j + 2 < c; j += 4) {
        int sa = __ldg(&csr[s0 + j]);
        int sb = __ldg(&csr[s0 + j + 2]);
        float4 va = Y4[(size_t)sa * 16 + q];
        float4 vb = Y4[(size_t)sb * 16 + q];
        acc.x += va.x; acc.y += va.y; acc.z += va.z; acc.w += va.w;
        acc.x += vb.x; acc.y += vb.y; acc.z += vb.z; acc.w += vb.w;
    }
    if (j < c) {
        int sa = __ldg(&csr[s0 + j]);
        float4 va = Y4[(size_t)sa * 16 + q];
        acc.x += va.x; acc.y += va.y; acc.z += va.z; acc.w += va.w;
    }
    acc.x += __shfl_xor_sync(0xffffffffu, acc.x, 16);
    acc.y += __shfl_xor_sync(0xffffffffu, acc.y, 16);
    acc.z += __shfl_xor_sync(0xffffffffu, acc.z, 16);
    acc.w += __shfl_xor_sync(0xffffffffu, acc.w, 16);
    // both halves now hold the full u-row segment for cols q*4..q*4+3
    const float s = invn[row];
    float4 hr = ((const float4*)h)[(size_t)row * 16 + q];
    float4 bv = *(const float4*)&bb[q * 4];
    float x0 = fmaf(acc.x, s, hr.x) + bv.x;
    float x1 = fmaf(acc.y, s, hr.y) + bv.y;
    float x2 = fmaf(acc.z, s, hr.z) + bv.z;
    float x3 = fmaf(acc.w, s, hr.w) + bv.w;
    // LN over 64 cols (values duplicated across halves -> sums are 2x)
    float psum = x0 + x1 + x2 + x3;
    #pragma unroll
    for (int o = 16; o; o >>= 1) psum += __shfl_xor_sync(0xffffffffu, psum, o);
    float mu = psum * (1.0f / 128.0f);
    float d0 = x0 - mu, d1 = x1 - mu, d2 = x2 - mu, d3 = x3 - mu;
    float pvar = d0 * d0 + d1 * d1 + d2 * d2 + d3 * d3;
    #pragma unroll
    for (int o = 16; o; o >>= 1) pvar += __shfl_xor_sync(0xffffffffu, pvar, o);
    float inv = rsqrtf(pvar * (1.0f / 128.0f) + 1e-5f);
    if (half == 0) {
        float4 gv = *(const float4*)&g[q * 4];
        float4 bvv = *(const float4*)&b[q * 4];
        float4 o4;
        o4.x = fmaf(d0 * inv, gv.x, bvv.x);
        o4.y = fmaf(d1 * inv, gv.y, bvv.y);
        o4.z = fmaf(d2 * inv, gv.z, bvv.z);
        o4.w = fmaf(d3 * inv, gv.w, bvv.w);
        ((float4*)h)[(size_t)row * 16 + q] = o4;
    }
}

// ---------------- generic HMMA GEMM (FFN1 + final projection) ----------------
// AMODE: 0 = fp32 A -> bf16 split (3-term) | 3 = fp32 A -> fp16 plane (2-term)
// POST:  1 = fp32 C + bvec | 4 = relu(v+bvec) -> fp16 Chi
template<int KT, int NT, int AMODE, int POST, int DT>
__global__ void __launch_bounds__(256, 2)
k_mma(const float* __restrict__ A,
      const u16* __restrict__ Whi_g, const u16* __restrict__ Wlo_g,
      const float* __restrict__ bvec,
      float* __restrict__ C, u16* __restrict__ Chi_g, int M, int nstride) {
    constexpr int KP = KT + 8;
    constexpr bool THREE = (AMODE == 0);
    constexpr int A_ELEMS = 128 * KP;
    constexpr int B_ELEMS = NT * KP;
    extern __shared__ __align__(16) u16 sm[];
    u16* Ahi = sm;
    u16* Alo = THREE ? (Ahi + A_ELEMS) : Ahi;
    u16* Bhi = (THREE ? Alo : Ahi) + A_ELEMS;
    u16* Blo = Bhi + B_ELEMS;

    const int tid = threadIdx.x;
    const int wid = tid >> 5, lane = tid & 31;
    const int row0 = blockIdx.x * 128;
    const int col_base = blockIdx.y * NT;
    Whi_g += (size_t)col_base * KT;
    Wlo_g += (size_t)col_base * KT;

    // ---- fill A ----
    {
        constexpr int KH = KT / 2;
        for (int idx = tid; idx < 128 * KH; idx += 256) {
            int r = idx / KH, kp = idx - r * KH, k = kp * 2;
            int gr = row0 + r;
            float a0 = 0.f, a1 = 0.f;
            if (gr < M) {
                float2 t = ((const float2*)A)[(size_t)gr * KH + kp];
                a0 = t.x; a1 = t.y;
            }
            if (AMODE == 0) {
                uint32_t hi, lo; split2(a0, a1, hi, lo);
                *(uint32_t*)&Ahi[r * KP + k] = hi;
                *(uint32_t*)&Alo[r * KP + k] = lo;
            } else {
                *(uint32_t*)&Ahi[r * KP + k] = pack_f16(a0, a1);
            }
        }
    }
    // ---- fill B ----
    {
        constexpr int K8 = KT / 8;
        for (int idx = tid; idx < NT * K8; idx += 256) {
            int n = idx / K8, k8 = idx - n * K8;
            *(uint4*)&Bhi[n * KP + k8 * 8] = *(const uint4*)&Whi_g[(size_t)n * KT + k8 * 8];
            *(uint4*)&Blo[n * KP + k8 * 8] = *(const uint4*)&Wlo_g[(size_t)n * KT + k8 * 8];
        }
    }
    __syncthreads();

    constexpr int NW = NT / 2;
    constexpr int NF = NW / 8;
    const int wm = wid & 3, wn = wid >> 2;
    const int mrow = wm * 32;
    const int ncol = wn * NW;

    float acc[2][NF][4];
    #pragma unroll
    for (int i = 0; i < 2; i++)
        #pragma unroll
        for (int nf = 0; nf < NF; nf++)
            #pragma unroll
            for (int j = 0; j < 4; j++) acc[i][nf][j] = 0.f;

    const uint32_t ahi_b = smem_u32(Ahi), alo_b = smem_u32(Alo);
    const uint32_t bhi_b = smem_u32(Bhi), blo_b = smem_u32(Blo);
    const int la  = lane & 15;
    const int lka = (lane >> 4) << 3;
    const int lbn = ((lane >> 4) << 3) + (lane & 7);
    const int lbk = ((lane >> 3) & 1) << 3;

    for (int kb = 0; kb < KT; kb += 16) {
        uint32_t ah[2][4], al[2][4];
        #pragma unroll
        for (int i = 0; i < 2; i++) {
            uint32_t aoff = (uint32_t)(((mrow + i * 16 + la) * KP + kb + lka) * 2);
            ldsm_x4(ah[i], ahi_b + aoff);
            if (THREE) ldsm_x4(al[i], alo_b + aoff);
        }
        #pragma unroll
        for (int nf = 0; nf < NF; nf += 2) {
            uint32_t boff = (uint32_t)(((ncol + nf * 8 + lbn) * KP + kb + lbk) * 2);
            uint32_t bh[4], bl[4];
            ldsm_x4(bh, bhi_b + boff);
            ldsm_x4(bl, blo_b + boff);
            #pragma unroll
            for (int i = 0; i < 2; i++) {
                mma16816<DT>(acc[i][nf],     ah[i], bh);
                mma16816<DT>(acc[i][nf],     ah[i], bl);
                mma16816<DT>(acc[i][nf + 1], ah[i], bh + 2);
                mma16816<DT>(acc[i][nf + 1], ah[i], bl + 2);
                if (THREE) {
                    mma16816<DT>(acc[i][nf],     al[i], bh);
                    mma16816<DT>(acc[i][nf + 1], al[i], bh + 2);
                }
            }
        }
    }

    // ---- epilogue ----
    const int qr = lane >> 2;
    const int qc = (lane & 3) * 2;
    #pragma unroll
    for (int i = 0; i < 2; i++) {
        #pragma unroll
        for (int half = 0; half < 2; half++) {
            int gr = row0 + mrow + i * 16 + half * 8 + qr;
            if (gr < M) {
                #pragma unroll
                for (int nf = 0; nf < NF; nf++) {
                    int c = col_base + ncol + nf * 8 + qc;
                    float v0 = acc[i][nf][half * 2 + 0];
                    float v1 = acc[i][nf][half * 2 + 1];
                    if (POST == 1) {
                        v0 += bvec[c]; v1 += bvec[c + 1];
                        *(float2*)&C[(size_t)gr * nstride + c] = make_float2(v0, v1);
                    } else {
                        float t0 = fmaxf(v0 + bvec[c], 0.f);
                        float t1 = fmaxf(v1 + bvec[c + 1], 0.f);
                        ((uint32_t*)Chi_g)[((size_t)gr * nstride + c) >> 1] = pack_f16(t0, t1);
                    }
                }
            }
        }
    }
}

// ---------------- fused conv kernel: w = f(z@Wa) @ Wb ------------------------
// y = (z@Wa * rs[r] + ba[c]) * rs[r]  (kept in smem as split bf16), w = y@Wb
__global__ void __launch_bounds__(256, 2)
k_conv(const float* __restrict__ Z,
       const u16* __restrict__ WaHi_g, const u16* __restrict__ WaLo_g,
       const u16* __restrict__ WbHi_g, const u16* __restrict__ WbLo_g,
       const float* __restrict__ rs, const float* __restrict__ ba,
       float* __restrict__ Wout, int M) {
    constexpr int KP = 72;
    extern __shared__ __align__(16) u16 sm[];
    u16* Ahi = sm;
    u16* Alo = Ahi + 128 * KP;
    u16* BaH = Alo + 128 * KP;
    u16* BaL = BaH + 64 * KP;
    u16* BbH = BaL + 64 * KP;
    u16* BbL = BbH + 64 * KP;

    const int tid = threadIdx.x;
    const int wid = tid >> 5, lane = tid & 31;
    const int row0 = blockIdx.x * 128;

    // fill A (split z)
    for (int idx = tid; idx < 128 * 32; idx += 256) {
        int r = idx >> 5, kp = idx & 31, k = kp * 2;
        int gr = row0 + r;
        float a0 = 0.f, a1 = 0.f;
        if (gr < M) {
            float2 t = ((const float2*)Z)[(size_t)gr * 32 + kp];
            a0 = t.x; a1 = t.y;
        }
        uint32_t hi, lo; split2(a0, a1, hi, lo);
        *(uint32_t*)&Ahi[r * KP + k] = hi;
        *(uint32_t*)&Alo[r * KP + k] = lo;
    }
    // fill all four B planes
    for (int idx = tid; idx < 64 * 8; idx += 256) {
        int n = idx >> 3, k8 = idx & 7;
        *(uint4*)&BaH[n * KP + k8 * 8] = *(const uint4*)&WaHi_g[(size_t)n * 64 + k8 * 8];
        *(uint4*)&BaL[n * KP + k8 * 8] = *(const uint4*)&WaLo_g[(size_t)n * 64 + k8 * 8];
        *(uint4*)&BbH[n * KP + k8 * 8] = *(const uint4*)&WbHi_g[(size_t)n * 64 + k8 * 8];
        *(uint4*)&BbL[n * KP + k8 * 8] = *(const uint4*)&WbLo_g[(size_t)n * 64 + k8 * 8];
    }
    __syncthreads();

    const int wm = wid & 3, wn = wid >> 2;
    const int mrow = wm * 32;
    const int ncol = wn * 32;
    const uint32_t ahi_b = smem_u32(Ahi), alo_b = smem_u32(Alo);
    const int la  = lane & 15;
    const int lka = (lane >> 4) << 3;
    const int lbn = ((lane >> 4) << 3) + (lane & 7);
    const int lbk = ((lane >> 3) & 1) << 3;
    const int qr = lane >> 2;
    const int qc = (lane & 3) * 2;

    float acc[2][4][4];
    // ---- mainloop 1: z @ Wa ----
    {
        const uint32_t bh_b = smem_u32(BaH), bl_b = smem_u32(BaL);
        #pragma unroll
        for (int i = 0; i < 2; i++)
            #pragma unroll
            for (int nf = 0; nf < 4; nf++)
                #pragma unroll
                for (int j = 0; j < 4; j++) acc[i][nf][j] = 0.f;
        #pragma unroll
        for (int kb = 0; kb < 64; kb += 16) {
            uint32_t ah[2][4], al[2][4];
            #pragma unroll
            for (int i = 0; i < 2; i++) {
                uint32_t aoff = (uint32_t)(((mrow + i * 16 + la) * KP + kb + lka) * 2);
                ldsm_x4(ah[i], ahi_b + aoff);
                ldsm_x4(al[i], alo_b + aoff);
            }
            #pragma unroll
            for (int nf = 0; nf < 4; nf += 2) {
                uint32_t boff = (uint32_t)(((ncol + nf * 8 + lbn) * KP + kb + lbk) * 2);
                uint32_t bh[4], bl[4];
                ldsm_x4(bh, bh_b + boff);
                ldsm_x4(bl, bl_b + boff);
                #pragma unroll
                for (int i = 0; i < 2; i++) {
                    mma16816<0>(acc[i][nf],     ah[i], bh);
                    mma16816<0>(acc[i][nf],     ah[i], bl);
                    mma16816<0>(acc[i][nf],     al[i], bh);
                    mma16816<0>(acc[i][nf + 1], ah[i], bh + 2);
                    mma16816<0>(acc[i][nf + 1], ah[i], bl + 2);
                    mma16816<0>(acc[i][nf + 1], al[i], bh + 2);
                }
            }
        }
    }
    __syncthreads();   // all warps done reading A

    // ---- epilogue 1: y -> split bf16, back into A smem ----
    #pragma unroll
    for (int i = 0; i < 2; i++) {
        #pragma unroll
        for (int half = 0; half < 2; half++) {
            int rloc = mrow + i * 16 + half * 8 + qr;
            int gr = row0 + rloc;
            float s = (gr < M) ? rs[gr] : 0.f;
            #pragma unroll
            for (int nf = 0; nf < 4; nf++) {
                int c = ncol + nf * 8 + qc;
                float y0 = (acc[i][nf][half * 2 + 0] * s + ba[c]) * s;
                float y1 = (acc[i][nf][half * 2 + 1] * s + ba[c + 1]) * s;
                uint32_t hi, lo; split2(y0, y1, hi, lo);
                *(uint32_t*)&Ahi[rloc * KP + c] = hi;
                *(uint32_t*)&Alo[rloc * KP + c] = lo;
            }
        }
    }
    __syncthreads();

    // ---- mainloop 2: y @ Wb ----
    {
        const uint32_t bh_b = smem_u32(BbH), bl_b = smem_u32(BbL);
        #pragma unroll
        for (int i = 0; i < 2; i++)
            #pragma unroll
            for (int nf = 0; nf < 4; nf++)
                #pragma unroll
                for (int j = 0; j < 4; j++) acc[i][nf][j] = 0.f;
        #pragma unroll
        for (int kb = 0; kb < 64; kb += 16) {
            uint32_t ah[2][4], al[2][4];
            #pragma unroll
            for (int i = 0; i < 2; i++) {
                uint32_t aoff = (uint32_t)(((mrow + i * 16 + la) * KP + kb + lka) * 2);
                ldsm_x4(ah[i], ahi_b + aoff);
                ldsm_x4(al[i], alo_b + aoff);
            }
            #pragma unroll
            for (int nf = 0; nf < 4; nf += 2) {
                uint32_t boff = (uint32_t)(((ncol + nf * 8 + lbn) * KP + kb + lbk) * 2);
                uint32_t bh[4], bl[4];
                ldsm_x4(bh, bh_b + boff);
                ldsm_x4(bl, bl_b + boff);
                #pragma unroll
                for (int i = 0; i < 2; i++) {
                    mma16816<0>(acc[i][nf],     ah[i], bh);
                    mma16816<0>(acc[i][nf],     ah[i], bl);
                    mma16816<0>(acc[i][nf],     al[i], bh);
                    mma16816<0>(acc[i][nf + 1], ah[i], bh + 2);
                    mma16816<0>(acc[i][nf + 1], ah[i], bl + 2);
                    mma16816<0>(acc[i][nf + 1], al[i], bh + 2);
                }
            }
        }
    }
    // ---- epilogue 2: w -> gmem fp32 ----
    #pragma unroll
    for (int i = 0; i < 2; i++) {
        #pragma unroll
        for (int half = 0; half < 2; half++) {
            int gr = row0 + mrow + i * 16 + half * 8 + qr;
            if (gr < M) {
                #pragma unroll
                for (int nf = 0; nf < 4; nf++) {
                    int c = ncol + nf * 8 + qc;
                    *(float2*)&Wout[(size_t)gr * 64 + c] =
                        make_float2(acc[i][nf][half * 2 + 0], acc[i][nf][half * 2 + 1]);
                }
            }
        }
    }
}

// ---------------- FFN2: K-chunked (2x128), fp16 2-term -----------------------
__global__ void __launch_bounds__(256, 2)
k_ffn2(const u16* __restrict__ T, const u16* __restrict__ Whi_g,
       const u16* __restrict__ Wlo_g, const float* __restrict__ bvec,
       float* __restrict__ C, int M) {
    constexpr int KC = 128, KP = KC + 8;
    extern __shared__ __align__(16) u16 sm[];
    u16* As  = sm;                 // 128 x 136 fp16
    u16* Bhi = As + 128 * KP;      // 64 x 136
    u16* Blo = Bhi + 64 * KP;

    const int tid = threadIdx.x;
    const int wid = tid >> 5, lane = tid & 31;
    const int row0 = blockIdx.x * 128;
    const int wm = wid & 3, wn = wid >> 2;
    const int mrow = wm * 32;
    const int ncol = wn * 32;
    const int la  = lane & 15;
    const int lka = (lane >> 4) << 3;
    const int lbn = ((lane >> 4) << 3) + (lane & 7);
    const int lbk = ((lane >> 3) & 1) << 3;

    float acc[2][4][4];
    #pragma unroll
    for (int i = 0; i < 2; i++)
        #pragma unroll
        for (int nf = 0; nf < 4; nf++)
            #pragma unroll
            for (int j = 0; j < 4; j++) acc[i][nf][j] = 0.f;

    const uint32_t as_b = smem_u32(As);
    const uint32_t bh_b = smem_u32(Bhi), bl_b = smem_u32(Blo);
    const uint4 z4 = make_uint4(0, 0, 0, 0);

    for (int kc = 0; kc < 2; kc++) {
        __syncthreads();
        for (int idx = tid; idx < 128 * 16; idx += 256) {
            int r = idx >> 4, k8 = idx & 15;
            int gr = row0 + r;
            uint4 v = z4;
            if (gr < M) v = *(const uint4*)&T[(size_t)gr * 256 + kc * 128 + k8 * 8];
            *(uint4*)&As[r * KP + k8 * 8] = v;
        }
        for (int idx = tid; idx < 64 * 16; idx += 256) {
            int n = idx >> 4, k8 = idx & 15;
            *(uint4*)&Bhi[n * KP + k8 * 8] = *(const uint4*)&Whi_g[(size_t)n * 256 + kc * 128 + k8 * 8];
            *(uint4*)&Blo[n * KP + k8 * 8] = *(const uint4*)&Wlo_g[(size_t)n * 256 + kc * 128 + k8 * 8];
        }
        __syncthreads();
        for (int kb = 0; kb < KC; kb += 16) {
            uint32_t ah[2][4];
            #pragma unroll
            for (int i = 0; i < 2; i++) {
                uint32_t aoff = (uint32_t)(((mrow + i * 16 + la) * KP + kb + lka) * 2);
                ldsm_x4(ah[i], as_b + aoff);
            }
            #pragma unroll
            for (int nf = 0; nf < 4; nf += 2) {
                uint32_t boff = (uint32_t)(((ncol + nf * 8 + lbn) * KP + kb + lbk) * 2);
                uint32_t bh[4], bl[4];
                ldsm_x4(bh, bh_b + boff);
                ldsm_x4(bl, bl_b + boff);
                #pragma unroll
                for (int i = 0; i < 2; i++) {
                    mma16816<1>(acc[i][nf],     ah[i], bh);
                    mma16816<1>(acc[i][nf],     ah[i], bl);
                    mma16816<1>(acc[i][nf + 1], ah[i], bh + 2);
                    mma16816<1>(acc[i][nf + 1], ah[i], bl + 2);
                }
            }
        }
    }

    const int qr = lane >> 2;
    const int qc = (lane & 3) * 2;
    #pragma unroll
    for (int i = 0; i < 2; i++) {
        #pragma unroll
        for (int half = 0; half < 2; half++) {
            int gr = row0 + mrow + i * 16 + half * 8 + qr;
            if (gr < M) {
                #pragma unroll
                for (int nf = 0; nf < 4; nf++) {
                    int c = ncol + nf * 8 + qc;
                    *(float2*)&C[(size_t)gr * 64 + c] = make_float2(
                        acc[i][nf][half * 2 + 0] + bvec[c],
                        acc[i][nf][half * 2 + 1] + bvec[c + 1]);
                }
            }
        }
    }
}

// ---------------- LayerNorm (standalone, modes 0/2) --------------------------
template <int MODE>
__global__ void k_ln(const float* __restrict__ base, const float* __restrict__ add,
                     const float* __restrict__ g, const float* __restrict__ b,
                     float* __restrict__ out, int M) {
    const int warp = threadIdx.x >> 5;
    const int lane = threadIdx.x & 31;
    const int row = blockIdx.x * (blockDim.x >> 5) + warp;
    if (row >= M) return;
    const int i0 = row * 64 + lane;
    const int i1 = i0 + 32;

    float x0 = base[i0], x1 = base[i1];
    if (MODE == 2) { x0 += add[i0]; x1 += add[i1]; }
    float sum = x0 + x1;
    #pragma unroll
    for (int o = 16; o; o >>= 1) sum += __shfl_xor_sync(0xffffffffu, sum, o);
    float mu = sum * (1.0f / 64.0f);
    float d0 = x0 - mu, d1 = x1 - mu;
    float vs = d0 * d0 + d1 * d1;
    #pragma unroll
    for (int o = 16; o; o >>= 1) vs += __shfl_xor_sync(0xffffffffu, vs, o);
    float inv = rsqrtf(vs * (1.0f / 64.0f) + 1e-5f);
    out[i0] = fmaf(d0 * inv, g[lane], b[lane]);
    out[i1] = fmaf(d1 * inv, g[lane + 32], b[lane + 32]);
}

// ---------------- orchestration ----------------------------------------------
extern "C" void kernel_launch(void* const* d_in, const int* in_sizes, int n_in,
                              void* d_out, int out_size) {
    const float* x    = (const float*)d_in[0];
    const int*   esrc = (const int*)d_in[1];
    const int*   edst = (const int*)d_in[2];
    const int wi = (n_in >= 20) ? 4 : 3;
    const float* Wn2h = (const float*)d_in[wi + 0];
    const float* bn2h = (const float*)d_in[wi + 1];
    const float* Wh2n = (const float*)d_in[wi + 2];
    const float* bh2n = (const float*)d_in[wi + 3];
    const float* W1   = (const float*)d_in[wi + 4];
    const float* b1   = (const float*)d_in[wi + 5];
    const float* W2   = (const float*)d_in[wi + 6];
    const float* b2   = (const float*)d_in[wi + 7];
    const float* g1   = (const float*)d_in[wi + 8];
    const float* be1  = (const float*)d_in[wi + 9];
    const float* g2   = (const float*)d_in[wi + 10];
    const float* be2  = (const float*)d_in[wi + 11];
    const float* gF   = (const float*)d_in[wi + 12];
    const float* bF   = (const float*)d_in[wi + 13];
    const float* Wo   = (const float*)d_in[wi + 14];
    const float* bo   = (const float*)d_in[wi + 15];

    float *p_h, *p_b1, *p_b2, *p_ha, *p_hb, *p_invn, *p_invh;
    u16 *p_thi;
    u16 *p_wa_hi, *p_wa_lo, *p_wb_hi, *p_wb_lo, *p_w1_hi, *p_w1_lo;
    u16 *p_w2_hi, *p_w2_lo, *p_wo_hi, *p_wo_lo;
    int *p_cntH, *p_cntN, *p_stH, *p_stN, *p_cuH, *p_cuN, *p_csrH, *p_csrN;
    cudaGetSymbolAddress((void**)&p_h,    g_h);
    cudaGetSymbolAddress((void**)&p_b1,   g_b1);
    cudaGetSymbolAddress((void**)&p_b2,   g_b2);
    cudaGetSymbolAddress((void**)&p_ha,   g_ha);
    cudaGetSymbolAddress((void**)&p_hb,   g_hb);
    cudaGetSymbolAddress((void**)&p_thi,  g_thi);
    cudaGetSymbolAddress((void**)&p_wa_hi, g_wa_hi);
    cudaGetSymbolAddress((void**)&p_wa_lo, g_wa_lo);
    cudaGetSymbolAddress((void**)&p_wb_hi, g_wb_hi);
    cudaGetSymbolAddress((void**)&p_wb_lo, g_wb_lo);
    cudaGetSymbolAddress((void**)&p_w1_hi, g_w1_hi);
    cudaGetSymbolAddress((void**)&p_w1_lo, g_w1_lo);
    cudaGetSymbolAddress((void**)&p_w2_hi, g_w2_hi);
    cudaGetSymbolAddress((void**)&p_w2_lo, g_w2_lo);
    cudaGetSymbolAddress((void**)&p_wo_hi, g_wo_hi);
    cudaGetSymbolAddress((void**)&p_wo_lo, g_wo_lo);
    cudaGetSymbolAddress((void**)&p_invn, g_invn);
    cudaGetSymbolAddress((void**)&p_invh, g_invh);
    cudaGetSymbolAddress((void**)&p_cntH, g_cntH);
    cudaGetSymbolAddress((void**)&p_cntN, g_cntN);
    cudaGetSymbolAddress((void**)&p_stH,  g_startH);
    cudaGetSymbolAddress((void**)&p_stN,  g_startN);
    cudaGetSymbolAddress((void**)&p_cuH,  g_curH);
    cudaGetSymbolAddress((void**)&p_cuN,  g_curN);
    cudaGetSymbolAddress((void**)&p_csrH, g_csrH);
    cudaGetSymbolAddress((void**)&p_csrN, g_csrN);

    const int smem_convf = (2 * 128 * 72 + 4 * 64 * 72) * 2;   //  73728
    const int smem_ffn1  = (1 * 128 * 72 + 2 * 128 * 72) * 2;  //  55296
    const int smem_ffn2  = (128 * 136 + 2 * 64 * 136) * 2;     //  69632
    const int smem_proj  = (2 * 128 * 72 + 2 * 64 * 72) * 2;   //  55296
    cudaFuncSetAttribute((const void*)k_conv, cudaFuncAttributeMaxDynamicSharedMemorySize, smem_convf);
    cudaFuncSetAttribute((const void*)k_mma<64, 128, 3, 4, 1>, cudaFuncAttributeMaxDynamicSharedMemorySize, smem_ffn1);
    cudaFuncSetAttribute((const void*)k_ffn2, cudaFuncAttributeMaxDynamicSharedMemorySize, smem_ffn2);
    cudaFuncSetAttribute((const void*)k_mma<64, 64, 0, 1, 0>, cudaFuncAttributeMaxDynamicSharedMemorySize, smem_proj);

    cudaMemcpyAsync(p_h, x, (size_t)NN * DD * sizeof(float), cudaMemcpyDeviceToDevice);

    // ---- weight pre-split ----
    k_prep<0><<<(LL * DD * DD + 255) / 256, 256>>>(Wn2h, DD, DD, LL * DD * DD, p_wa_hi, p_wa_lo);
    k_prep<0><<<(LL * DD * DD + 255) / 256, 256>>>(Wh2n, DD, DD, LL * DD * DD, p_wb_hi, p_wb_lo);
    k_prep<1><<<(LL * DD * FF + 255) / 256, 256>>>(W1, DD, FF, LL * DD * FF, p_w1_hi, p_w1_lo);
    k_prep<1><<<(LL * FF * DD + 255) / 256, 256>>>(W2, FF, DD, LL * FF * DD, p_w2_hi, p_w2_lo);
    k_prep<0><<<(DD * DD + 255) / 256, 256>>>(Wo, DD, DD, DD * DD, p_wo_hi, p_wo_lo);

    // ---- build CSR + degree norms ----
    k_zeroi<<<256, 256>>>(p_cntN, NN);
    k_zeroi<<<64, 256>>>(p_cntH, HH);
    k_zeroi<<<256, 256>>>(p_cuN, NN);
    k_zeroi<<<64, 256>>>(p_cuH, HH);
    k_hist<<<(EE + 255) / 256, 256>>>(esrc, edst, p_cntN, p_cntH);
    k_scan<<<1, 1024>>>(p_cntH, p_stH, HH);
    k_scan<<<1, 1024>>>(p_cntN, p_stN, NN);
    k_fill<<<(EE + 255) / 256, 256>>>(esrc, edst, p_stH, p_stN, p_cuH, p_cuN, p_csrH, p_csrN);
    k_inv<<<(NN + 255) / 256, 256>>>(p_cntN, p_cntH, p_invn, p_invh);

    const int gN  = (NN + 127) / 128;
    const int gH  = (HH + 127) / 128;
    const int gLN = (NN + 7) / 8;
    const int gAgH = (HH + 7) / 8;
    const int gAgN = (NN + 7) / 8;

    for (int l = 0; l < LL; l++) {
        const float* ba = bn2h + (size_t)l * DD;
        const float* bb = bh2n + (size_t)l * DD;
        const float* c1 = b1 + (size_t)l * FF;
        const float* c2 = b2 + (size_t)l * DD;
        const float* gg1 = g1 + (size_t)l * DD;
        const float* ee1 = be1 + (size_t)l * DD;
        const float* gg2 = g2 + (size_t)l * DD;
        const float* ee2 = be2 + (size_t)l * DD;

        // z = agg_H(h * invn[src])
        k_agg<<<gAgH, 256>>>(p_h, p_csrH, p_stH, p_cntH, p_invn, p_ha, HH);
        // fused: y = (z@Wa*invh+ba)*invh ; w = y@Wb
        k_conv<<<gH, 256, smem_convf>>>(
            p_ha, p_wa_hi + (size_t)l * DD * DD, p_wa_lo + (size_t)l * DD * DD,
            p_wb_hi + (size_t)l * DD * DD, p_wb_lo + (size_t)l * DD * DD,
            p_invh, ba, p_hb, HH);
        // fused: u = agg_N(w); h = LN(h + u*invn + bb)
        k_agg_ln<<<gAgN, 256>>>(p_hb, p_csrN, p_stN, p_cntN, p_invn, bb, gg1, ee1, p_h, NN);
        // FFN1: T = relu(h@W1 + c1) -> fp16 (2-term fp16, NT=128 x 2 tiles)
        k_mma<64, 128, 3, 4, 1><<<dim3(gN, 2), 256, smem_ffn1>>>(
            p_h, p_w1_hi + (size_t)l * DD * FF, p_w1_lo + (size_t)l * DD * FF,
            c1, nullptr, p_thi, NN, FF);
        // FFN2: U = T@W2 + c2 (2-term fp16, K-chunked)
        k_ffn2<<<gN, 256, smem_ffn2>>>(
            p_thi, p_w2_hi + (size_t)l * FF * DD, p_w2_lo + (size_t)l * FF * DD,
            c2, p_b2, NN);
        // h = LN(h + U)
        k_ln<2><<<gLN, 256>>>(p_h, p_b2, gg2, ee2, p_h, NN);
    }

    // final LN + projection
    k_ln<0><<<gLN, 256>>>(p_h, nullptr, gF, bF, p_b1, NN);
    k_mma<64, 64, 0, 1, 0><<<gN, 256, smem_proj>>>(
        p_b1, p_wo_hi, p_wo_lo, bo, (float*)d_out, nullptr, NN, DD);
}

// round 9
// speedup vs baseline: 1.3722x; 1.0890x over previous
#include <cuda_runtime.h>
#include <cuda_bf16.h>
#include <cuda_fp16.h>
#include <cstdint>
#include <math.h>

#define NN 100000
#define HH 20000
#define EE 1600000
#define DD 64
#define FF 256
#define LL 3

typedef unsigned short u16;

// ---------------- helpers ----------------------------------------------------
__device__ __forceinline__ uint32_t smem_u32(const void* p) {
    uint32_t a;
    asm("{ .reg .u64 t; cvta.to.shared.u64 t, %1; cvt.u32.u64 %0, t; }" : "=r"(a) : "l"(p));
    return a;
}
__device__ __forceinline__ void ldsm_x4(uint32_t* r, uint32_t addr) {
    asm volatile("ldmatrix.sync.aligned.m8n8.x4.shared.b16 {%0,%1,%2,%3}, [%4];"
                 : "=r"(r[0]), "=r"(r[1]), "=r"(r[2]), "=r"(r[3]) : "r"(addr));
}
// DT 0 = bf16, 1 = fp16
template<int DT>
__device__ __forceinline__ void mma16816(float* d, const uint32_t* a, const uint32_t* b) {
    if (DT == 0)
        asm volatile("mma.sync.aligned.m16n8k16.row.col.f32.bf16.bf16.f32 "
                     "{%0,%1,%2,%3}, {%4,%5,%6,%7}, {%8,%9}, {%0,%1,%2,%3};"
                     : "+f"(d[0]), "+f"(d[1]), "+f"(d[2]), "+f"(d[3])
                     : "r"(a[0]), "r"(a[1]), "r"(a[2]), "r"(a[3]), "r"(b[0]), "r"(b[1]));
    else
        asm volatile("mma.sync.aligned.m16n8k16.row.col.f32.f16.f16.f32 "
                     "{%0,%1,%2,%3}, {%4,%5,%6,%7}, {%8,%9}, {%0,%1,%2,%3};"
                     : "+f"(d[0]), "+f"(d[1]), "+f"(d[2]), "+f"(d[3])
                     : "r"(a[0]), "r"(a[1]), "r"(a[2]), "r"(a[3]), "r"(b[0]), "r"(b[1]));
}
__device__ __forceinline__ void split2(float a, float b, uint32_t& hi, uint32_t& lo) {
    __nv_bfloat16 ha = __float2bfloat16(a), hb = __float2bfloat16(b);
    float ra = a - __bfloat162float(ha);
    float rb = b - __bfloat162float(hb);
    __nv_bfloat16 la = __float2bfloat16(ra), lb = __float2bfloat16(rb);
    hi = (uint32_t)__bfloat16_as_ushort(ha) | ((uint32_t)__bfloat16_as_ushort(hb) << 16);
    lo = (uint32_t)__bfloat16_as_ushort(la) | ((uint32_t)__bfloat16_as_ushort(lb) << 16);
}
__device__ __forceinline__ uint32_t pack_f16(float lo, float hi) {
    __half2 h = __floats2half2_rn(lo, hi);
    return *(uint32_t*)&h;
}
__device__ __forceinline__ void unpack_f16(uint32_t v, float& lo, float& hi) {
    __half2 h = *(__half2*)&v;
    float2 f = __half22float2(h);
    lo = f.x; hi = f.y;
}

// ---------------- scratch ----------------------------------------------------
__device__ __align__(16) float g_h  [NN * DD];
__device__ __align__(16) float g_b1 [NN * DD];
__device__ __align__(16) u16 g_hf16[NN * DD];    // fp16 copy of h
__device__ __align__(16) float g_ha [HH * DD];   // z (fp32)
__device__ __align__(16) u16 g_wf16[HH * DD];    // w (fp16)
__device__ __align__(16) u16 g_thi [NN * FF];    // FFN hidden (fp16)
// pre-split transposed weights [N][K]
__device__ __align__(16) u16 g_wa_hi[LL * DD * DD];   // bf16
__device__ __align__(16) u16 g_wa_lo[LL * DD * DD];
__device__ __align__(16) u16 g_wb_hi[LL * DD * DD];   // bf16
__device__ __align__(16) u16 g_wb_lo[LL * DD * DD];
__device__ __align__(16) u16 g_w1_hi[LL * DD * FF];   // fp16
__device__ __align__(16) u16 g_w1_lo[LL * DD * FF];
__device__ __align__(16) u16 g_w2_hi[LL * FF * DD];   // fp16
__device__ __align__(16) u16 g_w2_lo[LL * FF * DD];
__device__ __align__(16) u16 g_wo_hi[DD * DD];        // bf16
__device__ __align__(16) u16 g_wo_lo[DD * DD];
__device__ float g_invn[NN];
__device__ float g_invh[HH];
__device__ int g_cntH [HH];
__device__ int g_cntN [NN];
__device__ int g_startH[HH];
__device__ int g_startN[NN];
__device__ int g_curH [HH];
__device__ int g_curN [NN];
__device__ int g_csrH [EE];
__device__ int g_csrN [EE];

// ---------------- weight prep ------------------------------------------------
template<int DT>
__global__ void k_prep(const float* __restrict__ src, int K, int N, int total,
                       u16* __restrict__ hi, u16* __restrict__ lo) {
    int idx = blockIdx.x * blockDim.x + threadIdx.x;
    if (idx >= total) return;
    int KN = K * N;
    int l = idx / KN;
    int r = idx - l * KN;
    int k = r / N, n = r - k * N;
    float v = src[idx];
    u16 h_bits, l_bits;
    if (DT == 0) {
        __nv_bfloat16 h = __float2bfloat16(v);
        float res = v - __bfloat162float(h);
        h_bits = __bfloat16_as_ushort(h);
        l_bits = __bfloat16_as_ushort(__float2bfloat16(res));
    } else {
        __half h = __float2half_rn(v);
        float res = v - __half2float(h);
        h_bits = __half_as_ushort(h);
        l_bits = __half_as_ushort(__float2half_rn(res));
    }
    size_t o = (size_t)l * KN + (size_t)n * K + k;
    hi[o] = h_bits;
    lo[o] = l_bits;
}

// fp32 -> fp16 plane copy (for initial h)
__global__ void k_f2h(const float* __restrict__ src, u16* __restrict__ dst, int n2) {
    int i = blockIdx.x * blockDim.x + threadIdx.x;
    if (i < n2) {
        float2 v = ((const float2*)src)[i];
        ((uint32_t*)dst)[i] = pack_f16(v.x, v.y);
    }
}

// ---------------- CSR build --------------------------------------------------
__global__ void k_zeroi(int* __restrict__ p, int n) {
    int i = blockIdx.x * blockDim.x + threadIdx.x;
    int stride = gridDim.x * blockDim.x;
    for (; i < n; i += stride) p[i] = 0;
}

__global__ void k_hist(const int* __restrict__ src, const int* __restrict__ dst,
                       int* __restrict__ cntN, int* __restrict__ cntH) {
    int e = blockIdx.x * blockDim.x + threadIdx.x;
    if (e < EE) {
        atomicAdd(&cntN[src[e]], 1);
        atomicAdd(&cntH[dst[e]], 1);
    }
}

__global__ void k_scan(const int* __restrict__ cnt, int* __restrict__ start, int n) {
    __shared__ int shw[33];
    __shared__ int sh_carry;
    const int tid = threadIdx.x;
    const int lane = tid & 31, warp = tid >> 5;
    if (tid == 0) sh_carry = 0;
    __syncthreads();
    for (int base = 0; base < n; base += 1024) {
        int i = base + tid;
        int v = (i < n) ? cnt[i] : 0;
        int inc = v;
        #pragma unroll
        for (int o = 1; o < 32; o <<= 1) {
            int t = __shfl_up_sync(0xffffffffu, inc, o);
            if (lane >= o) inc += t;
        }
        if (lane == 31) shw[warp] = inc;
        __syncthreads();
        if (warp == 0) {
            int t = shw[lane];
            int winc = t;
            #pragma unroll
            for (int o = 1; o < 32; o <<= 1) {
                int u = __shfl_up_sync(0xffffffffu, winc, o);
                if (lane >= o) winc += u;
            }
            shw[lane] = winc - t;
            if (lane == 31) shw[32] = winc;
        }
        __syncthreads();
        int carry = sh_carry;
        if (i < n) start[i] = carry + shw[warp] + inc - v;
        __syncthreads();
        if (tid == 0) sh_carry = carry + shw[32];
        __syncthreads();
    }
}

__global__ void k_fill(const int* __restrict__ src, const int* __restrict__ dst,
                       const int* __restrict__ startH, const int* __restrict__ startN,
                       int* __restrict__ curH, int* __restrict__ curN,
                       int* __restrict__ csrH, int* __restrict__ csrN) {
    int e = blockIdx.x * blockDim.x + threadIdx.x;
    if (e < EE) {
        int s = src[e], d = dst[e];
        int p = atomicAdd(&curH[d], 1);
        csrH[startH[d] + p] = s;
        int q = atomicAdd(&curN[s], 1);
        csrN[startN[s] + q] = d;
    }
}

__global__ void k_inv(const int* __restrict__ cntN, const int* __restrict__ cntH,
                      float* __restrict__ invn, float* __restrict__ invh) {
    int i = blockIdx.x * blockDim.x + threadIdx.x;
    if (i < NN) invn[i] = rsqrtf(fmaxf((float)cntN[i], 1.0f));
    if (i < HH) invh[i] = rsqrtf(fmaxf((float)cntH[i], 1.0f));
}

// ------- fp16 gather aggregation (scaled): z = sum hf16[csr[j]]*scale --------
__global__ void k_agg16(const u16* __restrict__ Y, const int* __restrict__ csr,
                        const int* __restrict__ start, const int* __restrict__ cnt,
                        const float* __restrict__ scale, float* __restrict__ out, int M) {
    const int warp = threadIdx.x >> 5;
    const int lane = threadIdx.x & 31;
    const int row = blockIdx.x * (blockDim.x >> 5) + warp;
    if (row >= M) return;
    const int half = lane >> 4;
    const int q = lane & 15;
    const int s0 = start[row];
    const int c  = cnt[row];
    const uint2* __restrict__ Y2 = (const uint2*)Y;   // 8B = 4 halves

    float4 acc = make_float4(0.f, 0.f, 0.f, 0.f);
    int j = half;
    for (; j + 2 < c; j += 4) {
        int sa = __ldg(&csr[s0 + j]);
        int sb = __ldg(&csr[s0 + j + 2]);
        uint2 pa = Y2[(size_t)sa * 16 + q];
        uint2 pb = Y2[(size_t)sb * 16 + q];
        float fa = __ldg(&scale[sa]), fb = __ldg(&scale[sb]);
        float a0, a1, a2, a3;
        unpack_f16(pa.x, a0, a1); unpack_f16(pa.y, a2, a3);
        acc.x = fmaf(a0, fa, acc.x); acc.y = fmaf(a1, fa, acc.y);
        acc.z = fmaf(a2, fa, acc.z); acc.w = fmaf(a3, fa, acc.w);
        unpack_f16(pb.x, a0, a1); unpack_f16(pb.y, a2, a3);
        acc.x = fmaf(a0, fb, acc.x); acc.y = fmaf(a1, fb, acc.y);
        acc.z = fmaf(a2, fb, acc.z); acc.w = fmaf(a3, fb, acc.w);
    }
    if (j < c) {
        int sa = __ldg(&csr[s0 + j]);
        uint2 pa = Y2[(size_t)sa * 16 + q];
        float fa = __ldg(&scale[sa]);
        float a0, a1, a2, a3;
        unpack_f16(pa.x, a0, a1); unpack_f16(pa.y, a2, a3);
        acc.x = fmaf(a0, fa, acc.x); acc.y = fmaf(a1, fa, acc.y);
        acc.z = fmaf(a2, fa, acc.z); acc.w = fmaf(a3, fa, acc.w);
    }
    acc.x += __shfl_xor_sync(0xffffffffu, acc.x, 16);
    acc.y += __shfl_xor_sync(0xffffffffu, acc.y, 16);
    acc.z += __shfl_xor_sync(0xffffffffu, acc.z, 16);
    acc.w += __shfl_xor_sync(0xffffffffu, acc.w, 16);
    if (half == 0) ((float4*)out)[(size_t)row * 16 + q] = acc;
}

// --- fp16 gather + residual + bias + LN, writes h fp32 and fp16 planes -------
__global__ void k_agg_ln16(const u16* __restrict__ Y, const int* __restrict__ csr,
                           const int* __restrict__ start, const int* __restrict__ cnt,
                           const float* __restrict__ invn, const float* __restrict__ bb,
                           const float* __restrict__ g, const float* __restrict__ b,
                           float* __restrict__ h, u16* __restrict__ hf16, int M) {
    const int warp = threadIdx.x >> 5;
    const int lane = threadIdx.x & 31;
    const int row = blockIdx.x * (blockDim.x >> 5) + warp;
    if (row >= M) return;
    const int half = lane >> 4;
    const int q = lane & 15;
    const int s0 = start[row];
    const int c  = cnt[row];
    const uint2* __restrict__ Y2 = (const uint2*)Y;

    float4 acc = make_float4(0.f, 0.f, 0.f, 0.f);
    int j = half;
    for (; j + 2 < c; j += 4) {
        int sa = __ldg(&csr[s0 + j]);
        int sb = __ldg(&csr[s0 + j + 2]);
        uint2 pa = Y2[(size_t)sa * 16 + q];
        uint2 pb = Y2[(size_t)sb * 16 + q];
        float a0, a1, a2, a3;
        unpack_f16(pa.x, a0, a1); unpack_f16(pa.y, a2, a3);
        acc.x += a0; acc.y += a1; acc.z += a2; acc.w += a3;
        unpack_f16(pb.x, a0, a1); unpack_f16(pb.y, a2, a3);
        acc.x += a0; acc.y += a1; acc.z += a2; acc.w += a3;
    }
    if (j < c) {
        int sa = __ldg(&csr[s0 + j]);
        uint2 pa = Y2[(size_t)sa * 16 + q];
        float a0, a1, a2, a3;
        unpack_f16(pa.x, a0, a1); unpack_f16(pa.y, a2, a3);
        acc.x += a0; acc.y += a1; acc.z += a2; acc.w += a3;
    }
    acc.x += __shfl_xor_sync(0xffffffffu, acc.x, 16);
    acc.y += __shfl_xor_sync(0xffffffffu, acc.y, 16);
    acc.z += __shfl_xor_sync(0xffffffffu, acc.z, 16);
    acc.w += __shfl_xor_sync(0xffffffffu, acc.w, 16);

    const float s = invn[row];
    float4 hr = ((const float4*)h)[(size_t)row * 16 + q];
    float4 bv = *(const float4*)&bb[q * 4];
    float x0 = fmaf(acc.x, s, hr.x) + bv.x;
    float x1 = fmaf(acc.y, s, hr.y) + bv.y;
    float x2 = fmaf(acc.z, s, hr.z) + bv.z;
    float x3 = fmaf(acc.w, s, hr.w) + bv.w;
    float psum = x0 + x1 + x2 + x3;
    #pragma unroll
    for (int o = 16; o; o >>= 1) psum += __shfl_xor_sync(0xffffffffu, psum, o);
    float mu = psum * (1.0f / 128.0f);
    float d0 = x0 - mu, d1 = x1 - mu, d2 = x2 - mu, d3 = x3 - mu;
    float pvar = d0 * d0 + d1 * d1 + d2 * d2 + d3 * d3;
    #pragma unroll
    for (int o = 16; o; o >>= 1) pvar += __shfl_xor_sync(0xffffffffu, pvar, o);
    float inv = rsqrtf(pvar * (1.0f / 128.0f) + 1e-5f);
    if (half == 0) {
        float4 gv = *(const float4*)&g[q * 4];
        float4 bvv = *(const float4*)&b[q * 4];
        float4 o4;
        o4.x = fmaf(d0 * inv, gv.x, bvv.x);
        o4.y = fmaf(d1 * inv, gv.y, bvv.y);
        o4.z = fmaf(d2 * inv, gv.z, bvv.z);
        o4.w = fmaf(d3 * inv, gv.w, bvv.w);
        ((float4*)h)[(size_t)row * 16 + q] = o4;
        uint2 p;
        p.x = pack_f16(o4.x, o4.y);
        p.y = pack_f16(o4.z, o4.w);
        ((uint2*)hf16)[(size_t)row * 16 + q] = p;
    }
}

// ---------------- generic HMMA GEMM (FFN1 + final projection) ----------------
// AMODE: 0 = fp32 A -> bf16 split (3-term) | 2 = u16 fp16 plane copy (2-term)
// POST:  1 = fp32 C + bvec | 4 = relu(v+bvec) -> fp16 Chi
template<int KT, int NT, int AMODE, int POST, int DT>
__global__ void __launch_bounds__(256, 2)
k_mma(const float* __restrict__ A, const u16* __restrict__ Af16,
      const u16* __restrict__ Whi_g, const u16* __restrict__ Wlo_g,
      const float* __restrict__ bvec,
      float* __restrict__ C, u16* __restrict__ Chi_g, int M, int nstride) {
    constexpr int KP = KT + 8;
    constexpr bool THREE = (AMODE == 0);
    constexpr int A_ELEMS = 128 * KP;
    constexpr int B_ELEMS = NT * KP;
    extern __shared__ __align__(16) u16 sm[];
    u16* Ahi = sm;
    u16* Alo = THREE ? (Ahi + A_ELEMS) : Ahi;
    u16* Bhi = (THREE ? Alo : Ahi) + A_ELEMS;
    u16* Blo = Bhi + B_ELEMS;

    const int tid = threadIdx.x;
    const int wid = tid >> 5, lane = tid & 31;
    const int row0 = blockIdx.x * 128;
    const int col_base = blockIdx.y * NT;
    Whi_g += (size_t)col_base * KT;
    Wlo_g += (size_t)col_base * KT;

    // ---- fill A ----
    if (AMODE == 0) {
        constexpr int KH = KT / 2;
        for (int idx = tid; idx < 128 * KH; idx += 256) {
            int r = idx / KH, kp = idx - r * KH, k = kp * 2;
            int gr = row0 + r;
            float a0 = 0.f, a1 = 0.f;
            if (gr < M) {
                float2 t = ((const float2*)A)[(size_t)gr * KH + kp];
                a0 = t.x; a1 = t.y;
            }
            uint32_t hi, lo; split2(a0, a1, hi, lo);
            *(uint32_t*)&Ahi[r * KP + k] = hi;
            *(uint32_t*)&Alo[r * KP + k] = lo;
        }
    } else {
        constexpr int K8 = KT / 8;
        const uint4 z4 = make_uint4(0, 0, 0, 0);
        for (int idx = tid; idx < 128 * K8; idx += 256) {
            int r = idx / K8, k8 = idx - r * K8;
            int gr = row0 + r;
            uint4 vh = z4;
            if (gr < M) vh = *(const uint4*)&Af16[(size_t)gr * KT + k8 * 8];
            *(uint4*)&Ahi[r * KP + k8 * 8] = vh;
        }
    }
    // ---- fill B ----
    {
        constexpr int K8 = KT / 8;
        for (int idx = tid; idx < NT * K8; idx += 256) {
            int n = idx / K8, k8 = idx - n * K8;
            *(uint4*)&Bhi[n * KP + k8 * 8] = *(const uint4*)&Whi_g[(size_t)n * KT + k8 * 8];
            *(uint4*)&Blo[n * KP + k8 * 8] = *(const uint4*)&Wlo_g[(size_t)n * KT + k8 * 8];
        }
    }
    __syncthreads();

    constexpr int NW = NT / 2;
    constexpr int NF = NW / 8;
    const int wm = wid & 3, wn = wid >> 2;
    const int mrow = wm * 32;
    const int ncol = wn * NW;

    float acc[2][NF][4];
    #pragma unroll
    for (int i = 0; i < 2; i++)
        #pragma unroll
        for (int nf = 0; nf < NF; nf++)
            #pragma unroll
            for (int j = 0; j < 4; j++) acc[i][nf][j] = 0.f;

    const uint32_t ahi_b = smem_u32(Ahi), alo_b = smem_u32(Alo);
    const uint32_t bhi_b = smem_u32(Bhi), blo_b = smem_u32(Blo);
    const int la  = lane & 15;
    const int lka = (lane >> 4) << 3;
    const int lbn = ((lane >> 4) << 3) + (lane & 7);
    const int lbk = ((lane >> 3) & 1) << 3;

    for (int kb = 0; kb < KT; kb += 16) {
        uint32_t ah[2][4], al[2][4];
        #pragma unroll
        for (int i = 0; i < 2; i++) {
            uint32_t aoff = (uint32_t)(((mrow + i * 16 + la) * KP + kb + lka) * 2);
            ldsm_x4(ah[i], ahi_b + aoff);
            if (THREE) ldsm_x4(al[i], alo_b + aoff);
        }
        #pragma unroll
        for (int nf = 0; nf < NF; nf += 2) {
            uint32_t boff = (uint32_t)(((ncol + nf * 8 + lbn) * KP + kb + lbk) * 2);
            uint32_t bh[4], bl[4];
            ldsm_x4(bh, bhi_b + boff);
            ldsm_x4(bl, blo_b + boff);
            #pragma unroll
            for (int i = 0; i < 2; i++) {
                mma16816<DT>(acc[i][nf],     ah[i], bh);
                mma16816<DT>(acc[i][nf],     ah[i], bl);
                mma16816<DT>(acc[i][nf + 1], ah[i], bh + 2);
                mma16816<DT>(acc[i][nf + 1], ah[i], bl + 2);
                if (THREE) {
                    mma16816<DT>(acc[i][nf],     al[i], bh);
                    mma16816<DT>(acc[i][nf + 1], al[i], bh + 2);
                }
            }
        }
    }

    // ---- epilogue ----
    const int qr = lane >> 2;
    const int qc = (lane & 3) * 2;
    #pragma unroll
    for (int i = 0; i < 2; i++) {
        #pragma unroll
        for (int half = 0; half < 2; half++) {
            int gr = row0 + mrow + i * 16 + half * 8 + qr;
            if (gr < M) {
                #pragma unroll
                for (int nf = 0; nf < NF; nf++) {
                    int c = col_base + ncol + nf * 8 + qc;
                    float v0 = acc[i][nf][half * 2 + 0];
                    float v1 = acc[i][nf][half * 2 + 1];
                    if (POST == 1) {
                        v0 += bvec[c]; v1 += bvec[c + 1];
                        *(float2*)&C[(size_t)gr * nstride + c] = make_float2(v0, v1);
                    } else {
                        float t0 = fmaxf(v0 + bvec[c], 0.f);
                        float t1 = fmaxf(v1 + bvec[c + 1], 0.f);
                        ((uint32_t*)Chi_g)[((size_t)gr * nstride + c) >> 1] = pack_f16(t0, t1);
                    }
                }
            }
        }
    }
}

// ---------------- fused conv kernel: w = f(z@Wa) @ Wb -> fp16 ----------------
__global__ void __launch_bounds__(256, 2)
k_conv(const float* __restrict__ Z,
       const u16* __restrict__ WaHi_g, const u16* __restrict__ WaLo_g,
       const u16* __restrict__ WbHi_g, const u16* __restrict__ WbLo_g,
       const float* __restrict__ rs, const float* __restrict__ ba,
       u16* __restrict__ Wout16, int M) {
    constexpr int KP = 72;
    extern __shared__ __align__(16) u16 sm[];
    u16* Ahi = sm;
    u16* Alo = Ahi + 128 * KP;
    u16* BaH = Alo + 128 * KP;
    u16* BaL = BaH + 64 * KP;
    u16* BbH = BaL + 64 * KP;
    u16* BbL = BbH + 64 * KP;

    const int tid = threadIdx.x;
    const int wid = tid >> 5, lane = tid & 31;
    const int row0 = blockIdx.x * 128;

    for (int idx = tid; idx < 128 * 32; idx += 256) {
        int r = idx >> 5, kp = idx & 31, k = kp * 2;
        int gr = row0 + r;
        float a0 = 0.f, a1 = 0.f;
        if (gr < M) {
            float2 t = ((const float2*)Z)[(size_t)gr * 32 + kp];
            a0 = t.x; a1 = t.y;
        }
        uint32_t hi, lo; split2(a0, a1, hi, lo);
        *(uint32_t*)&Ahi[r * KP + k] = hi;
        *(uint32_t*)&Alo[r * KP + k] = lo;
    }
    for (int idx = tid; idx < 64 * 8; idx += 256) {
        int n = idx >> 3, k8 = idx & 7;
        *(uint4*)&BaH[n * KP + k8 * 8] = *(const uint4*)&WaHi_g[(size_t)n * 64 + k8 * 8];
        *(uint4*)&BaL[n * KP + k8 * 8] = *(const uint4*)&WaLo_g[(size_t)n * 64 + k8 * 8];
        *(uint4*)&BbH[n * KP + k8 * 8] = *(const uint4*)&WbHi_g[(size_t)n * 64 + k8 * 8];
        *(uint4*)&BbL[n * KP + k8 * 8] = *(const uint4*)&WbLo_g[(size_t)n * 64 + k8 * 8];
    }
    __syncthreads();

    const int wm = wid & 3, wn = wid >> 2;
    const int mrow = wm * 32;
    const int ncol = wn * 32;
    const uint32_t ahi_b = smem_u32(Ahi), alo_b = smem_u32(Alo);
    const int la  = lane & 15;
    const int lka = (lane >> 4) << 3;
    const int lbn = ((lane >> 4) << 3) + (lane & 7);
    const int lbk = ((lane >> 3) & 1) << 3;
    const int qr = lane >> 2;
    const int qc = (lane & 3) * 2;

    float acc[2][4][4];
    // ---- mainloop 1: z @ Wa ----
    {
        const uint32_t bh_b = smem_u32(BaH), bl_b = smem_u32(BaL);
        #pragma unroll
        for (int i = 0; i < 2; i++)
            #pragma unroll
            for (int nf = 0; nf < 4; nf++)
                #pragma unroll
                for (int j = 0; j < 4; j++) acc[i][nf][j] = 0.f;
        #pragma unroll
        for (int kb = 0; kb < 64; kb += 16) {
            uint32_t ah[2][4], al[2][4];
            #pragma unroll
            for (int i = 0; i < 2; i++) {
                uint32_t aoff = (uint32_t)(((mrow + i * 16 + la) * KP + kb + lka) * 2);
                ldsm_x4(ah[i], ahi_b + aoff);
                ldsm_x4(al[i], alo_b + aoff);
            }
            #pragma unroll
            for (int nf = 0; nf < 4; nf += 2) {
                uint32_t boff = (uint32_t)(((ncol + nf * 8 + lbn) * KP + kb + lbk) * 2);
                uint32_t bh[4], bl[4];
                ldsm_x4(bh, bh_b + boff);
                ldsm_x4(bl, bl_b + boff);
                #pragma unroll
                for (int i = 0; i < 2; i++) {
                    mma16816<0>(acc[i][nf],     ah[i], bh);
                    mma16816<0>(acc[i][nf],     ah[i], bl);
                    mma16816<0>(acc[i][nf],     al[i], bh);
                    mma16816<0>(acc[i][nf + 1], ah[i], bh + 2);
                    mma16816<0>(acc[i][nf + 1], ah[i], bl + 2);
                    mma16816<0>(acc[i][nf + 1], al[i], bh + 2);
                }
            }
        }
    }
    __syncthreads();

    // ---- epilogue 1: y -> split bf16, back into A smem ----
    #pragma unroll
    for (int i = 0; i < 2; i++) {
        #pragma unroll
        for (int half = 0; half < 2; half++) {
            int rloc = mrow + i * 16 + half * 8 + qr;
            int gr = row0 + rloc;
            float s = (gr < M) ? rs[gr] : 0.f;
            #pragma unroll
            for (int nf = 0; nf < 4; nf++) {
                int c = ncol + nf * 8 + qc;
                float y0 = (acc[i][nf][half * 2 + 0] * s + ba[c]) * s;
                float y1 = (acc[i][nf][half * 2 + 1] * s + ba[c + 1]) * s;
                uint32_t hi, lo; split2(y0, y1, hi, lo);
                *(uint32_t*)&Ahi[rloc * KP + c] = hi;
                *(uint32_t*)&Alo[rloc * KP + c] = lo;
            }
        }
    }
    __syncthreads();

    // ---- mainloop 2: y @ Wb ----
    {
        const uint32_t bh_b = smem_u32(BbH), bl_b = smem_u32(BbL);
        #pragma unroll
        for (int i = 0; i < 2; i++)
            #pragma unroll
            for (int nf = 0; nf < 4; nf++)
                #pragma unroll
                for (int j = 0; j < 4; j++) acc[i][nf][j] = 0.f;
        #pragma unroll
        for (int kb = 0; kb < 64; kb += 16) {
            uint32_t ah[2][4], al[2][4];
            #pragma unroll
            for (int i = 0; i < 2; i++) {
                uint32_t aoff = (uint32_t)(((mrow + i * 16 + la) * KP + kb + lka) * 2);
                ldsm_x4(ah[i], ahi_b + aoff);
                ldsm_x4(al[i], alo_b + aoff);
            }
            #pragma unroll
            for (int nf = 0; nf < 4; nf += 2) {
                uint32_t boff = (uint32_t)(((ncol + nf * 8 + lbn) * KP + kb + lbk) * 2);
                uint32_t bh[4], bl[4];
                ldsm_x4(bh, bh_b + boff);
                ldsm_x4(bl, bl_b + boff);
                #pragma unroll
                for (int i = 0; i < 2; i++) {
                    mma16816<0>(acc[i][nf],     ah[i], bh);
                    mma16816<0>(acc[i][nf],     ah[i], bl);
                    mma16816<0>(acc[i][nf],     al[i], bh);
                    mma16816<0>(acc[i][nf + 1], ah[i], bh + 2);
                    mma16816<0>(acc[i][nf + 1], ah[i], bl + 2);
                    mma16816<0>(acc[i][nf + 1], al[i], bh + 2);
                }
            }
        }
    }
    // ---- epilogue 2: w -> gmem fp16 ----
    #pragma unroll
    for (int i = 0; i < 2; i++) {
        #pragma unroll
        for (int half = 0; half < 2; half++) {
            int gr = row0 + mrow + i * 16 + half * 8 + qr;
            if (gr < M) {
                #pragma unroll
                for (int nf = 0; nf < 4; nf++) {
                    int c = ncol + nf * 8 + qc;
                    ((uint32_t*)Wout16)[((size_t)gr * 64 + c) >> 1] =
                        pack_f16(acc[i][nf][half * 2 + 0], acc[i][nf][half * 2 + 1]);
                }
            }
        }
    }
}

// --------- FFN2 fused with residual + LN2: h = LN(h + T@W2 + c2) -------------
__global__ void __launch_bounds__(256, 2)
k_ffn2_ln(const u16* __restrict__ T, const u16* __restrict__ Whi_g,
          const u16* __restrict__ Wlo_g, const float* __restrict__ bvec,
          const float* __restrict__ g, const float* __restrict__ b,
          float* __restrict__ h, u16* __restrict__ hf16, int M) {
    constexpr int KC = 128, KP = KC + 8;
    extern __shared__ __align__(16) u16 sm[];
    u16* As  = sm;
    u16* Bhi = As + 128 * KP;
    u16* Blo = Bhi + 64 * KP;

    const int tid = threadIdx.x;
    const int wid = tid >> 5, lane = tid & 31;
    const int row0 = blockIdx.x * 128;
    const int wm = wid & 3, wn = wid >> 2;
    const int mrow = wm * 32;
    const int ncol = wn * 32;
    const int la  = lane & 15;
    const int lka = (lane >> 4) << 3;
    const int lbn = ((lane >> 4) << 3) + (lane & 7);
    const int lbk = ((lane >> 3) & 1) << 3;

    float acc[2][4][4];
    #pragma unroll
    for (int i = 0; i < 2; i++)
        #pragma unroll
        for (int nf = 0; nf < 4; nf++)
            #pragma unroll
            for (int j = 0; j < 4; j++) acc[i][nf][j] = 0.f;

    const uint32_t as_b = smem_u32(As);
    const uint32_t bh_b = smem_u32(Bhi), bl_b = smem_u32(Blo);
    const uint4 z4 = make_uint4(0, 0, 0, 0);

    for (int kc = 0; kc < 2; kc++) {
        __syncthreads();
        for (int idx = tid; idx < 128 * 16; idx += 256) {
            int r = idx >> 4, k8 = idx & 15;
            int gr = row0 + r;
            uint4 v = z4;
            if (gr < M) v = *(const uint4*)&T[(size_t)gr * 256 + kc * 128 + k8 * 8];
            *(uint4*)&As[r * KP + k8 * 8] = v;
        }
        for (int idx = tid; idx < 64 * 16; idx += 256) {
            int n = idx >> 4, k8 = idx & 15;
            *(uint4*)&Bhi[n * KP + k8 * 8] = *(const uint4*)&Whi_g[(size_t)n * 256 + kc * 128 + k8 * 8];
            *(uint4*)&Blo[n * KP + k8 * 8] = *(const uint4*)&Wlo_g[(size_t)n * 256 + kc * 128 + k8 * 8];
        }
        __syncthreads();
        for (int kb = 0; kb < KC; kb += 16) {
            uint32_t ah[2][4];
            #pragma unroll
            for (int i = 0; i < 2; i++) {
                uint32_t aoff = (uint32_t)(((mrow + i * 16 + la) * KP + kb + lka) * 2);
                ldsm_x4(ah[i], as_b + aoff);
            }
            #pragma unroll
            for (int nf = 0; nf < 4; nf += 2) {
                uint32_t boff = (uint32_t)(((ncol + nf * 8 + lbn) * KP + kb + lbk) * 2);
                uint32_t bh[4], bl[4];
                ldsm_x4(bh, bh_b + boff);
                ldsm_x4(bl, bl_b + boff);
                #pragma unroll
                for (int i = 0; i < 2; i++) {
                    mma16816<1>(acc[i][nf],     ah[i], bh);
                    mma16816<1>(acc[i][nf],     ah[i], bl);
                    mma16816<1>(acc[i][nf + 1], ah[i], bh + 2);
                    mma16816<1>(acc[i][nf + 1], ah[i], bl + 2);
                }
            }
        }
    }

    // ---- stage x = h + U + c2 into smem (fp32, stride 72) ----
    __syncthreads();
    float* xs = (float*)sm;       // 128 x 72 floats = 36864 B (fits in smem block)
    const int qr = lane >> 2;
    const int qc = (lane & 3) * 2;
    #pragma unroll
    for (int i = 0; i < 2; i++) {
        #pragma unroll
        for (int half = 0; half < 2; half++) {
            int rloc = mrow + i * 16 + half * 8 + qr;
            int gr = row0 + rloc;
            #pragma unroll
            for (int nf = 0; nf < 4; nf++) {
                int c = ncol + nf * 8 + qc;
                float x0 = 0.f, x1 = 0.f;
                if (gr < M) {
                    float2 hres = *(const float2*)&h[(size_t)gr * 64 + c];
                    x0 = acc[i][nf][half * 2 + 0] + bvec[c] + hres.x;
                    x1 = acc[i][nf][half * 2 + 1] + bvec[c + 1] + hres.y;
                }
                xs[rloc * 72 + c]     = x0;
                xs[rloc * 72 + c + 1] = x1;
            }
        }
    }
    __syncthreads();

    // ---- LN: warp wid handles rows wid*16 .. wid*16+15 ----
    const int c0 = lane * 2;
    for (int rr = 0; rr < 16; rr++) {
        int rloc = wid * 16 + rr;
        int gr = row0 + rloc;
        if (gr >= M) continue;
        float x0 = xs[rloc * 72 + c0];
        float x1 = xs[rloc * 72 + c0 + 1];
        float sum = x0 + x1;
        #pragma unroll
        for (int o = 16; o; o >>= 1) sum += __shfl_xor_sync(0xffffffffu, sum, o);
        float mu = sum * (1.0f / 64.0f);
        float d0 = x0 - mu, d1 = x1 - mu;
        float vs = d0 * d0 + d1 * d1;
        #pragma unroll
        for (int o = 16; o; o >>= 1) vs += __shfl_xor_sync(0xffffffffu, vs, o);
        float inv = rsqrtf(vs * (1.0f / 64.0f) + 1e-5f);
        float o0 = fmaf(d0 * inv, g[c0], b[c0]);
        float o1 = fmaf(d1 * inv, g[c0 + 1], b[c0 + 1]);
        *(float2*)&h[(size_t)gr * 64 + c0] = make_float2(o0, o1);
        ((uint32_t*)hf16)[((size_t)gr * 64 + c0) >> 1] = pack_f16(o0, o1);
    }
}

// ---------------- LayerNorm (standalone, final) ------------------------------
__global__ void k_lnF(const float* __restrict__ base,
                      const float* __restrict__ g, const float* __restrict__ b,
                      float* __restrict__ out, int M) {
    const int warp = threadIdx.x >> 5;
    const int lane = threadIdx.x & 31;
    const int row = blockIdx.x * (blockDim.x >> 5) + warp;
    if (row >= M) return;
    const int i0 = row * 64 + lane;
    const int i1 = i0 + 32;
    float x0 = base[i0], x1 = base[i1];
    float sum = x0 + x1;
    #pragma unroll
    for (int o = 16; o; o >>= 1) sum += __shfl_xor_sync(0xffffffffu, sum, o);
    float mu = sum * (1.0f / 64.0f);
    float d0 = x0 - mu, d1 = x1 - mu;
    float vs = d0 * d0 + d1 * d1;
    #pragma unroll
    for (int o = 16; o; o >>= 1) vs += __shfl_xor_sync(0xffffffffu, vs, o);
    float inv = rsqrtf(vs * (1.0f / 64.0f) + 1e-5f);
    out[i0] = fmaf(d0 * inv, g[lane], b[lane]);
    out[i1] = fmaf(d1 * inv, g[lane + 32], b[lane + 32]);
}

// ---------------- orchestration ----------------------------------------------
extern "C" void kernel_launch(void* const* d_in, const int* in_sizes, int n_in,
                              void* d_out, int out_size) {
    const float* x    = (const float*)d_in[0];
    const int*   esrc = (const int*)d_in[1];
    const int*   edst = (const int*)d_in[2];
    const int wi = (n_in >= 20) ? 4 : 3;
    const float* Wn2h = (const float*)d_in[wi + 0];
    const float* bn2h = (const float*)d_in[wi + 1];
    const float* Wh2n = (const float*)d_in[wi + 2];
    const float* bh2n = (const float*)d_in[wi + 3];
    const float* W1   = (const float*)d_in[wi + 4];
    const float* b1   = (const float*)d_in[wi + 5];
    const float* W2   = (const float*)d_in[wi + 6];
    const float* b2   = (const float*)d_in[wi + 7];
    const float* g1   = (const float*)d_in[wi + 8];
    const float* be1  = (const float*)d_in[wi + 9];
    const float* g2   = (const float*)d_in[wi + 10];
    const float* be2  = (const float*)d_in[wi + 11];
    const float* gF   = (const float*)d_in[wi + 12];
    const float* bF   = (const float*)d_in[wi + 13];
    const float* Wo   = (const float*)d_in[wi + 14];
    const float* bo   = (const float*)d_in[wi + 15];

    float *p_h, *p_b1, *p_ha, *p_invn, *p_invh;
    u16 *p_hf16, *p_wf16, *p_thi;
    u16 *p_wa_hi, *p_wa_lo, *p_wb_hi, *p_wb_lo, *p_w1_hi, *p_w1_lo;
    u16 *p_w2_hi, *p_w2_lo, *p_wo_hi, *p_wo_lo;
    int *p_cntH, *p_cntN, *p_stH, *p_stN, *p_cuH, *p_cuN, *p_csrH, *p_csrN;
    cudaGetSymbolAddress((void**)&p_h,    g_h);
    cudaGetSymbolAddress((void**)&p_b1,   g_b1);
    cudaGetSymbolAddress((void**)&p_hf16, g_hf16);
    cudaGetSymbolAddress((void**)&p_ha,   g_ha);
    cudaGetSymbolAddress((void**)&p_wf16, g_wf16);
    cudaGetSymbolAddress((void**)&p_thi,  g_thi);
    cudaGetSymbolAddress((void**)&p_wa_hi, g_wa_hi);
    cudaGetSymbolAddress((void**)&p_wa_lo, g_wa_lo);
    cudaGetSymbolAddress((void**)&p_wb_hi, g_wb_hi);
    cudaGetSymbolAddress((void**)&p_wb_lo, g_wb_lo);
    cudaGetSymbolAddress((void**)&p_w1_hi, g_w1_hi);
    cudaGetSymbolAddress((void**)&p_w1_lo, g_w1_lo);
    cudaGetSymbolAddress((void**)&p_w2_hi, g_w2_hi);
    cudaGetSymbolAddress((void**)&p_w2_lo, g_w2_lo);
    cudaGetSymbolAddress((void**)&p_wo_hi, g_wo_hi);
    cudaGetSymbolAddress((void**)&p_wo_lo, g_wo_lo);
    cudaGetSymbolAddress((void**)&p_invn, g_invn);
    cudaGetSymbolAddress((void**)&p_invh, g_invh);
    cudaGetSymbolAddress((void**)&p_cntH, g_cntH);
    cudaGetSymbolAddress((void**)&p_cntN, g_cntN);
    cudaGetSymbolAddress((void**)&p_stH,  g_startH);
    cudaGetSymbolAddress((void**)&p_stN,  g_startN);
    cudaGetSymbolAddress((void**)&p_cuH,  g_curH);
    cudaGetSymbolAddress((void**)&p_cuN,  g_curN);
    cudaGetSymbolAddress((void**)&p_csrH, g_csrH);
    cudaGetSymbolAddress((void**)&p_csrN, g_csrN);

    const int smem_convf = (2 * 128 * 72 + 4 * 64 * 72) * 2;   //  73728
    const int smem_ffn1  = (1 * 128 * 72 + 2 * 128 * 72) * 2;  //  55296
    const int smem_ffn2  = (128 * 136 + 2 * 64 * 136) * 2;     //  69632
    const int smem_proj  = (2 * 128 * 72 + 2 * 64 * 72) * 2;   //  55296
    cudaFuncSetAttribute((const void*)k_conv, cudaFuncAttributeMaxDynamicSharedMemorySize, smem_convf);
    cudaFuncSetAttribute((const void*)k_mma<64, 128, 2, 4, 1>, cudaFuncAttributeMaxDynamicSharedMemorySize, smem_ffn1);
    cudaFuncSetAttribute((const void*)k_ffn2_ln, cudaFuncAttributeMaxDynamicSharedMemorySize, smem_ffn2);
    cudaFuncSetAttribute((const void*)k_mma<64, 64, 0, 1, 0>, cudaFuncAttributeMaxDynamicSharedMemorySize, smem_proj);

    cudaMemcpyAsync(p_h, x, (size_t)NN * DD * sizeof(float), cudaMemcpyDeviceToDevice);
    k_f2h<<<(NN * 32 + 255) / 256, 256>>>(x, p_hf16, NN * 32);

    // ---- weight pre-split ----
    k_prep<0><<<(LL * DD * DD + 255) / 256, 256>>>(Wn2h, DD, DD, LL * DD * DD, p_wa_hi, p_wa_lo);
    k_prep<0><<<(LL * DD * DD + 255) / 256, 256>>>(Wh2n, DD, DD, LL * DD * DD, p_wb_hi, p_wb_lo);
    k_prep<1><<<(LL * DD * FF + 255) / 256, 256>>>(W1, DD, FF, LL * DD * FF, p_w1_hi, p_w1_lo);
    k_prep<1><<<(LL * FF * DD + 255) / 256, 256>>>(W2, FF, DD, LL * FF * DD, p_w2_hi, p_w2_lo);
    k_prep<0><<<(DD * DD + 255) / 256, 256>>>(Wo, DD, DD, DD * DD, p_wo_hi, p_wo_lo);

    // ---- build CSR + degree norms ----
    k_zeroi<<<256, 256>>>(p_cntN, NN);
    k_zeroi<<<64, 256>>>(p_cntH, HH);
    k_zeroi<<<256, 256>>>(p_cuN, NN);
    k_zeroi<<<64, 256>>>(p_cuH, HH);
    k_hist<<<(EE + 255) / 256, 256>>>(esrc, edst, p_cntN, p_cntH);
    k_scan<<<1, 1024>>>(p_cntH, p_stH, HH);
    k_scan<<<1, 1024>>>(p_cntN, p_stN, NN);
    k_fill<<<(EE + 255) / 256, 256>>>(esrc, edst, p_stH, p_stN, p_cuH, p_cuN, p_csrH, p_csrN);
    k_inv<<<(NN + 255) / 256, 256>>>(p_cntN, p_cntH, p_invn, p_invh);

    const int gN  = (NN + 127) / 128;
    const int gH  = (HH + 127) / 128;
    const int gLN = (NN + 7) / 8;
    const int gAgH = (HH + 7) / 8;
    const int gAgN = (NN + 7) / 8;

    for (int l = 0; l < LL; l++) {
        const float* ba = bn2h + (size_t)l * DD;
        const float* bb = bh2n + (size_t)l * DD;
        const float* c1 = b1 + (size_t)l * FF;
        const float* c2 = b2 + (size_t)l * DD;
        const float* gg1 = g1 + (size_t)l * DD;
        const float* ee1 = be1 + (size_t)l * DD;
        const float* gg2 = g2 + (size_t)l * DD;
        const float* ee2 = be2 + (size_t)l * DD;

        // z = agg_H(hf16 * invn[src])
        k_agg16<<<gAgH, 256>>>(p_hf16, p_csrH, p_stH, p_cntH, p_invn, p_ha, HH);
        // fused: y = (z@Wa*invh+ba)*invh ; w = y@Wb -> fp16
        k_conv<<<gH, 256, smem_convf>>>(
            p_ha, p_wa_hi + (size_t)l * DD * DD, p_wa_lo + (size_t)l * DD * DD,
            p_wb_hi + (size_t)l * DD * DD, p_wb_lo + (size_t)l * DD * DD,
            p_invh, ba, p_wf16, HH);
        // fused: u = agg_N(wf16); h = LN(h + u*invn + bb) -> h fp32 + fp16
        k_agg_ln16<<<gAgN, 256>>>(p_wf16, p_csrN, p_stN, p_cntN, p_invn, bb,
                                  gg1, ee1, p_h, p_hf16, NN);
        // FFN1: T = relu(hf16@W1 + c1) -> fp16 (2-term fp16)
        k_mma<64, 128, 2, 4, 1><<<dim3(gN, 2), 256, smem_ffn1>>>(
            nullptr, p_hf16, p_w1_hi + (size_t)l * DD * FF, p_w1_lo + (size_t)l * DD * FF,
            c1, nullptr, p_thi, NN, FF);
        // FFN2 fused with residual + LN2 -> h fp32 + fp16
        k_ffn2_ln<<<gN, 256, smem_ffn2>>>(
            p_thi, p_w2_hi + (size_t)l * FF * DD, p_w2_lo + (size_t)l * FF * DD,
            c2, gg2, ee2, p_h, p_hf16, NN);
    }

    // final LN + projection
    k_lnF<<<gLN, 256>>>(p_h, gF, bF, p_b1, NN);
    k_mma<64, 64, 0, 1, 0><<<gN, 256, smem_proj>>>(
        p_b1, nullptr, p_wo_hi, p_wo_lo, bo, (float*)d_out, nullptr, NN, DD);
}

// round 10
// speedup vs baseline: 1.6348x; 1.1914x over previous
#include <cuda_runtime.h>
#include <cuda_bf16.h>
#include <cuda_fp16.h>
#include <cstdint>
#include <math.h>

#define NN 100000
#define HH 20000
#define EE 1600000
#define DD 64
#define FF 256
#define LL 3

typedef unsigned short u16;

// ---------------- helpers ----------------------------------------------------
__device__ __forceinline__ uint32_t smem_u32(const void* p) {
    uint32_t a;
    asm("{ .reg .u64 t; cvta.to.shared.u64 t, %1; cvt.u32.u64 %0, t; }" : "=r"(a) : "l"(p));
    return a;
}
__device__ __forceinline__ void ldsm_x4(uint32_t* r, uint32_t addr) {
    asm volatile("ldmatrix.sync.aligned.m8n8.x4.shared.b16 {%0,%1,%2,%3}, [%4];"
                 : "=r"(r[0]), "=r"(r[1]), "=r"(r[2]), "=r"(r[3]) : "r"(addr));
}
// DT 0 = bf16, 1 = fp16
template<int DT>
__device__ __forceinline__ void mma16816(float* d, const uint32_t* a, const uint32_t* b) {
    if (DT == 0)
        asm volatile("mma.sync.aligned.m16n8k16.row.col.f32.bf16.bf16.f32 "
                     "{%0,%1,%2,%3}, {%4,%5,%6,%7}, {%8,%9}, {%0,%1,%2,%3};"
                     : "+f"(d[0]), "+f"(d[1]), "+f"(d[2]), "+f"(d[3])
                     : "r"(a[0]), "r"(a[1]), "r"(a[2]), "r"(a[3]), "r"(b[0]), "r"(b[1]));
    else
        asm volatile("mma.sync.aligned.m16n8k16.row.col.f32.f16.f16.f32 "
                     "{%0,%1,%2,%3}, {%4,%5,%6,%7}, {%8,%9}, {%0,%1,%2,%3};"
                     : "+f"(d[0]), "+f"(d[1]), "+f"(d[2]), "+f"(d[3])
                     : "r"(a[0]), "r"(a[1]), "r"(a[2]), "r"(a[3]), "r"(b[0]), "r"(b[1]));
}
__device__ __forceinline__ void split2(float a, float b, uint32_t& hi, uint32_t& lo) {
    __nv_bfloat16 ha = __float2bfloat16(a), hb = __float2bfloat16(b);
    float ra = a - __bfloat162float(ha);
    float rb = b - __bfloat162float(hb);
    __nv_bfloat16 la = __float2bfloat16(ra), lb = __float2bfloat16(rb);
    hi = (uint32_t)__bfloat16_as_ushort(ha) | ((uint32_t)__bfloat16_as_ushort(hb) << 16);
    lo = (uint32_t)__bfloat16_as_ushort(la) | ((uint32_t)__bfloat16_as_ushort(lb) << 16);
}
__device__ __forceinline__ uint32_t pack_f16(float lo, float hi) {
    __half2 h = __floats2half2_rn(lo, hi);
    return *(uint32_t*)&h;
}
__device__ __forceinline__ void unpack_f16(uint32_t v, float& lo, float& hi) {
    __half2 h = *(__half2*)&v;
    float2 f = __half22float2(h);
    lo = f.x; hi = f.y;
}

// ---------------- scratch ----------------------------------------------------
__device__ __align__(16) float g_h  [NN * DD];
__device__ __align__(16) float g_b1 [NN * DD];
__device__ __align__(16) u16 g_hf16[NN * DD];
__device__ __align__(16) float g_ha [HH * DD];
__device__ __align__(16) u16 g_wf16[HH * DD];
__device__ __align__(16) u16 g_thi [NN * FF];
__device__ __align__(16) u16 g_wa_hi[LL * DD * DD];   // bf16
__device__ __align__(16) u16 g_wa_lo[LL * DD * DD];
__device__ __align__(16) u16 g_wb_hi[LL * DD * DD];   // bf16
__device__ __align__(16) u16 g_wb_lo[LL * DD * DD];
__device__ __align__(16) u16 g_w1_hi[LL * DD * FF];   // fp16 (single plane used)
__device__ __align__(16) u16 g_w1_lo[LL * DD * FF];
__device__ __align__(16) u16 g_w2_hi[LL * FF * DD];   // fp16 (single plane used)
__device__ __align__(16) u16 g_w2_lo[LL * FF * DD];
__device__ __align__(16) u16 g_wo_hi[DD * DD];        // bf16
__device__ __align__(16) u16 g_wo_lo[DD * DD];
__device__ float g_invn[NN];
__device__ float g_invh[HH];
__device__ int g_cntH [HH];
__device__ int g_cntN [NN];
__device__ int g_startH[HH];
__device__ int g_startN[NN];
__device__ int g_curH [HH];
__device__ int g_curN [NN];
__device__ int g_csrH [EE];
__device__ int g_csrN [EE];
__device__ int g_bsumN[128];
__device__ int g_boffN[128];
__device__ int g_bsumH[32];
__device__ int g_boffH[32];

// ---------------- weight prep ------------------------------------------------
template<int DT>
__global__ void k_prep(const float* __restrict__ src, int K, int N, int total,
                       u16* __restrict__ hi, u16* __restrict__ lo) {
    int idx = blockIdx.x * blockDim.x + threadIdx.x;
    if (idx >= total) return;
    int KN = K * N;
    int l = idx / KN;
    int r = idx - l * KN;
    int k = r / N, n = r - k * N;
    float v = src[idx];
    u16 h_bits, l_bits;
    if (DT == 0) {
        __nv_bfloat16 h = __float2bfloat16(v);
        float res = v - __bfloat162float(h);
        h_bits = __bfloat16_as_ushort(h);
        l_bits = __bfloat16_as_ushort(__float2bfloat16(res));
    } else {
        __half h = __float2half_rn(v);
        float res = v - __half2float(h);
        h_bits = __half_as_ushort(h);
        l_bits = __half_as_ushort(__float2half_rn(res));
    }
    size_t o = (size_t)l * KN + (size_t)n * K + k;
    hi[o] = h_bits;
    lo[o] = l_bits;
}

__global__ void k_f2h(const float* __restrict__ src, u16* __restrict__ dst, int n2) {
    int i = blockIdx.x * blockDim.x + threadIdx.x;
    if (i < n2) {
        float2 v = ((const float2*)src)[i];
        ((uint32_t*)dst)[i] = pack_f16(v.x, v.y);
    }
}

// ---------------- CSR build --------------------------------------------------
__global__ void k_zero4(int* __restrict__ a, int na, int* __restrict__ b, int nb,
                        int* __restrict__ c, int nc, int* __restrict__ d, int nd) {
    int i = blockIdx.x * blockDim.x + threadIdx.x;
    int stride = gridDim.x * blockDim.x;
    for (int j = i; j < na; j += stride) a[j] = 0;
    for (int j = i; j < nb; j += stride) b[j] = 0;
    for (int j = i; j < nc; j += stride) c[j] = 0;
    for (int j = i; j < nd; j += stride) d[j] = 0;
}

__global__ void k_hist(const int* __restrict__ src, const int* __restrict__ dst,
                       int* __restrict__ cntN, int* __restrict__ cntH) {
    int e = blockIdx.x * blockDim.x + threadIdx.x;
    if (e < EE) {
        atomicAdd(&cntN[src[e]], 1);
        atomicAdd(&cntH[dst[e]], 1);
    }
}

// per-1024-chunk sums
__global__ void k_bsum(const int* __restrict__ cnt, int* __restrict__ bsum, int n) {
    __shared__ int sw[32];
    const int tid = threadIdx.x, lane = tid & 31, warp = tid >> 5;
    int i = blockIdx.x * 1024 + tid;
    int v = (i < n) ? cnt[i] : 0;
    #pragma unroll
    for (int o = 16; o; o >>= 1) v += __shfl_xor_sync(0xffffffffu, v, o);
    if (lane == 0) sw[warp] = v;
    __syncthreads();
    if (warp == 0) {
        int t = sw[lane];
        #pragma unroll
        for (int o = 16; o; o >>= 1) t += __shfl_xor_sync(0xffffffffu, t, o);
        if (lane == 0) bsum[blockIdx.x] = t;
    }
}

// single-block exclusive scan (used for the small block-sum array)
__global__ void k_scan(const int* __restrict__ cnt, int* __restrict__ start, int n) {
    __shared__ int shw[33];
    __shared__ int sh_carry;
    const int tid = threadIdx.x;
    const int lane = tid & 31, warp = tid >> 5;
    if (tid == 0) sh_carry = 0;
    __syncthreads();
    for (int base = 0; base < n; base += 1024) {
        int i = base + tid;
        int v = (i < n) ? cnt[i] : 0;
        int inc = v;
        #pragma unroll
        for (int o = 1; o < 32; o <<= 1) {
            int t = __shfl_up_sync(0xffffffffu, inc, o);
            if (lane >= o) inc += t;
        }
        if (lane == 31) shw[warp] = inc;
        __syncthreads();
        if (warp == 0) {
            int t = shw[lane];
            int winc = t;
            #pragma unroll
            for (int o = 1; o < 32; o <<= 1) {
                int u = __shfl_up_sync(0xffffffffu, winc, o);
                if (lane >= o) winc += u;
            }
            shw[lane] = winc - t;
            if (lane == 31) shw[32] = winc;
        }
        __syncthreads();
        int carry = sh_carry;
        if (i < n) start[i] = carry + shw[warp] + inc - v;
        __syncthreads();
        if (tid == 0) sh_carry = carry + shw[32];
        __syncthreads();
    }
}

// apply: start[i] = boff[chunk] + exclusive-within-chunk
__global__ void k_scan2(const int* __restrict__ cnt, const int* __restrict__ boff,
                        int* __restrict__ start, int n) {
    __shared__ int shw[32];
    const int tid = threadIdx.x, lane = tid & 31, warp = tid >> 5;
    int i = blockIdx.x * 1024 + tid;
    int v = (i < n) ? cnt[i] : 0;
    int inc = v;
    #pragma unroll
    for (int o = 1; o < 32; o <<= 1) {
        int t = __shfl_up_sync(0xffffffffu, inc, o);
        if (lane >= o) inc += t;
    }
    if (lane == 31) shw[warp] = inc;
    __syncthreads();
    if (warp == 0) {
        int t = shw[lane];
        int winc = t;
        #pragma unroll
        for (int o = 1; o < 32; o <<= 1) {
            int u = __shfl_up_sync(0xffffffffu, winc, o);
            if (lane >= o) winc += u;
        }
        shw[lane] = winc - t;
    }
    __syncthreads();
    if (i < n) start[i] = boff[blockIdx.x] + shw[warp] + inc - v;
}

__global__ void k_fill(const int* __restrict__ src, const int* __restrict__ dst,
                       const int* __restrict__ startH, const int* __restrict__ startN,
                       int* __restrict__ curH, int* __restrict__ curN,
                       int* __restrict__ csrH, int* __restrict__ csrN) {
    int e = blockIdx.x * blockDim.x + threadIdx.x;
    if (e < EE) {
        int s = src[e], d = dst[e];
        int p = atomicAdd(&curH[d], 1);
        csrH[startH[d] + p] = s;
        int q = atomicAdd(&curN[s], 1);
        csrN[startN[s] + q] = d;
    }
}

__global__ void k_inv(const int* __restrict__ cntN, const int* __restrict__ cntH,
                      float* __restrict__ invn, float* __restrict__ invh) {
    int i = blockIdx.x * blockDim.x + threadIdx.x;
    if (i < NN) invn[i] = rsqrtf(fmaxf((float)cntN[i], 1.0f));
    if (i < HH) invh[i] = rsqrtf(fmaxf((float)cntH[i], 1.0f));
}

// ------- fp16 gather aggregation (scaled), MLP=4 -----------------------------
__global__ void k_agg16(const u16* __restrict__ Y, const int* __restrict__ csr,
                        const int* __restrict__ start, const int* __restrict__ cnt,
                        const float* __restrict__ scale, float* __restrict__ out, int M) {
    const int warp = threadIdx.x >> 5;
    const int lane = threadIdx.x & 31;
    const int row = blockIdx.x * (blockDim.x >> 5) + warp;
    if (row >= M) return;
    const int half = lane >> 4;
    const int q = lane & 15;
    const int s0 = start[row];
    const int c  = cnt[row];
    const uint2* __restrict__ Y2 = (const uint2*)Y;

    float4 acc = make_float4(0.f, 0.f, 0.f, 0.f);
    int j = half;
    for (; j + 6 < c; j += 8) {
        int i0 = __ldg(&csr[s0 + j]);
        int i1 = __ldg(&csr[s0 + j + 2]);
        int i2 = __ldg(&csr[s0 + j + 4]);
        int i3 = __ldg(&csr[s0 + j + 6]);
        uint2 p0 = Y2[(size_t)i0 * 16 + q];
        uint2 p1 = Y2[(size_t)i1 * 16 + q];
        uint2 p2 = Y2[(size_t)i2 * 16 + q];
        uint2 p3 = Y2[(size_t)i3 * 16 + q];
        float f0 = __ldg(&scale[i0]), f1 = __ldg(&scale[i1]);
        float f2 = __ldg(&scale[i2]), f3 = __ldg(&scale[i3]);
        float a0, a1, a2, a3;
        unpack_f16(p0.x, a0, a1); unpack_f16(p0.y, a2, a3);
        acc.x = fmaf(a0, f0, acc.x); acc.y = fmaf(a1, f0, acc.y);
        acc.z = fmaf(a2, f0, acc.z); acc.w = fmaf(a3, f0, acc.w);
        unpack_f16(p1.x, a0, a1); unpack_f16(p1.y, a2, a3);
        acc.x = fmaf(a0, f1, acc.x); acc.y = fmaf(a1, f1, acc.y);
        acc.z = fmaf(a2, f1, acc.z); acc.w = fmaf(a3, f1, acc.w);
        unpack_f16(p2.x, a0, a1); unpack_f16(p2.y, a2, a3);
        acc.x = fmaf(a0, f2, acc.x); acc.y = fmaf(a1, f2, acc.y);
        acc.z = fmaf(a2, f2, acc.z); acc.w = fmaf(a3, f2, acc.w);
        unpack_f16(p3.x, a0, a1); unpack_f16(p3.y, a2, a3);
        acc.x = fmaf(a0, f3, acc.x); acc.y = fmaf(a1, f3, acc.y);
        acc.z = fmaf(a2, f3, acc.z); acc.w = fmaf(a3, f3, acc.w);
    }
    for (; j < c; j += 2) {
        int i0 = __ldg(&csr[s0 + j]);
        uint2 p0 = Y2[(size_t)i0 * 16 + q];
        float f0 = __ldg(&scale[i0]);
        float a0, a1, a2, a3;
        unpack_f16(p0.x, a0, a1); unpack_f16(p0.y, a2, a3);
        acc.x = fmaf(a0, f0, acc.x); acc.y = fmaf(a1, f0, acc.y);
        acc.z = fmaf(a2, f0, acc.z); acc.w = fmaf(a3, f0, acc.w);
    }
    acc.x += __shfl_xor_sync(0xffffffffu, acc.x, 16);
    acc.y += __shfl_xor_sync(0xffffffffu, acc.y, 16);
    acc.z += __shfl_xor_sync(0xffffffffu, acc.z, 16);
    acc.w += __shfl_xor_sync(0xffffffffu, acc.w, 16);
    if (half == 0) ((float4*)out)[(size_t)row * 16 + q] = acc;
}

// --- fp16 gather + residual + bias + LN (MLP=4), writes h fp32 + fp16 --------
__global__ void k_agg_ln16(const u16* __restrict__ Y, const int* __restrict__ csr,
                           const int* __restrict__ start, const int* __restrict__ cnt,
                           const float* __restrict__ invn, const float* __restrict__ bb,
                           const float* __restrict__ g, const float* __restrict__ b,
                           float* __restrict__ h, u16* __restrict__ hf16, int M) {
    const int warp = threadIdx.x >> 5;
    const int lane = threadIdx.x & 31;
    const int row = blockIdx.x * (blockDim.x >> 5) + warp;
    if (row >= M) return;
    const int half = lane >> 4;
    const int q = lane & 15;
    const int s0 = start[row];
    const int c  = cnt[row];
    const uint2* __restrict__ Y2 = (const uint2*)Y;

    float4 acc = make_float4(0.f, 0.f, 0.f, 0.f);
    int j = half;
    for (; j + 6 < c; j += 8) {
        int i0 = __ldg(&csr[s0 + j]);
        int i1 = __ldg(&csr[s0 + j + 2]);
        int i2 = __ldg(&csr[s0 + j + 4]);
        int i3 = __ldg(&csr[s0 + j + 6]);
        uint2 p0 = Y2[(size_t)i0 * 16 + q];
        uint2 p1 = Y2[(size_t)i1 * 16 + q];
        uint2 p2 = Y2[(size_t)i2 * 16 + q];
        uint2 p3 = Y2[(size_t)i3 * 16 + q];
        float a0, a1, a2, a3;
        unpack_f16(p0.x, a0, a1); unpack_f16(p0.y, a2, a3);
        acc.x += a0; acc.y += a1; acc.z += a2; acc.w += a3;
        unpack_f16(p1.x, a0, a1); unpack_f16(p1.y, a2, a3);
        acc.x += a0; acc.y += a1; acc.z += a2; acc.w += a3;
        unpack_f16(p2.x, a0, a1); unpack_f16(p2.y, a2, a3);
        acc.x += a0; acc.y += a1; acc.z += a2; acc.w += a3;
        unpack_f16(p3.x, a0, a1); unpack_f16(p3.y, a2, a3);
        acc.x += a0; acc.y += a1; acc.z += a2; acc.w += a3;
    }
    for (; j < c; j += 2) {
        int i0 = __ldg(&csr[s0 + j]);
        uint2 p0 = Y2[(size_t)i0 * 16 + q];
        float a0, a1, a2, a3;
        unpack_f16(p0.x, a0, a1); unpack_f16(p0.y, a2, a3);
        acc.x += a0; acc.y += a1; acc.z += a2; acc.w += a3;
    }
    acc.x += __shfl_xor_sync(0xffffffffu, acc.x, 16);
    acc.y += __shfl_xor_sync(0xffffffffu, acc.y, 16);
    acc.z += __shfl_xor_sync(0xffffffffu, acc.z, 16);
    acc.w += __shfl_xor_sync(0xffffffffu, acc.w, 16);

    const float s = invn[row];
    float4 hr = ((const float4*)h)[(size_t)row * 16 + q];
    float4 bv = *(const float4*)&bb[q * 4];
    float x0 = fmaf(acc.x, s, hr.x) + bv.x;
    float x1 = fmaf(acc.y, s, hr.y) + bv.y;
    float x2 = fmaf(acc.z, s, hr.z) + bv.z;
    float x3 = fmaf(acc.w, s, hr.w) + bv.w;
    float psum = x0 + x1 + x2 + x3;
    #pragma unroll
    for (int o = 16; o; o >>= 1) psum += __shfl_xor_sync(0xffffffffu, psum, o);
    float mu = psum * (1.0f / 128.0f);
    float d0 = x0 - mu, d1 = x1 - mu, d2 = x2 - mu, d3 = x3 - mu;
    float pvar = d0 * d0 + d1 * d1 + d2 * d2 + d3 * d3;
    #pragma unroll
    for (int o = 16; o; o >>= 1) pvar += __shfl_xor_sync(0xffffffffu, pvar, o);
    float inv = rsqrtf(pvar * (1.0f / 128.0f) + 1e-5f);
    if (half == 0) {
        float4 gv = *(const float4*)&g[q * 4];
        float4 bvv = *(const float4*)&b[q * 4];
        float4 o4;
        o4.x = fmaf(d0 * inv, gv.x, bvv.x);
        o4.y = fmaf(d1 * inv, gv.y, bvv.y);
        o4.z = fmaf(d2 * inv, gv.z, bvv.z);
        o4.w = fmaf(d3 * inv, gv.w, bvv.w);
        ((float4*)h)[(size_t)row * 16 + q] = o4;
        uint2 p;
        p.x = pack_f16(o4.x, o4.y);
        p.y = pack_f16(o4.z, o4.w);
        ((uint2*)hf16)[(size_t)row * 16 + q] = p;
    }
}

// ---------------- generic HMMA GEMM ------------------------------------------
// AMODE: 0 = fp32 A -> bf16 split (A 3-term) | 2 = u16 fp16 plane copy
// BT: 1 = B hi only | 2 = B hi+lo
// POST: 1 = fp32 C + bvec | 4 = relu(v+bvec) -> fp16 Chi
template<int KT, int NT, int AMODE, int POST, int DT, int BT>
__global__ void __launch_bounds__(256, 2)
k_mma(const float* __restrict__ A, const u16* __restrict__ Af16,
      const u16* __restrict__ Whi_g, const u16* __restrict__ Wlo_g,
      const float* __restrict__ bvec,
      float* __restrict__ C, u16* __restrict__ Chi_g, int M, int nstride) {
    constexpr int KP = KT + 8;
    constexpr bool THREE = (AMODE == 0);
    constexpr bool BLO = (BT == 2);
    constexpr int A_ELEMS = 128 * KP;
    constexpr int B_ELEMS = NT * KP;
    extern __shared__ __align__(16) u16 sm[];
    u16* Ahi = sm;
    u16* Alo = THREE ? (Ahi + A_ELEMS) : Ahi;
    u16* Bhi = (THREE ? Alo : Ahi) + A_ELEMS;
    u16* Blo = BLO ? (Bhi + B_ELEMS) : Bhi;

    const int tid = threadIdx.x;
    const int wid = tid >> 5, lane = tid & 31;
    const int row0 = blockIdx.x * 128;
    const int col_base = blockIdx.y * NT;
    Whi_g += (size_t)col_base * KT;
    Wlo_g += (size_t)col_base * KT;

    // ---- fill A ----
    if (AMODE == 0) {
        constexpr int KH = KT / 2;
        for (int idx = tid; idx < 128 * KH; idx += 256) {
            int r = idx / KH, kp = idx - r * KH, k = kp * 2;
            int gr = row0 + r;
            float a0 = 0.f, a1 = 0.f;
            if (gr < M) {
                float2 t = ((const float2*)A)[(size_t)gr * KH + kp];
                a0 = t.x; a1 = t.y;
            }
            uint32_t hi, lo; split2(a0, a1, hi, lo);
            *(uint32_t*)&Ahi[r * KP + k] = hi;
            *(uint32_t*)&Alo[r * KP + k] = lo;
        }
    } else {
        constexpr int K8 = KT / 8;
        const uint4 z4 = make_uint4(0, 0, 0, 0);
        for (int idx = tid; idx < 128 * K8; idx += 256) {
            int r = idx / K8, k8 = idx - r * K8;
            int gr = row0 + r;
            uint4 vh = z4;
            if (gr < M) vh = *(const uint4*)&Af16[(size_t)gr * KT + k8 * 8];
            *(uint4*)&Ahi[r * KP + k8 * 8] = vh;
        }
    }
    // ---- fill B ----
    {
        constexpr int K8 = KT / 8;
        for (int idx = tid; idx < NT * K8; idx += 256) {
            int n = idx / K8, k8 = idx - n * K8;
            *(uint4*)&Bhi[n * KP + k8 * 8] = *(const uint4*)&Whi_g[(size_t)n * KT + k8 * 8];
            if (BLO)
                *(uint4*)&Blo[n * KP + k8 * 8] = *(const uint4*)&Wlo_g[(size_t)n * KT + k8 * 8];
        }
    }
    __syncthreads();

    constexpr int NW = NT / 2;
    constexpr int NF = NW / 8;
    const int wm = wid & 3, wn = wid >> 2;
    const int mrow = wm * 32;
    const int ncol = wn * NW;

    float acc[2][NF][4];
    #pragma unroll
    for (int i = 0; i < 2; i++)
        #pragma unroll
        for (int nf = 0; nf < NF; nf++)
            #pragma unroll
            for (int j = 0; j < 4; j++) acc[i][nf][j] = 0.f;

    const uint32_t ahi_b = smem_u32(Ahi), alo_b = smem_u32(Alo);
    const uint32_t bhi_b = smem_u32(Bhi), blo_b = smem_u32(Blo);
    const int la  = lane & 15;
    const int lka = (lane >> 4) << 3;
    const int lbn = ((lane >> 4) << 3) + (lane & 7);
    const int lbk = ((lane >> 3) & 1) << 3;

    for (int kb = 0; kb < KT; kb += 16) {
        uint32_t ah[2][4], al[2][4];
        #pragma unroll
        for (int i = 0; i < 2; i++) {
            uint32_t aoff = (uint32_t)(((mrow + i * 16 + la) * KP + kb + lka) * 2);
            ldsm_x4(ah[i], ahi_b + aoff);
            if (THREE) ldsm_x4(al[i], alo_b + aoff);
        }
        #pragma unroll
        for (int nf = 0; nf < NF; nf += 2) {
            uint32_t boff = (uint32_t)(((ncol + nf * 8 + lbn) * KP + kb + lbk) * 2);
            uint32_t bh[4], bl[4];
            ldsm_x4(bh, bhi_b + boff);
            if (BLO) ldsm_x4(bl, blo_b + boff);
            #pragma unroll
            for (int i = 0; i < 2; i++) {
                mma16816<DT>(acc[i][nf],     ah[i], bh);
                mma16816<DT>(acc[i][nf + 1], ah[i], bh + 2);
                if (BLO) {
                    mma16816<DT>(acc[i][nf],     ah[i], bl);
                    mma16816<DT>(acc[i][nf + 1], ah[i], bl + 2);
                }
                if (THREE) {
                    mma16816<DT>(acc[i][nf],     al[i], bh);
                    mma16816<DT>(acc[i][nf + 1], al[i], bh + 2);
                }
            }
        }
    }

    // ---- epilogue ----
    const int qr = lane >> 2;
    const int qc = (lane & 3) * 2;
    #pragma unroll
    for (int i = 0; i < 2; i++) {
        #pragma unroll
        for (int half = 0; half < 2; half++) {
            int gr = row0 + mrow + i * 16 + half * 8 + qr;
            if (gr < M) {
                #pragma unroll
                for (int nf = 0; nf < NF; nf++) {
                    int c = col_base + ncol + nf * 8 + qc;
                    float v0 = acc[i][nf][half * 2 + 0];
                    float v1 = acc[i][nf][half * 2 + 1];
                    if (POST == 1) {
                        v0 += bvec[c]; v1 += bvec[c + 1];
                        *(float2*)&C[(size_t)gr * nstride + c] = make_float2(v0, v1);
                    } else {
                        float t0 = fmaxf(v0 + bvec[c], 0.f);
                        float t1 = fmaxf(v1 + bvec[c + 1], 0.f);
                        ((uint32_t*)Chi_g)[((size_t)gr * nstride + c) >> 1] = pack_f16(t0, t1);
                    }
                }
            }
        }
    }
}

// ---------------- fused conv kernel: w = f(z@Wa) @ Wb -> fp16 ----------------
__global__ void __launch_bounds__(256, 2)
k_conv(const float* __restrict__ Z,
       const u16* __restrict__ WaHi_g, const u16* __restrict__ WaLo_g,
       const u16* __restrict__ WbHi_g, const u16* __restrict__ WbLo_g,
       const float* __restrict__ rs, const float* __restrict__ ba,
       u16* __restrict__ Wout16, int M) {
    constexpr int KP = 72;
    extern __shared__ __align__(16) u16 sm[];
    u16* Ahi = sm;
    u16* Alo = Ahi + 128 * KP;
    u16* BaH = Alo + 128 * KP;
    u16* BaL = BaH + 64 * KP;
    u16* BbH = BaL + 64 * KP;
    u16* BbL = BbH + 64 * KP;

    const int tid = threadIdx.x;
    const int wid = tid >> 5, lane = tid & 31;
    const int row0 = blockIdx.x * 128;

    for (int idx = tid; idx < 128 * 32; idx += 256) {
        int r = idx >> 5, kp = idx & 31, k = kp * 2;
        int gr = row0 + r;
        float a0 = 0.f, a1 = 0.f;
        if (gr < M) {
            float2 t = ((const float2*)Z)[(size_t)gr * 32 + kp];
            a0 = t.x; a1 = t.y;
        }
        uint32_t hi, lo; split2(a0, a1, hi, lo);
        *(uint32_t*)&Ahi[r * KP + k] = hi;
        *(uint32_t*)&Alo[r * KP + k] = lo;
    }
    for (int idx = tid; idx < 64 * 8; idx += 256) {
        int n = idx >> 3, k8 = idx & 7;
        *(uint4*)&BaH[n * KP + k8 * 8] = *(const uint4*)&WaHi_g[(size_t)n * 64 + k8 * 8];
        *(uint4*)&BaL[n * KP + k8 * 8] = *(const uint4*)&WaLo_g[(size_t)n * 64 + k8 * 8];
        *(uint4*)&BbH[n * KP + k8 * 8] = *(const uint4*)&WbHi_g[(size_t)n * 64 + k8 * 8];
        *(uint4*)&BbL[n * KP + k8 * 8] = *(const uint4*)&WbLo_g[(size_t)n * 64 + k8 * 8];
    }
    __syncthreads();

    const int wm = wid & 3, wn = wid >> 2;
    const int mrow = wm * 32;
    const int ncol = wn * 32;
    const uint32_t ahi_b = smem_u32(Ahi), alo_b = smem_u32(Alo);
    const int la  = lane & 15;
    const int lka = (lane >> 4) << 3;
    const int lbn = ((lane >> 4) << 3) + (lane & 7);
    const int lbk = ((lane >> 3) & 1) << 3;
    const int qr = lane >> 2;
    const int qc = (lane & 3) * 2;

    float acc[2][4][4];
    // ---- mainloop 1: z @ Wa ----
    {
        const uint32_t bh_b = smem_u32(BaH), bl_b = smem_u32(BaL);
        #pragma unroll
        for (int i = 0; i < 2; i++)
            #pragma unroll
            for (int nf = 0; nf < 4; nf++)
                #pragma unroll
                for (int j = 0; j < 4; j++) acc[i][nf][j] = 0.f;
        #pragma unroll
        for (int kb = 0; kb < 64; kb += 16) {
            uint32_t ah[2][4], al[2][4];
            #pragma unroll
            for (int i = 0; i < 2; i++) {
                uint32_t aoff = (uint32_t)(((mrow + i * 16 + la) * KP + kb + lka) * 2);
                ldsm_x4(ah[i], ahi_b + aoff);
                ldsm_x4(al[i], alo_b + aoff);
            }
            #pragma unroll
            for (int nf = 0; nf < 4; nf += 2) {
                uint32_t boff = (uint32_t)(((ncol + nf * 8 + lbn) * KP + kb + lbk) * 2);
                uint32_t bh[4], bl[4];
                ldsm_x4(bh, bh_b + boff);
                ldsm_x4(bl, bl_b + boff);
                #pragma unroll
                for (int i = 0; i < 2; i++) {
                    mma16816<0>(acc[i][nf],     ah[i], bh);
                    mma16816<0>(acc[i][nf],     ah[i], bl);
                    mma16816<0>(acc[i][nf],     al[i], bh);
                    mma16816<0>(acc[i][nf + 1], ah[i], bh + 2);
                    mma16816<0>(acc[i][nf + 1], ah[i], bl + 2);
                    mma16816<0>(acc[i][nf + 1], al[i], bh + 2);
                }
            }
        }
    }
    __syncthreads();

    // ---- epilogue 1: y -> split bf16, back into A smem ----
    #pragma unroll
    for (int i = 0; i < 2; i++) {
        #pragma unroll
        for (int half = 0; half < 2; half++) {
            int rloc = mrow + i * 16 + half * 8 + qr;
            int gr = row0 + rloc;
            float s = (gr < M) ? rs[gr] : 0.f;
            #pragma unroll
            for (int nf = 0; nf < 4; nf++) {
                int c = ncol + nf * 8 + qc;
                float y0 = (acc[i][nf][half * 2 + 0] * s + ba[c]) * s;
                float y1 = (acc[i][nf][half * 2 + 1] * s + ba[c + 1]) * s;
                uint32_t hi, lo; split2(y0, y1, hi, lo);
                *(uint32_t*)&Ahi[rloc * KP + c] = hi;
                *(uint32_t*)&Alo[rloc * KP + c] = lo;
            }
        }
    }
    __syncthreads();

    // ---- mainloop 2: y @ Wb ----
    {
        const uint32_t bh_b = smem_u32(BbH), bl_b = smem_u32(BbL);
        #pragma unroll
        for (int i = 0; i < 2; i++)
            #pragma unroll
            for (int nf = 0; nf < 4; nf++)
                #pragma unroll
                for (int j = 0; j < 4; j++) acc[i][nf][j] = 0.f;
        #pragma unroll
        for (int kb = 0; kb < 64; kb += 16) {
            uint32_t ah[2][4], al[2][4];
            #pragma unroll
            for (int i = 0; i < 2; i++) {
                uint32_t aoff = (uint32_t)(((mrow + i * 16 + la) * KP + kb + lka) * 2);
                ldsm_x4(ah[i], ahi_b + aoff);
                ldsm_x4(al[i], alo_b + aoff);
            }
            #pragma unroll
            for (int nf = 0; nf < 4; nf += 2) {
                uint32_t boff = (uint32_t)(((ncol + nf * 8 + lbn) * KP + kb + lbk) * 2);
                uint32_t bh[4], bl[4];
                ldsm_x4(bh, bh_b + boff);
                ldsm_x4(bl, bl_b + boff);
                #pragma unroll
                for (int i = 0; i < 2; i++) {
                    mma16816<0>(acc[i][nf],     ah[i], bh);
                    mma16816<0>(acc[i][nf],     ah[i], bl);
                    mma16816<0>(acc[i][nf],     al[i], bh);
                    mma16816<0>(acc[i][nf + 1], ah[i], bh + 2);
                    mma16816<0>(acc[i][nf + 1], ah[i], bl + 2);
                    mma16816<0>(acc[i][nf + 1], al[i], bh + 2);
                }
            }
        }
    }
    // ---- epilogue 2: w -> gmem fp16 ----
    #pragma unroll
    for (int i = 0; i < 2; i++) {
        #pragma unroll
        for (int half = 0; half < 2; half++) {
            int gr = row0 + mrow + i * 16 + half * 8 + qr;
            if (gr < M) {
                #pragma unroll
                for (int nf = 0; nf < 4; nf++) {
                    int c = ncol + nf * 8 + qc;
                    ((uint32_t*)Wout16)[((size_t)gr * 64 + c) >> 1] =
                        pack_f16(acc[i][nf][half * 2 + 0], acc[i][nf][half * 2 + 1]);
                }
            }
        }
    }
}

// --------- FFN2 (1-term fp16) fused with residual + LN2 ----------------------
__global__ void __launch_bounds__(256, 2)
k_ffn2_ln(const u16* __restrict__ T, const u16* __restrict__ Whi_g,
          const float* __restrict__ bvec,
          const float* __restrict__ g, const float* __restrict__ b,
          float* __restrict__ h, u16* __restrict__ hf16, int M) {
    constexpr int KC = 128, KP = KC + 8;
    extern __shared__ __align__(16) u16 sm[];
    u16* As  = sm;
    u16* Bhi = As + 128 * KP;

    const int tid = threadIdx.x;
    const int wid = tid >> 5, lane = tid & 31;
    const int row0 = blockIdx.x * 128;
    const int wm = wid & 3, wn = wid >> 2;
    const int mrow = wm * 32;
    const int ncol = wn * 32;
    const int la  = lane & 15;
    const int lka = (lane >> 4) << 3;
    const int lbn = ((lane >> 4) << 3) + (lane & 7);
    const int lbk = ((lane >> 3) & 1) << 3;

    float acc[2][4][4];
    #pragma unroll
    for (int i = 0; i < 2; i++)
        #pragma unroll
        for (int nf = 0; nf < 4; nf++)
            #pragma unroll
            for (int j = 0; j < 4; j++) acc[i][nf][j] = 0.f;

    const uint32_t as_b = smem_u32(As);
    const uint32_t bh_b = smem_u32(Bhi);
    const uint4 z4 = make_uint4(0, 0, 0, 0);

    for (int kc = 0; kc < 2; kc++) {
        __syncthreads();
        for (int idx = tid; idx < 128 * 16; idx += 256) {
            int r = idx >> 4, k8 = idx & 15;
            int gr = row0 + r;
            uint4 v = z4;
            if (gr < M) v = *(const uint4*)&T[(size_t)gr * 256 + kc * 128 + k8 * 8];
            *(uint4*)&As[r * KP + k8 * 8] = v;
        }
        for (int idx = tid; idx < 64 * 16; idx += 256) {
            int n = idx >> 4, k8 = idx & 15;
            *(uint4*)&Bhi[n * KP + k8 * 8] = *(const uint4*)&Whi_g[(size_t)n * 256 + kc * 128 + k8 * 8];
        }
        __syncthreads();
        for (int kb = 0; kb < KC; kb += 16) {
            uint32_t ah[2][4];
            #pragma unroll
            for (int i = 0; i < 2; i++) {
                uint32_t aoff = (uint32_t)(((mrow + i * 16 + la) * KP + kb + lka) * 2);
                ldsm_x4(ah[i], as_b + aoff);
            }
            #pragma unroll
            for (int nf = 0; nf < 4; nf += 2) {
                uint32_t boff = (uint32_t)(((ncol + nf * 8 + lbn) * KP + kb + lbk) * 2);
                uint32_t bh[4];
                ldsm_x4(bh, bh_b + boff);
                #pragma unroll
                for (int i = 0; i < 2; i++) {
                    mma16816<1>(acc[i][nf],     ah[i], bh);
                    mma16816<1>(acc[i][nf + 1], ah[i], bh + 2);
                }
            }
        }
    }

    // ---- stage x = h + U + c2 into smem (fp32, stride 72) ----
    __syncthreads();
    float* xs = (float*)sm;
    const int qr = lane >> 2;
    const int qc = (lane & 3) * 2;
    #pragma unroll
    for (int i = 0; i < 2; i++) {
        #pragma unroll
        for (int half = 0; half < 2; half++) {
            int rloc = mrow + i * 16 + half * 8 + qr;
            int gr = row0 + rloc;
            #pragma unroll
            for (int nf = 0; nf < 4; nf++) {
                int c = ncol + nf * 8 + qc;
                float x0 = 0.f, x1 = 0.f;
                if (gr < M) {
                    float2 hres = *(const float2*)&h[(size_t)gr * 64 + c];
                    x0 = acc[i][nf][half * 2 + 0] + bvec[c] + hres.x;
                    x1 = acc[i][nf][half * 2 + 1] + bvec[c + 1] + hres.y;
                }
                xs[rloc * 72 + c]     = x0;
                xs[rloc * 72 + c + 1] = x1;
            }
        }
    }
    __syncthreads();

    // ---- LN: warp wid handles rows wid*16 .. wid*16+15 ----
    const int c0 = lane * 2;
    for (int rr = 0; rr < 16; rr++) {
        int rloc = wid * 16 + rr;
        int gr = row0 + rloc;
        if (gr >= M) continue;
        float x0 = xs[rloc * 72 + c0];
        float x1 = xs[rloc * 72 + c0 + 1];
        float sum = x0 + x1;
        #pragma unroll
        for (int o = 16; o; o >>= 1) sum += __shfl_xor_sync(0xffffffffu, sum, o);
        float mu = sum * (1.0f / 64.0f);
        float d0 = x0 - mu, d1 = x1 - mu;
        float vs = d0 * d0 + d1 * d1;
        #pragma unroll
        for (int o = 16; o; o >>= 1) vs += __shfl_xor_sync(0xffffffffu, vs, o);
        float inv = rsqrtf(vs * (1.0f / 64.0f) + 1e-5f);
        float o0 = fmaf(d0 * inv, g[c0], b[c0]);
        float o1 = fmaf(d1 * inv, g[c0 + 1], b[c0 + 1]);
        *(float2*)&h[(size_t)gr * 64 + c0] = make_float2(o0, o1);
        ((uint32_t*)hf16)[((size_t)gr * 64 + c0) >> 1] = pack_f16(o0, o1);
    }
}

// ---------------- LayerNorm (standalone, final) ------------------------------
__global__ void k_lnF(const float* __restrict__ base,
                      const float* __restrict__ g, const float* __restrict__ b,
                      float* __restrict__ out, int M) {
    const int warp = threadIdx.x >> 5;
    const int lane = threadIdx.x & 31;
    const int row = blockIdx.x * (blockDim.x >> 5) + warp;
    if (row >= M) return;
    const int i0 = row * 64 + lane;
    const int i1 = i0 + 32;
    float x0 = base[i0], x1 = base[i1];
    float sum = x0 + x1;
    #pragma unroll
    for (int o = 16; o; o >>= 1) sum += __shfl_xor_sync(0xffffffffu, sum, o);
    float mu = sum * (1.0f / 64.0f);
    float d0 = x0 - mu, d1 = x1 - mu;
    float vs = d0 * d0 + d1 * d1;
    #pragma unroll
    for (int o = 16; o; o >>= 1) vs += __shfl_xor_sync(0xffffffffu, vs, o);
    float inv = rsqrtf(vs * (1.0f / 64.0f) + 1e-5f);
    out[i0] = fmaf(d0 * inv, g[lane], b[lane]);
    out[i1] = fmaf(d1 * inv, g[lane + 32], b[lane + 32]);
}

// ---------------- orchestration ----------------------------------------------
extern "C" void kernel_launch(void* const* d_in, const int* in_sizes, int n_in,
                              void* d_out, int out_size) {
    const float* x    = (const float*)d_in[0];
    const int*   esrc = (const int*)d_in[1];
    const int*   edst = (const int*)d_in[2];
    const int wi = (n_in >= 20) ? 4 : 3;
    const float* Wn2h = (const float*)d_in[wi + 0];
    const float* bn2h = (const float*)d_in[wi + 1];
    const float* Wh2n = (const float*)d_in[wi + 2];
    const float* bh2n = (const float*)d_in[wi + 3];
    const float* W1   = (const float*)d_in[wi + 4];
    const float* b1   = (const float*)d_in[wi + 5];
    const float* W2   = (const float*)d_in[wi + 6];
    const float* b2   = (const float*)d_in[wi + 7];
    const float* g1   = (const float*)d_in[wi + 8];
    const float* be1  = (const float*)d_in[wi + 9];
    const float* g2   = (const float*)d_in[wi + 10];
    const float* be2  = (const float*)d_in[wi + 11];
    const float* gF   = (const float*)d_in[wi + 12];
    const float* bF   = (const float*)d_in[wi + 13];
    const float* Wo   = (const float*)d_in[wi + 14];
    const float* bo   = (const float*)d_in[wi + 15];

    float *p_h, *p_b1, *p_ha, *p_invn, *p_invh;
    u16 *p_hf16, *p_wf16, *p_thi;
    u16 *p_wa_hi, *p_wa_lo, *p_wb_hi, *p_wb_lo, *p_w1_hi, *p_w1_lo;
    u16 *p_w2_hi, *p_w2_lo, *p_wo_hi, *p_wo_lo;
    int *p_cntH, *p_cntN, *p_stH, *p_stN, *p_cuH, *p_cuN, *p_csrH, *p_csrN;
    int *p_bsN, *p_boN, *p_bsH, *p_boH;
    cudaGetSymbolAddress((void**)&p_h,    g_h);
    cudaGetSymbolAddress((void**)&p_b1,   g_b1);
    cudaGetSymbolAddress((void**)&p_hf16, g_hf16);
    cudaGetSymbolAddress((void**)&p_ha,   g_ha);
    cudaGetSymbolAddress((void**)&p_wf16, g_wf16);
    cudaGetSymbolAddress((void**)&p_thi,  g_thi);
    cudaGetSymbolAddress((void**)&p_wa_hi, g_wa_hi);
    cudaGetSymbolAddress((void**)&p_wa_lo, g_wa_lo);
    cudaGetSymbolAddress((void**)&p_wb_hi, g_wb_hi);
    cudaGetSymbolAddress((void**)&p_wb_lo, g_wb_lo);
    cudaGetSymbolAddress((void**)&p_w1_hi, g_w1_hi);
    cudaGetSymbolAddress((void**)&p_w1_lo, g_w1_lo);
    cudaGetSymbolAddress((void**)&p_w2_hi, g_w2_hi);
    cudaGetSymbolAddress((void**)&p_w2_lo, g_w2_lo);
    cudaGetSymbolAddress((void**)&p_wo_hi, g_wo_hi);
    cudaGetSymbolAddress((void**)&p_wo_lo, g_wo_lo);
    cudaGetSymbolAddress((void**)&p_invn, g_invn);
    cudaGetSymbolAddress((void**)&p_invh, g_invh);
    cudaGetSymbolAddress((void**)&p_cntH, g_cntH);
    cudaGetSymbolAddress((void**)&p_cntN, g_cntN);
    cudaGetSymbolAddress((void**)&p_stH,  g_startH);
    cudaGetSymbolAddress((void**)&p_stN,  g_startN);
    cudaGetSymbolAddress((void**)&p_cuH,  g_curH);
    cudaGetSymbolAddress((void**)&p_cuN,  g_curN);
    cudaGetSymbolAddress((void**)&p_csrH, g_csrH);
    cudaGetSymbolAddress((void**)&p_csrN, g_csrN);
    cudaGetSymbolAddress((void**)&p_bsN, g_bsumN);
    cudaGetSymbolAddress((void**)&p_boN, g_boffN);
    cudaGetSymbolAddress((void**)&p_bsH, g_bsumH);
    cudaGetSymbolAddress((void**)&p_boH, g_boffH);

    const int smem_convf = (2 * 128 * 72 + 4 * 64 * 72) * 2;   //  73728
    const int smem_ffn1  = (1 * 128 * 72 + 1 * 128 * 72) * 2;  //  36864
    const int smem_ffn2  = (128 * 136 + 64 * 136) * 2;         //  52224
    const int smem_proj  = (2 * 128 * 72 + 2 * 64 * 72) * 2;   //  55296
    cudaFuncSetAttribute((const void*)k_conv, cudaFuncAttributeMaxDynamicSharedMemorySize, smem_convf);
    cudaFuncSetAttribute((const void*)k_mma<64, 128, 2, 4, 1, 1>, cudaFuncAttributeMaxDynamicSharedMemorySize, smem_ffn1);
    cudaFuncSetAttribute((const void*)k_ffn2_ln, cudaFuncAttributeMaxDynamicSharedMemorySize, smem_ffn2);
    cudaFuncSetAttribute((const void*)k_mma<64, 64, 0, 1, 0, 2>, cudaFuncAttributeMaxDynamicSharedMemorySize, smem_proj);

    cudaMemcpyAsync(p_h, x, (size_t)NN * DD * sizeof(float), cudaMemcpyDeviceToDevice);
    k_f2h<<<(NN * 32 + 255) / 256, 256>>>(x, p_hf16, NN * 32);

    // ---- weight pre-split ----
    k_prep<0><<<(LL * DD * DD + 255) / 256, 256>>>(Wn2h, DD, DD, LL * DD * DD, p_wa_hi, p_wa_lo);
    k_prep<0><<<(LL * DD * DD + 255) / 256, 256>>>(Wh2n, DD, DD, LL * DD * DD, p_wb_hi, p_wb_lo);
    k_prep<1><<<(LL * DD * FF + 255) / 256, 256>>>(W1, DD, FF, LL * DD * FF, p_w1_hi, p_w1_lo);
    k_prep<1><<<(LL * FF * DD + 255) / 256, 256>>>(W2, FF, DD, LL * FF * DD, p_w2_hi, p_w2_lo);
    k_prep<0><<<(DD * DD + 255) / 256, 256>>>(Wo, DD, DD, DD * DD, p_wo_hi, p_wo_lo);

    // ---- build CSR + degree norms (multi-block scans) ----
    const int nbN = (NN + 1023) / 1024;   // 98
    const int nbH = (HH + 1023) / 1024;   // 20
    k_zero4<<<256, 256>>>(p_cntN, NN, p_cntH, HH, p_cuN, NN, p_cuH, HH);
    k_hist<<<(EE + 255) / 256, 256>>>(esrc, edst, p_cntN, p_cntH);
    k_bsum<<<nbH, 1024>>>(p_cntH, p_bsH, HH);
    k_bsum<<<nbN, 1024>>>(p_cntN, p_bsN, NN);
    k_scan<<<1, 1024>>>(p_bsH, p_boH, nbH);
    k_scan<<<1, 1024>>>(p_bsN, p_boN, nbN);
    k_scan2<<<nbH, 1024>>>(p_cntH, p_boH, p_stH, HH);
    k_scan2<<<nbN, 1024>>>(p_cntN, p_boN, p_stN, NN);
    k_fill<<<(EE + 255) / 256, 256>>>(esrc, edst, p_stH, p_stN, p_cuH, p_cuN, p_csrH, p_csrN);
    k_inv<<<(NN + 255) / 256, 256>>>(p_cntN, p_cntH, p_invn, p_invh);

    const int gN  = (NN + 127) / 128;
    const int gH  = (HH + 127) / 128;
    const int gLN = (NN + 7) / 8;
    const int gAgH = (HH + 7) / 8;
    const int gAgN = (NN + 7) / 8;

    for (int l = 0; l < LL; l++) {
        const float* ba = bn2h + (size_t)l * DD;
        const float* bb = bh2n + (size_t)l * DD;
        const float* c1 = b1 + (size_t)l * FF;
        const float* c2 = b2 + (size_t)l * DD;
        const float* gg1 = g1 + (size_t)l * DD;
        const float* ee1 = be1 + (size_t)l * DD;
        const float* gg2 = g2 + (size_t)l * DD;
        const float* ee2 = be2 + (size_t)l * DD;

        // z = agg_H(hf16 * invn[src])
        k_agg16<<<gAgH, 256>>>(p_hf16, p_csrH, p_stH, p_cntH, p_invn, p_ha, HH);
        // fused: y = (z@Wa*invh+ba)*invh ; w = y@Wb -> fp16
        k_conv<<<gH, 256, smem_convf>>>(
            p_ha, p_wa_hi + (size_t)l * DD * DD, p_wa_lo + (size_t)l * DD * DD,
            p_wb_hi + (size_t)l * DD * DD, p_wb_lo + (size_t)l * DD * DD,
            p_invh, ba, p_wf16, HH);
        // fused: u = agg_N(wf16); h = LN(h + u*invn + bb) -> h fp32 + fp16
        k_agg_ln16<<<gAgN, 256>>>(p_wf16, p_csrN, p_stN, p_cntN, p_invn, bb,
                                  gg1, ee1, p_h, p_hf16, NN);
        // FFN1: T = relu(hf16@W1 + c1) -> fp16 (1-term fp16)
        k_mma<64, 128, 2, 4, 1, 1><<<dim3(gN, 2), 256, smem_ffn1>>>(
            nullptr, p_hf16, p_w1_hi + (size_t)l * DD * FF, p_w1_lo + (size_t)l * DD * FF,
            c1, nullptr, p_thi, NN, FF);
        // FFN2 (1-term) fused with residual + LN2 -> h fp32 + fp16
        k_ffn2_ln<<<gN, 256, smem_ffn2>>>(
            p_thi, p_w2_hi + (size_t)l * FF * DD,
            c2, gg2, ee2, p_h, p_hf16, NN);
    }

    // final LN + projection (3-term bf16, exact path)
    k_lnF<<<gLN, 256>>>(p_h, gF, bF, p_b1, NN);
    k_mma<64, 64, 0, 1, 0, 2><<<gN, 256, smem_proj>>>(
        p_b1, nullptr, p_wo_hi, p_wo_lo, bo, (float*)d_out, nullptr, NN, DD);
}

// round 11
// speedup vs baseline: 1.8332x; 1.1213x over previous
#include <cuda_runtime.h>
#include <cuda_bf16.h>
#include <cuda_fp16.h>
#include <cstdint>
#include <math.h>

#define NN 100000
#define HH 20000
#define EE 1600000
#define DD 64
#define FF 256
#define LL 3

typedef unsigned short u16;

// ---------------- helpers ----------------------------------------------------
__device__ __forceinline__ uint32_t smem_u32(const void* p) {
    uint32_t a;
    asm("{ .reg .u64 t; cvta.to.shared.u64 t, %1; cvt.u32.u64 %0, t; }" : "=r"(a) : "l"(p));
    return a;
}
__device__ __forceinline__ void ldsm_x4(uint32_t* r, uint32_t addr) {
    asm volatile("ldmatrix.sync.aligned.m8n8.x4.shared.b16 {%0,%1,%2,%3}, [%4];"
                 : "=r"(r[0]), "=r"(r[1]), "=r"(r[2]), "=r"(r[3]) : "r"(addr));
}
// DT 0 = bf16, 1 = fp16
template<int DT>
__device__ __forceinline__ void mma16816(float* d, const uint32_t* a, const uint32_t* b) {
    if (DT == 0)
        asm volatile("mma.sync.aligned.m16n8k16.row.col.f32.bf16.bf16.f32 "
                     "{%0,%1,%2,%3}, {%4,%5,%6,%7}, {%8,%9}, {%0,%1,%2,%3};"
                     : "+f"(d[0]), "+f"(d[1]), "+f"(d[2]), "+f"(d[3])
                     : "r"(a[0]), "r"(a[1]), "r"(a[2]), "r"(a[3]), "r"(b[0]), "r"(b[1]));
    else
        asm volatile("mma.sync.aligned.m16n8k16.row.col.f32.f16.f16.f32 "
                     "{%0,%1,%2,%3}, {%4,%5,%6,%7}, {%8,%9}, {%0,%1,%2,%3};"
                     : "+f"(d[0]), "+f"(d[1]), "+f"(d[2]), "+f"(d[3])
                     : "r"(a[0]), "r"(a[1]), "r"(a[2]), "r"(a[3]), "r"(b[0]), "r"(b[1]));
}
__device__ __forceinline__ void split2(float a, float b, uint32_t& hi, uint32_t& lo) {
    __nv_bfloat16 ha = __float2bfloat16(a), hb = __float2bfloat16(b);
    float ra = a - __bfloat162float(ha);
    float rb = b - __bfloat162float(hb);
    __nv_bfloat16 la = __float2bfloat16(ra), lb = __float2bfloat16(rb);
    hi = (uint32_t)__bfloat16_as_ushort(ha) | ((uint32_t)__bfloat16_as_ushort(hb) << 16);
    lo = (uint32_t)__bfloat16_as_ushort(la) | ((uint32_t)__bfloat16_as_ushort(lb) << 16);
}
__device__ __forceinline__ uint32_t pack_f16(float lo, float hi) {
    __half2 h = __floats2half2_rn(lo, hi);
    return *(uint32_t*)&h;
}
__device__ __forceinline__ void unpack_f16(uint32_t v, float& lo, float& hi) {
    __half2 h = *(__half2*)&v;
    float2 f = __half22float2(h);
    lo = f.x; hi = f.y;
}
// unpack a uint4 (8 halves) into 8 floats
__device__ __forceinline__ void unpack8(const uint4& p, float* f) {
    unpack_f16(p.x, f[0], f[1]);
    unpack_f16(p.y, f[2], f[3]);
    unpack_f16(p.z, f[4], f[5]);
    unpack_f16(p.w, f[6], f[7]);
}

// ---------------- scratch ----------------------------------------------------
__device__ __align__(16) float g_h  [NN * DD];
__device__ __align__(16) float g_b1 [NN * DD];
__device__ __align__(16) u16 g_hf16[NN * DD];
__device__ __align__(16) float g_ha [HH * DD];
__device__ __align__(16) u16 g_wf16[HH * DD];
__device__ __align__(16) u16 g_wa_hi[LL * DD * DD];   // bf16
__device__ __align__(16) u16 g_wa_lo[LL * DD * DD];
__device__ __align__(16) u16 g_wb_hi[LL * DD * DD];   // bf16
__device__ __align__(16) u16 g_wb_lo[LL * DD * DD];
__device__ __align__(16) u16 g_w1_hi[LL * DD * FF];   // fp16
__device__ __align__(16) u16 g_w2_hi[LL * FF * DD];   // fp16
__device__ __align__(16) u16 g_wo_hi[DD * DD];        // bf16
__device__ __align__(16) u16 g_wo_lo[DD * DD];
__device__ float g_invn[NN];
__device__ float g_invh[HH];
__device__ int g_cntH [HH];
__device__ int g_cntN [NN];
__device__ int g_startH[HH];
__device__ int g_startN[NN];
__device__ int g_curH [HH];
__device__ int g_curN [NN];
__device__ int g_csrH [EE];
__device__ int g_csrN [EE];
__device__ int g_bsumN[128];
__device__ int g_boffN[128];
__device__ int g_bsumH[32];
__device__ int g_boffH[32];

// ---------------- weight prep ------------------------------------------------
// DT 0: bf16 hi+lo; DT 1: fp16 hi only
template<int DT>
__global__ void k_prep(const float* __restrict__ src, int K, int N, int total,
                       u16* __restrict__ hi, u16* __restrict__ lo) {
    int idx = blockIdx.x * blockDim.x + threadIdx.x;
    if (idx >= total) return;
    int KN = K * N;
    int l = idx / KN;
    int r = idx - l * KN;
    int k = r / N, n = r - k * N;
    float v = src[idx];
    size_t o = (size_t)l * KN + (size_t)n * K + k;
    if (DT == 0) {
        __nv_bfloat16 h = __float2bfloat16(v);
        float res = v - __bfloat162float(h);
        hi[o] = __bfloat16_as_ushort(h);
        lo[o] = __bfloat16_as_ushort(__float2bfloat16(res));
    } else {
        hi[o] = __half_as_ushort(__float2half_rn(v));
    }
}

__global__ void k_f2h(const float* __restrict__ src, u16* __restrict__ dst, int n2) {
    int i = blockIdx.x * blockDim.x + threadIdx.x;
    if (i < n2) {
        float2 v = ((const float2*)src)[i];
        ((uint32_t*)dst)[i] = pack_f16(v.x, v.y);
    }
}

// ---------------- CSR build --------------------------------------------------
__global__ void k_zero4(int* __restrict__ a, int na, int* __restrict__ b, int nb,
                        int* __restrict__ c, int nc, int* __restrict__ d, int nd) {
    int i = blockIdx.x * blockDim.x + threadIdx.x;
    int stride = gridDim.x * blockDim.x;
    for (int j = i; j < na; j += stride) a[j] = 0;
    for (int j = i; j < nb; j += stride) b[j] = 0;
    for (int j = i; j < nc; j += stride) c[j] = 0;
    for (int j = i; j < nd; j += stride) d[j] = 0;
}

__global__ void k_hist(const int* __restrict__ src, const int* __restrict__ dst,
                       int* __restrict__ cntN, int* __restrict__ cntH) {
    int e = blockIdx.x * blockDim.x + threadIdx.x;
    if (e < EE) {
        atomicAdd(&cntN[src[e]], 1);
        atomicAdd(&cntH[dst[e]], 1);
    }
}

__global__ void k_bsum(const int* __restrict__ cnt, int* __restrict__ bsum, int n) {
    __shared__ int sw[32];
    const int tid = threadIdx.x, lane = tid & 31, warp = tid >> 5;
    int i = blockIdx.x * 1024 + tid;
    int v = (i < n) ? cnt[i] : 0;
    #pragma unroll
    for (int o = 16; o; o >>= 1) v += __shfl_xor_sync(0xffffffffu, v, o);
    if (lane == 0) sw[warp] = v;
    __syncthreads();
    if (warp == 0) {
        int t = sw[lane];
        #pragma unroll
        for (int o = 16; o; o >>= 1) t += __shfl_xor_sync(0xffffffffu, t, o);
        if (lane == 0) bsum[blockIdx.x] = t;
    }
}

__global__ void k_scan(const int* __restrict__ cnt, int* __restrict__ start, int n) {
    __shared__ int shw[33];
    __shared__ int sh_carry;
    const int tid = threadIdx.x;
    const int lane = tid & 31, warp = tid >> 5;
    if (tid == 0) sh_carry = 0;
    __syncthreads();
    for (int base = 0; base < n; base += 1024) {
        int i = base + tid;
        int v = (i < n) ? cnt[i] : 0;
        int inc = v;
        #pragma unroll
        for (int o = 1; o < 32; o <<= 1) {
            int t = __shfl_up_sync(0xffffffffu, inc, o);
            if (lane >= o) inc += t;
        }
        if (lane == 31) shw[warp] = inc;
        __syncthreads();
        if (warp == 0) {
            int t = shw[lane];
            int winc = t;
            #pragma unroll
            for (int o = 1; o < 32; o <<= 1) {
                int u = __shfl_up_sync(0xffffffffu, winc, o);
                if (lane >= o) winc += u;
            }
            shw[lane] = winc - t;
            if (lane == 31) shw[32] = winc;
        }
        __syncthreads();
        int carry = sh_carry;
        if (i < n) start[i] = carry + shw[warp] + inc - v;
        __syncthreads();
        if (tid == 0) sh_carry = carry + shw[32];
        __syncthreads();
    }
}

__global__ void k_scan2(const int* __restrict__ cnt, const int* __restrict__ boff,
                        int* __restrict__ start, int n) {
    __shared__ int shw[32];
    const int tid = threadIdx.x, lane = tid & 31, warp = tid >> 5;
    int i = blockIdx.x * 1024 + tid;
    int v = (i < n) ? cnt[i] : 0;
    int inc = v;
    #pragma unroll
    for (int o = 1; o < 32; o <<= 1) {
        int t = __shfl_up_sync(0xffffffffu, inc, o);
        if (lane >= o) inc += t;
    }
    if (lane == 31) shw[warp] = inc;
    __syncthreads();
    if (warp == 0) {
        int t = shw[lane];
        int winc = t;
        #pragma unroll
        for (int o = 1; o < 32; o <<= 1) {
            int u = __shfl_up_sync(0xffffffffu, winc, o);
            if (lane >= o) winc += u;
        }
        shw[lane] = winc - t;
    }
    __syncthreads();
    if (i < n) start[i] = boff[blockIdx.x] + shw[warp] + inc - v;
}

__global__ void k_fill(const int* __restrict__ src, const int* __restrict__ dst,
                       const int* __restrict__ startH, const int* __restrict__ startN,
                       int* __restrict__ curH, int* __restrict__ curN,
                       int* __restrict__ csrH, int* __restrict__ csrN) {
    int e = blockIdx.x * blockDim.x + threadIdx.x;
    if (e < EE) {
        int s = src[e], d = dst[e];
        int p = atomicAdd(&curH[d], 1);
        csrH[startH[d] + p] = s;
        int q = atomicAdd(&curN[s], 1);
        csrN[startN[s] + q] = d;
    }
}

__global__ void k_inv(const int* __restrict__ cntN, const int* __restrict__ cntH,
                      float* __restrict__ invn, float* __restrict__ invh) {
    int i = blockIdx.x * blockDim.x + threadIdx.x;
    if (i < NN) invn[i] = rsqrtf(fmaxf((float)cntN[i], 1.0f));
    if (i < HH) invh[i] = rsqrtf(fmaxf((float)cntH[i], 1.0f));
}

// ------- fp16 gather (scaled), uint4 lanes: 8 lanes/row, 4 edges || x4 unroll -
__global__ void k_agg16(const u16* __restrict__ Y, const int* __restrict__ csr,
                        const int* __restrict__ start, const int* __restrict__ cnt,
                        const float* __restrict__ scale, float* __restrict__ out, int M) {
    const int warp = threadIdx.x >> 5;
    const int lane = threadIdx.x & 31;
    const int row = blockIdx.x * (blockDim.x >> 5) + warp;
    if (row >= M) return;
    const int quarter = lane >> 3;
    const int q = lane & 7;
    const int s0 = start[row];
    const int c  = cnt[row];
    const uint4* __restrict__ Y4 = (const uint4*)Y;   // 8 uint4 per row

    float acc[8];
    #pragma unroll
    for (int k = 0; k < 8; k++) acc[k] = 0.f;
    float t[8];

    int j = quarter;
    for (; j + 12 < c; j += 16) {
        int i0 = __ldg(&csr[s0 + j]);
        int i1 = __ldg(&csr[s0 + j + 4]);
        int i2 = __ldg(&csr[s0 + j + 8]);
        int i3 = __ldg(&csr[s0 + j + 12]);
        uint4 p0 = Y4[(size_t)i0 * 8 + q];
        uint4 p1 = Y4[(size_t)i1 * 8 + q];
        uint4 p2 = Y4[(size_t)i2 * 8 + q];
        uint4 p3 = Y4[(size_t)i3 * 8 + q];
        float f0 = __ldg(&scale[i0]), f1 = __ldg(&scale[i1]);
        float f2 = __ldg(&scale[i2]), f3 = __ldg(&scale[i3]);
        unpack8(p0, t);
        #pragma unroll
        for (int k = 0; k < 8; k++) acc[k] = fmaf(t[k], f0, acc[k]);
        unpack8(p1, t);
        #pragma unroll
        for (int k = 0; k < 8; k++) acc[k] = fmaf(t[k], f1, acc[k]);
        unpack8(p2, t);
        #pragma unroll
        for (int k = 0; k < 8; k++) acc[k] = fmaf(t[k], f2, acc[k]);
        unpack8(p3, t);
        #pragma unroll
        for (int k = 0; k < 8; k++) acc[k] = fmaf(t[k], f3, acc[k]);
    }
    for (; j < c; j += 4) {
        int i0 = __ldg(&csr[s0 + j]);
        uint4 p0 = Y4[(size_t)i0 * 8 + q];
        float f0 = __ldg(&scale[i0]);
        unpack8(p0, t);
        #pragma unroll
        for (int k = 0; k < 8; k++) acc[k] = fmaf(t[k], f0, acc[k]);
    }
    // combine the 4 quarters
    #pragma unroll
    for (int k = 0; k < 8; k++) {
        acc[k] += __shfl_xor_sync(0xffffffffu, acc[k], 8);
        acc[k] += __shfl_xor_sync(0xffffffffu, acc[k], 16);
    }
    if (quarter == 0) {
        float4* o4 = (float4*)&out[(size_t)row * 64 + q * 8];
        o4[0] = make_float4(acc[0], acc[1], acc[2], acc[3]);
        o4[1] = make_float4(acc[4], acc[5], acc[6], acc[7]);
    }
}

// --- fp16 gather (uint4) + residual + bias + LN, writes h fp32 + fp16 --------
__global__ void k_agg_ln16(const u16* __restrict__ Y, const int* __restrict__ csr,
                           const int* __restrict__ start, const int* __restrict__ cnt,
                           const float* __restrict__ invn, const float* __restrict__ bb,
                           const float* __restrict__ g, const float* __restrict__ b,
                           float* __restrict__ h, u16* __restrict__ hf16, int M) {
    const int warp = threadIdx.x >> 5;
    const int lane = threadIdx.x & 31;
    const int row = blockIdx.x * (blockDim.x >> 5) + warp;
    if (row >= M) return;
    const int quarter = lane >> 3;
    const int q = lane & 7;
    const int s0 = start[row];
    const int c  = cnt[row];
    const uint4* __restrict__ Y4 = (const uint4*)Y;

    float acc[8];
    #pragma unroll
    for (int k = 0; k < 8; k++) acc[k] = 0.f;
    float t[8];

    int j = quarter;
    for (; j + 12 < c; j += 16) {
        int i0 = __ldg(&csr[s0 + j]);
        int i1 = __ldg(&csr[s0 + j + 4]);
        int i2 = __ldg(&csr[s0 + j + 8]);
        int i3 = __ldg(&csr[s0 + j + 12]);
        uint4 p0 = Y4[(size_t)i0 * 8 + q];
        uint4 p1 = Y4[(size_t)i1 * 8 + q];
        uint4 p2 = Y4[(size_t)i2 * 8 + q];
        uint4 p3 = Y4[(size_t)i3 * 8 + q];
        unpack8(p0, t);
        #pragma unroll
        for (int k = 0; k < 8; k++) acc[k] += t[k];
        unpack8(p1, t);
        #pragma unroll
        for (int k = 0; k < 8; k++) acc[k] += t[k];
        unpack8(p2, t);
        #pragma unroll
        for (int k = 0; k < 8; k++) acc[k] += t[k];
        unpack8(p3, t);
        #pragma unroll
        for (int k = 0; k < 8; k++) acc[k] += t[k];
    }
    for (; j < c; j += 4) {
        int i0 = __ldg(&csr[s0 + j]);
        uint4 p0 = Y4[(size_t)i0 * 8 + q];
        unpack8(p0, t);
        #pragma unroll
        for (int k = 0; k < 8; k++) acc[k] += t[k];
    }
    #pragma unroll
    for (int k = 0; k < 8; k++) {
        acc[k] += __shfl_xor_sync(0xffffffffu, acc[k], 8);
        acc[k] += __shfl_xor_sync(0xffffffffu, acc[k], 16);
    }

    // residual + bias (all octs compute identically; loads coalesce/dedup)
    const float s = invn[row];
    const float4* hrow = (const float4*)&h[(size_t)row * 64 + q * 8];
    float4 h0 = hrow[0], h1 = hrow[1];
    float4 bb0 = *(const float4*)&bb[q * 8];
    float4 bb1 = *(const float4*)&bb[q * 8 + 4];
    float x[8];
    x[0] = fmaf(acc[0], s, h0.x) + bb0.x;
    x[1] = fmaf(acc[1], s, h0.y) + bb0.y;
    x[2] = fmaf(acc[2], s, h0.z) + bb0.z;
    x[3] = fmaf(acc[3], s, h0.w) + bb0.w;
    x[4] = fmaf(acc[4], s, h1.x) + bb1.x;
    x[5] = fmaf(acc[5], s, h1.y) + bb1.y;
    x[6] = fmaf(acc[6], s, h1.z) + bb1.z;
    x[7] = fmaf(acc[7], s, h1.w) + bb1.w;

    // LN within oct (offsets 1,2,4 stay inside the 8-lane group)
    float psum = 0.f;
    #pragma unroll
    for (int k = 0; k < 8; k++) psum += x[k];
    psum += __shfl_xor_sync(0xffffffffu, psum, 1);
    psum += __shfl_xor_sync(0xffffffffu, psum, 2);
    psum += __shfl_xor_sync(0xffffffffu, psum, 4);
    float mu = psum * (1.0f / 64.0f);
    float d[8], pvar = 0.f;
    #pragma unroll
    for (int k = 0; k < 8; k++) { d[k] = x[k] - mu; pvar += d[k] * d[k]; }
    pvar += __shfl_xor_sync(0xffffffffu, pvar, 1);
    pvar += __shfl_xor_sync(0xffffffffu, pvar, 2);
    pvar += __shfl_xor_sync(0xffffffffu, pvar, 4);
    float inv = rsqrtf(pvar * (1.0f / 64.0f) + 1e-5f);

    if (quarter == 0) {
        float4 g0 = *(const float4*)&g[q * 8];
        float4 g1 = *(const float4*)&g[q * 8 + 4];
        float4 e0 = *(const float4*)&b[q * 8];
        float4 e1 = *(const float4*)&b[q * 8 + 4];
        float o[8];
        o[0] = fmaf(d[0] * inv, g0.x, e0.x);
        o[1] = fmaf(d[1] * inv, g0.y, e0.y);
        o[2] = fmaf(d[2] * inv, g0.z, e0.z);
        o[3] = fmaf(d[3] * inv, g0.w, e0.w);
        o[4] = fmaf(d[4] * inv, g1.x, e1.x);
        o[5] = fmaf(d[5] * inv, g1.y, e1.y);
        o[6] = fmaf(d[6] * inv, g1.z, e1.z);
        o[7] = fmaf(d[7] * inv, g1.w, e1.w);
        float4* ho = (float4*)&h[(size_t)row * 64 + q * 8];
        ho[0] = make_float4(o[0], o[1], o[2], o[3]);
        ho[1] = make_float4(o[4], o[5], o[6], o[7]);
        uint4 p;
        p.x = pack_f16(o[0], o[1]);
        p.y = pack_f16(o[2], o[3]);
        p.z = pack_f16(o[4], o[5]);
        p.w = pack_f16(o[6], o[7]);
        *(uint4*)&hf16[(size_t)row * 64 + q * 8] = p;
    }
}

// ---------------- generic HMMA GEMM (final projection) -----------------------
template<int KT, int NT, int AMODE, int POST, int DT, int BT>
__global__ void __launch_bounds__(256, 2)
k_mma(const float* __restrict__ A, const u16* __restrict__ Af16,
      const u16* __restrict__ Whi_g, const u16* __restrict__ Wlo_g,
      const float* __restrict__ bvec,
      float* __restrict__ C, u16* __restrict__ Chi_g, int M, int nstride) {
    constexpr int KP = KT + 8;
    constexpr bool THREE = (AMODE == 0);
    constexpr bool BLO = (BT == 2);
    constexpr int A_ELEMS = 128 * KP;
    constexpr int B_ELEMS = NT * KP;
    extern __shared__ __align__(16) u16 sm[];
    u16* Ahi = sm;
    u16* Alo = THREE ? (Ahi + A_ELEMS) : Ahi;
    u16* Bhi = (THREE ? Alo : Ahi) + A_ELEMS;
    u16* Blo = BLO ? (Bhi + B_ELEMS) : Bhi;

    const int tid = threadIdx.x;
    const int wid = tid >> 5, lane = tid & 31;
    const int row0 = blockIdx.x * 128;
    const int col_base = blockIdx.y * NT;
    Whi_g += (size_t)col_base * KT;
    Wlo_g += (size_t)col_base * KT;

    if (AMODE == 0) {
        constexpr int KH = KT / 2;
        for (int idx = tid; idx < 128 * KH; idx += 256) {
            int r = idx / KH, kp = idx - r * KH, k = kp * 2;
            int gr = row0 + r;
            float a0 = 0.f, a1 = 0.f;
            if (gr < M) {
                float2 t = ((const float2*)A)[(size_t)gr * KH + kp];
                a0 = t.x; a1 = t.y;
            }
            uint32_t hi, lo; split2(a0, a1, hi, lo);
            *(uint32_t*)&Ahi[r * KP + k] = hi;
            *(uint32_t*)&Alo[r * KP + k] = lo;
        }
    } else {
        constexpr int K8 = KT / 8;
        const uint4 z4 = make_uint4(0, 0, 0, 0);
        for (int idx = tid; idx < 128 * K8; idx += 256) {
            int r = idx / K8, k8 = idx - r * K8;
            int gr = row0 + r;
            uint4 vh = z4;
            if (gr < M) vh = *(const uint4*)&Af16[(size_t)gr * KT + k8 * 8];
            *(uint4*)&Ahi[r * KP + k8 * 8] = vh;
        }
    }
    {
        constexpr int K8 = KT / 8;
        for (int idx = tid; idx < NT * K8; idx += 256) {
            int n = idx / K8, k8 = idx - n * K8;
            *(uint4*)&Bhi[n * KP + k8 * 8] = *(const uint4*)&Whi_g[(size_t)n * KT + k8 * 8];
            if (BLO)
                *(uint4*)&Blo[n * KP + k8 * 8] = *(const uint4*)&Wlo_g[(size_t)n * KT + k8 * 8];
        }
    }
    __syncthreads();

    constexpr int NW = NT / 2;
    constexpr int NF = NW / 8;
    const int wm = wid & 3, wn = wid >> 2;
    const int mrow = wm * 32;
    const int ncol = wn * NW;

    float acc[2][NF][4];
    #pragma unroll
    for (int i = 0; i < 2; i++)
        #pragma unroll
        for (int nf = 0; nf < NF; nf++)
            #pragma unroll
            for (int j = 0; j < 4; j++) acc[i][nf][j] = 0.f;

    const uint32_t ahi_b = smem_u32(Ahi), alo_b = smem_u32(Alo);
    const uint32_t bhi_b = smem_u32(Bhi), blo_b = smem_u32(Blo);
    const int la  = lane & 15;
    const int lka = (lane >> 4) << 3;
    const int lbn = ((lane >> 4) << 3) + (lane & 7);
    const int lbk = ((lane >> 3) & 1) << 3;

    for (int kb = 0; kb < KT; kb += 16) {
        uint32_t ah[2][4], al[2][4];
        #pragma unroll
        for (int i = 0; i < 2; i++) {
            uint32_t aoff = (uint32_t)(((mrow + i * 16 + la) * KP + kb + lka) * 2);
            ldsm_x4(ah[i], ahi_b + aoff);
            if (THREE) ldsm_x4(al[i], alo_b + aoff);
        }
        #pragma unroll
        for (int nf = 0; nf < NF; nf += 2) {
            uint32_t boff = (uint32_t)(((ncol + nf * 8 + lbn) * KP + kb + lbk) * 2);
            uint32_t bh[4], bl[4];
            ldsm_x4(bh, bhi_b + boff);
            if (BLO) ldsm_x4(bl, blo_b + boff);
            #pragma unroll
            for (int i = 0; i < 2; i++) {
                mma16816<DT>(acc[i][nf],     ah[i], bh);
                mma16816<DT>(acc[i][nf + 1], ah[i], bh + 2);
                if (BLO) {
                    mma16816<DT>(acc[i][nf],     ah[i], bl);
                    mma16816<DT>(acc[i][nf + 1], ah[i], bl + 2);
                }
                if (THREE) {
                    mma16816<DT>(acc[i][nf],     al[i], bh);
                    mma16816<DT>(acc[i][nf + 1], al[i], bh + 2);
                }
            }
        }
    }

    const int qr = lane >> 2;
    const int qc = (lane & 3) * 2;
    #pragma unroll
    for (int i = 0; i < 2; i++) {
        #pragma unroll
        for (int half = 0; half < 2; half++) {
            int gr = row0 + mrow + i * 16 + half * 8 + qr;
            if (gr < M) {
                #pragma unroll
                for (int nf = 0; nf < NF; nf++) {
                    int c = col_base + ncol + nf * 8 + qc;
                    float v0 = acc[i][nf][half * 2 + 0] + bvec[c];
                    float v1 = acc[i][nf][half * 2 + 1] + bvec[c + 1];
                    *(float2*)&C[(size_t)gr * nstride + c] = make_float2(v0, v1);
                }
            }
        }
    }
}

// ---------------- fused conv kernel: w = f(z@Wa) @ Wb -> fp16 ----------------
__global__ void __launch_bounds__(256, 2)
k_conv(const float* __restrict__ Z,
       const u16* __restrict__ WaHi_g, const u16* __restrict__ WaLo_g,
       const u16* __restrict__ WbHi_g, const u16* __restrict__ WbLo_g,
       const float* __restrict__ rs, const float* __restrict__ ba,
       u16* __restrict__ Wout16, int M) {
    constexpr int KP = 72;
    extern __shared__ __align__(16) u16 sm[];
    u16* Ahi = sm;
    u16* Alo = Ahi + 128 * KP;
    u16* BaH = Alo + 128 * KP;
    u16* BaL = BaH + 64 * KP;
    u16* BbH = BaL + 64 * KP;
    u16* BbL = BbH + 64 * KP;

    const int tid = threadIdx.x;
    const int wid = tid >> 5, lane = tid & 31;
    const int row0 = blockIdx.x * 128;

    for (int idx = tid; idx < 128 * 32; idx += 256) {
        int r = idx >> 5, kp = idx & 31, k = kp * 2;
        int gr = row0 + r;
        float a0 = 0.f, a1 = 0.f;
        if (gr < M) {
            float2 t = ((const float2*)Z)[(size_t)gr * 32 + kp];
            a0 = t.x; a1 = t.y;
        }
        uint32_t hi, lo; split2(a0, a1, hi, lo);
        *(uint32_t*)&Ahi[r * KP + k] = hi;
        *(uint32_t*)&Alo[r * KP + k] = lo;
    }
    for (int idx = tid; idx < 64 * 8; idx += 256) {
        int n = idx >> 3, k8 = idx & 7;
        *(uint4*)&BaH[n * KP + k8 * 8] = *(const uint4*)&WaHi_g[(size_t)n * 64 + k8 * 8];
        *(uint4*)&BaL[n * KP + k8 * 8] = *(const uint4*)&WaLo_g[(size_t)n * 64 + k8 * 8];
        *(uint4*)&BbH[n * KP + k8 * 8] = *(const uint4*)&WbHi_g[(size_t)n * 64 + k8 * 8];
        *(uint4*)&BbL[n * KP + k8 * 8] = *(const uint4*)&WbLo_g[(size_t)n * 64 + k8 * 8];
    }
    __syncthreads();

    const int wm = wid & 3, wn = wid >> 2;
    const int mrow = wm * 32;
    const int ncol = wn * 32;
    const uint32_t ahi_b = smem_u32(Ahi), alo_b = smem_u32(Alo);
    const int la  = lane & 15;
    const int lka = (lane >> 4) << 3;
    const int lbn = ((lane >> 4) << 3) + (lane & 7);
    const int lbk = ((lane >> 3) & 1) << 3;
    const int qr = lane >> 2;
    const int qc = (lane & 3) * 2;

    float acc[2][4][4];
    {
        const uint32_t bh_b = smem_u32(BaH), bl_b = smem_u32(BaL);
        #pragma unroll
        for (int i = 0; i < 2; i++)
            #pragma unroll
            for (int nf = 0; nf < 4; nf++)
                #pragma unroll
                for (int j = 0; j < 4; j++) acc[i][nf][j] = 0.f;
        #pragma unroll
        for (int kb = 0; kb < 64; kb += 16) {
            uint32_t ah[2][4], al[2][4];
            #pragma unroll
            for (int i = 0; i < 2; i++) {
                uint32_t aoff = (uint32_t)(((mrow + i * 16 + la) * KP + kb + lka) * 2);
                ldsm_x4(ah[i], ahi_b + aoff);
                ldsm_x4(al[i], alo_b + aoff);
            }
            #pragma unroll
            for (int nf = 0; nf < 4; nf += 2) {
                uint32_t boff = (uint32_t)(((ncol + nf * 8 + lbn) * KP + kb + lbk) * 2);
                uint32_t bh[4], bl[4];
                ldsm_x4(bh, bh_b + boff);
                ldsm_x4(bl, bl_b + boff);
                #pragma unroll
                for (int i = 0; i < 2; i++) {
                    mma16816<0>(acc[i][nf],     ah[i], bh);
                    mma16816<0>(acc[i][nf],     ah[i], bl);
                    mma16816<0>(acc[i][nf],     al[i], bh);
                    mma16816<0>(acc[i][nf + 1], ah[i], bh + 2);
                    mma16816<0>(acc[i][nf + 1], ah[i], bl + 2);
                    mma16816<0>(acc[i][nf + 1], al[i], bh + 2);
                }
            }
        }
    }
    __syncthreads();

    #pragma unroll
    for (int i = 0; i < 2; i++) {
        #pragma unroll
        for (int half = 0; half < 2; half++) {
            int rloc = mrow + i * 16 + half * 8 + qr;
            int gr = row0 + rloc;
            float s = (gr < M) ? rs[gr] : 0.f;
            #pragma unroll
            for (int nf = 0; nf < 4; nf++) {
                int c = ncol + nf * 8 + qc;
                float y0 = (acc[i][nf][half * 2 + 0] * s + ba[c]) * s;
                float y1 = (acc[i][nf][half * 2 + 1] * s + ba[c + 1]) * s;
                uint32_t hi, lo; split2(y0, y1, hi, lo);
                *(uint32_t*)&Ahi[rloc * KP + c] = hi;
                *(uint32_t*)&Alo[rloc * KP + c] = lo;
            }
        }
    }
    __syncthreads();

    {
        const uint32_t bh_b = smem_u32(BbH), bl_b = smem_u32(BbL);
        #pragma unroll
        for (int i = 0; i < 2; i++)
            #pragma unroll
            for (int nf = 0; nf < 4; nf++)
                #pragma unroll
                for (int j = 0; j < 4; j++) acc[i][nf][j] = 0.f;
        #pragma unroll
        for (int kb = 0; kb < 64; kb += 16) {
            uint32_t ah[2][4], al[2][4];
            #pragma unroll
            for (int i = 0; i < 2; i++) {
                uint32_t aoff = (uint32_t)(((mrow + i * 16 + la) * KP + kb + lka) * 2);
                ldsm_x4(ah[i], ahi_b + aoff);
                ldsm_x4(al[i], alo_b + aoff);
            }
            #pragma unroll
            for (int nf = 0; nf < 4; nf += 2) {
                uint32_t boff = (uint32_t)(((ncol + nf * 8 + lbn) * KP + kb + lbk) * 2);
                uint32_t bh[4], bl[4];
                ldsm_x4(bh, bh_b + boff);
                ldsm_x4(bl, bl_b + boff);
                #pragma unroll
                for (int i = 0; i < 2; i++) {
                    mma16816<0>(acc[i][nf],     ah[i], bh);
                    mma16816<0>(acc[i][nf],     ah[i], bl);
                    mma16816<0>(acc[i][nf],     al[i], bh);
                    mma16816<0>(acc[i][nf + 1], ah[i], bh + 2);
                    mma16816<0>(acc[i][nf + 1], ah[i], bl + 2);
                    mma16816<0>(acc[i][nf + 1], al[i], bh + 2);
                }
            }
        }
    }
    #pragma unroll
    for (int i = 0; i < 2; i++) {
        #pragma unroll
        for (int half = 0; half < 2; half++) {
            int gr = row0 + mrow + i * 16 + half * 8 + qr;
            if (gr < M) {
                #pragma unroll
                for (int nf = 0; nf < 4; nf++) {
                    int c = ncol + nf * 8 + qc;
                    ((uint32_t*)Wout16)[((size_t)gr * 64 + c) >> 1] =
                        pack_f16(acc[i][nf][half * 2 + 0], acc[i][nf][half * 2 + 1]);
                }
            }
        }
    }
}

// ------ fully fused FFN: h = LN(h + relu(hf16@W1+c1)@W2 + c2), T in smem -----
__global__ void __launch_bounds__(256, 2)
k_ffn_ln(const u16* __restrict__ hf16_in, const u16* __restrict__ W1hi_g,
         const u16* __restrict__ W2hi_g, const float* __restrict__ c1,
         const float* __restrict__ c2, const float* __restrict__ g,
         const float* __restrict__ b, float* __restrict__ h,
         u16* __restrict__ hf16_out, int M) {
    constexpr int KP = 72;     // pitch for As / B1 / Tb (K or chunk = 64)
    constexpr int KP2 = 264;   // pitch for B2 (K = 256)
    extern __shared__ __align__(16) u16 sm[];
    u16* As = sm;                  // 128 x 72
    u16* B1 = As + 128 * KP;       // 256 x 72
    u16* B2 = B1 + 256 * KP;       // 64 x 264
    u16* Tb = B2 + 64 * KP2;       // 128 x 72 (T chunk)

    const int tid = threadIdx.x;
    const int wid = tid >> 5, lane = tid & 31;
    const int row0 = blockIdx.x * 128;
    const int wm = wid & 3, wn = wid >> 2;
    const int mrow = wm * 32;
    const int ncol = wn * 32;
    const int la  = lane & 15;
    const int lka = (lane >> 4) << 3;
    const int lbn = ((lane >> 4) << 3) + (lane & 7);
    const int lbk = ((lane >> 3) & 1) << 3;
    const int qr = lane >> 2;
    const int qc = (lane & 3) * 2;
    const uint4 z4 = make_uint4(0, 0, 0, 0);

    // fill As (128 x 64 fp16)
    for (int idx = tid; idx < 128 * 8; idx += 256) {
        int r = idx >> 3, k8 = idx & 7;
        int gr = row0 + r;
        uint4 v = z4;
        if (gr < M) v = *(const uint4*)&hf16_in[(size_t)gr * 64 + k8 * 8];
        *(uint4*)&As[r * KP + k8 * 8] = v;
    }
    // fill B1 (256 n x 64 k)
    for (int idx = tid; idx < 256 * 8; idx += 256) {
        int n = idx >> 3, k8 = idx & 7;
        *(uint4*)&B1[n * KP + k8 * 8] = *(const uint4*)&W1hi_g[(size_t)n * 64 + k8 * 8];
    }
    // fill B2 (64 n x 256 k)
    for (int idx = tid; idx < 64 * 32; idx += 256) {
        int n = idx >> 5, k8 = idx & 31;
        *(uint4*)&B2[n * KP2 + k8 * 8] = *(const uint4*)&W2hi_g[(size_t)n * 256 + k8 * 8];
    }
    __syncthreads();

    const uint32_t as_b = smem_u32(As), b1_b = smem_u32(B1);
    const uint32_t b2_b = smem_u32(B2), tb_b = smem_u32(Tb);

    float uacc[2][4][4];
    #pragma unroll
    for (int i = 0; i < 2; i++)
        #pragma unroll
        for (int nf = 0; nf < 4; nf++)
            #pragma unroll
            for (int j = 0; j < 4; j++) uacc[i][nf][j] = 0.f;

    for (int chunk = 0; chunk < 4; chunk++) {
        const int cbase = chunk * 64;
        float tacc[2][4][4];
        #pragma unroll
        for (int i = 0; i < 2; i++)
            #pragma unroll
            for (int nf = 0; nf < 4; nf++)
                #pragma unroll
                for (int j = 0; j < 4; j++) tacc[i][nf][j] = 0.f;

        // FFN1 mainloop for this 64-col chunk
        #pragma unroll
        for (int kb = 0; kb < 64; kb += 16) {
            uint32_t ah[2][4];
            #pragma unroll
            for (int i = 0; i < 2; i++) {
                uint32_t aoff = (uint32_t)(((mrow + i * 16 + la) * KP + kb + lka) * 2);
                ldsm_x4(ah[i], as_b + aoff);
            }
            #pragma unroll
            for (int nf = 0; nf < 4; nf += 2) {
                uint32_t boff = (uint32_t)(((cbase + ncol + nf * 8 + lbn) * KP + kb + lbk) * 2);
                uint32_t bh[4];
                ldsm_x4(bh, b1_b + boff);
                #pragma unroll
                for (int i = 0; i < 2; i++) {
                    mma16816<1>(tacc[i][nf],     ah[i], bh);
                    mma16816<1>(tacc[i][nf + 1], ah[i], bh + 2);
                }
            }
        }
        __syncthreads();   // previous chunk's Tb fully consumed
        // write T chunk (relu + bias -> fp16) into Tb
        #pragma unroll
        for (int i = 0; i < 2; i++) {
            #pragma unroll
            for (int half = 0; half < 2; half++) {
                int rloc = mrow + i * 16 + half * 8 + qr;
                #pragma unroll
                for (int nf = 0; nf < 4; nf++) {
                    int c = ncol + nf * 8 + qc;
                    float t0 = fmaxf(tacc[i][nf][half * 2 + 0] + c1[cbase + c], 0.f);
                    float t1 = fmaxf(tacc[i][nf][half * 2 + 1] + c1[cbase + c + 1], 0.f);
                    *(uint32_t*)&Tb[rloc * KP + c] = pack_f16(t0, t1);
                }
            }
        }
        __syncthreads();
        // FFN2 partial: uacc += Tb(128x64) @ W2[cbase:cbase+64, :]
        #pragma unroll
        for (int kb = 0; kb < 64; kb += 16) {
            uint32_t ah[2][4];
            #pragma unroll
            for (int i = 0; i < 2; i++) {
                uint32_t aoff = (uint32_t)(((mrow + i * 16 + la) * KP + kb + lka) * 2);
                ldsm_x4(ah[i], tb_b + aoff);
            }
            #pragma unroll
            for (int nf = 0; nf < 4; nf += 2) {
                uint32_t boff = (uint32_t)(((ncol + nf * 8 + lbn) * KP2 + cbase + kb + lbk) * 2);
                uint32_t bh[4];
                ldsm_x4(bh, b2_b + boff);
                #pragma unroll
                for (int i = 0; i < 2; i++) {
                    mma16816<1>(uacc[i][nf],     ah[i], bh);
                    mma16816<1>(uacc[i][nf + 1], ah[i], bh + 2);
                }
            }
        }
    }

    // stage x = h + U + c2 into smem (fp32, stride 72; reuses As/B1 region)
    __syncthreads();
    float* xs = (float*)sm;
    #pragma unroll
    for (int i = 0; i < 2; i++) {
        #pragma unroll
        for (int half = 0; half < 2; half++) {
            int rloc = mrow + i * 16 + half * 8 + qr;
            int gr = row0 + rloc;
            #pragma unroll
            for (int nf = 0; nf < 4; nf++) {
                int c = ncol + nf * 8 + qc;
                float x0 = 0.f, x1 = 0.f;
                if (gr < M) {
                    float2 hres = *(const float2*)&h[(size_t)gr * 64 + c];
                    x0 = uacc[i][nf][half * 2 + 0] + c2[c] + hres.x;
                    x1 = uacc[i][nf][half * 2 + 1] + c2[c + 1] + hres.y;
                }
                xs[rloc * 72 + c]     = x0;
                xs[rloc * 72 + c + 1] = x1;
            }
        }
    }
    __syncthreads();

    // LN: warp wid handles rows wid*16 .. wid*16+15
    const int c0 = lane * 2;
    for (int rr = 0; rr < 16; rr++) {
        int rloc = wid * 16 + rr;
        int gr = row0 + rloc;
        if (gr >= M) continue;
        float x0 = xs[rloc * 72 + c0];
        float x1 = xs[rloc * 72 + c0 + 1];
        float sum = x0 + x1;
        #pragma unroll
        for (int o = 16; o; o >>= 1) sum += __shfl_xor_sync(0xffffffffu, sum, o);
        float mu = sum * (1.0f / 64.0f);
        float d0 = x0 - mu, d1 = x1 - mu;
        float vs = d0 * d0 + d1 * d1;
        #pragma unroll
        for (int o = 16; o; o >>= 1) vs += __shfl_xor_sync(0xffffffffu, vs, o);
        float inv = rsqrtf(vs * (1.0f / 64.0f) + 1e-5f);
        float o0 = fmaf(d0 * inv, g[c0], b[c0]);
        float o1 = fmaf(d1 * inv, g[c0 + 1], b[c0 + 1]);
        *(float2*)&h[(size_t)gr * 64 + c0] = make_float2(o0, o1);
        ((uint32_t*)hf16_out)[((size_t)gr * 64 + c0) >> 1] = pack_f16(o0, o1);
    }
}

// ---------------- LayerNorm (standalone, final) ------------------------------
__global__ void k_lnF(const float* __restrict__ base,
                      const float* __restrict__ g, const float* __restrict__ b,
                      float* __restrict__ out, int M) {
    const int warp = threadIdx.x >> 5;
    const int lane = threadIdx.x & 31;
    const int row = blockIdx.x * (blockDim.x >> 5) + warp;
    if (row >= M) return;
    const int i0 = row * 64 + lane;
    const int i1 = i0 + 32;
    float x0 = base[i0], x1 = base[i1];
    float sum = x0 + x1;
    #pragma unroll
    for (int o = 16; o; o >>= 1) sum += __shfl_xor_sync(0xffffffffu, sum, o);
    float mu = sum * (1.0f / 64.0f);
    float d0 = x0 - mu, d1 = x1 - mu;
    float vs = d0 * d0 + d1 * d1;
    #pragma unroll
    for (int o = 16; o; o >>= 1) vs += __shfl_xor_sync(0xffffffffu, vs, o);
    float inv = rsqrtf(vs * (1.0f / 64.0f) + 1e-5f);
    out[i0] = fmaf(d0 * inv, g[lane], b[lane]);
    out[i1] = fmaf(d1 * inv, g[lane + 32], b[lane + 32]);
}

// ---------------- orchestration ----------------------------------------------
extern "C" void kernel_launch(void* const* d_in, const int* in_sizes, int n_in,
                              void* d_out, int out_size) {
    const float* x    = (const float*)d_in[0];
    const int*   esrc = (const int*)d_in[1];
    const int*   edst = (const int*)d_in[2];
    const int wi = (n_in >= 20) ? 4 : 3;
    const float* Wn2h = (const float*)d_in[wi + 0];
    const float* bn2h = (const float*)d_in[wi + 1];
    const float* Wh2n = (const float*)d_in[wi + 2];
    const float* bh2n = (const float*)d_in[wi + 3];
    const float* W1   = (const float*)d_in[wi + 4];
    const float* b1   = (const float*)d_in[wi + 5];
    const float* W2   = (const float*)d_in[wi + 6];
    const float* b2   = (const float*)d_in[wi + 7];
    const float* g1   = (const float*)d_in[wi + 8];
    const float* be1  = (const float*)d_in[wi + 9];
    const float* g2   = (const float*)d_in[wi + 10];
    const float* be2  = (const float*)d_in[wi + 11];
    const float* gF   = (const float*)d_in[wi + 12];
    const float* bF   = (const float*)d_in[wi + 13];
    const float* Wo   = (const float*)d_in[wi + 14];
    const float* bo   = (const float*)d_in[wi + 15];

    float *p_h, *p_b1, *p_ha, *p_invn, *p_invh;
    u16 *p_hf16, *p_wf16;
    u16 *p_wa_hi, *p_wa_lo, *p_wb_hi, *p_wb_lo, *p_w1_hi, *p_w2_hi, *p_wo_hi, *p_wo_lo;
    int *p_cntH, *p_cntN, *p_stH, *p_stN, *p_cuH, *p_cuN, *p_csrH, *p_csrN;
    int *p_bsN, *p_boN, *p_bsH, *p_boH;
    cudaGetSymbolAddress((void**)&p_h,    g_h);
    cudaGetSymbolAddress((void**)&p_b1,   g_b1);
    cudaGetSymbolAddress((void**)&p_hf16, g_hf16);
    cudaGetSymbolAddress((void**)&p_ha,   g_ha);
    cudaGetSymbolAddress((void**)&p_wf16, g_wf16);
    cudaGetSymbolAddress((void**)&p_wa_hi, g_wa_hi);
    cudaGetSymbolAddress((void**)&p_wa_lo, g_wa_lo);
    cudaGetSymbolAddress((void**)&p_wb_hi, g_wb_hi);
    cudaGetSymbolAddress((void**)&p_wb_lo, g_wb_lo);
    cudaGetSymbolAddress((void**)&p_w1_hi, g_w1_hi);
    cudaGetSymbolAddress((void**)&p_w2_hi, g_w2_hi);
    cudaGetSymbolAddress((void**)&p_wo_hi, g_wo_hi);
    cudaGetSymbolAddress((void**)&p_wo_lo, g_wo_lo);
    cudaGetSymbolAddress((void**)&p_invn, g_invn);
    cudaGetSymbolAddress((void**)&p_invh, g_invh);
    cudaGetSymbolAddress((void**)&p_cntH, g_cntH);
    cudaGetSymbolAddress((void**)&p_cntN, g_cntN);
    cudaGetSymbolAddress((void**)&p_stH,  g_startH);
    cudaGetSymbolAddress((void**)&p_stN,  g_startN);
    cudaGetSymbolAddress((void**)&p_cuH,  g_curH);
    cudaGetSymbolAddress((void**)&p_cuN,  g_curN);
    cudaGetSymbolAddress((void**)&p_csrH, g_csrH);
    cudaGetSymbolAddress((void**)&p_csrN, g_csrN);
    cudaGetSymbolAddress((void**)&p_bsN, g_bsumN);
    cudaGetSymbolAddress((void**)&p_boN, g_boffN);
    cudaGetSymbolAddress((void**)&p_bsH, g_bsumH);
    cudaGetSymbolAddress((void**)&p_boH, g_boffH);

    const int smem_convf = (2 * 128 * 72 + 4 * 64 * 72) * 2;            //  73728
    const int smem_ffn   = (128 * 72 + 256 * 72 + 64 * 264 + 128 * 72) * 2;  // 107520
    const int smem_proj  = (2 * 128 * 72 + 2 * 64 * 72) * 2;            //  55296
    cudaFuncSetAttribute((const void*)k_conv, cudaFuncAttributeMaxDynamicSharedMemorySize, smem_convf);
    cudaFuncSetAttribute((const void*)k_ffn_ln, cudaFuncAttributeMaxDynamicSharedMemorySize, smem_ffn);
    cudaFuncSetAttribute((const void*)k_mma<64, 64, 0, 1, 0, 2>, cudaFuncAttributeMaxDynamicSharedMemorySize, smem_proj);

    cudaMemcpyAsync(p_h, x, (size_t)NN * DD * sizeof(float), cudaMemcpyDeviceToDevice);
    k_f2h<<<(NN * 32 + 255) / 256, 256>>>(x, p_hf16, NN * 32);

    // ---- weight pre-split ----
    k_prep<0><<<(LL * DD * DD + 255) / 256, 256>>>(Wn2h, DD, DD, LL * DD * DD, p_wa_hi, p_wa_lo);
    k_prep<0><<<(LL * DD * DD + 255) / 256, 256>>>(Wh2n, DD, DD, LL * DD * DD, p_wb_hi, p_wb_lo);
    k_prep<1><<<(LL * DD * FF + 255) / 256, 256>>>(W1, DD, FF, LL * DD * FF, p_w1_hi, nullptr);
    k_prep<1><<<(LL * FF * DD + 255) / 256, 256>>>(W2, FF, DD, LL * FF * DD, p_w2_hi, nullptr);
    k_prep<0><<<(DD * DD + 255) / 256, 256>>>(Wo, DD, DD, DD * DD, p_wo_hi, p_wo_lo);

    // ---- build CSR + degree norms (multi-block scans) ----
    const int nbN = (NN + 1023) / 1024;   // 98
    const int nbH = (HH + 1023) / 1024;   // 20
    k_zero4<<<256, 256>>>(p_cntN, NN, p_cntH, HH, p_cuN, NN, p_cuH, HH);
    k_hist<<<(EE + 255) / 256, 256>>>(esrc, edst, p_cntN, p_cntH);
    k_bsum<<<nbH, 1024>>>(p_cntH, p_bsH, HH);
    k_bsum<<<nbN, 1024>>>(p_cntN, p_bsN, NN);
    k_scan<<<1, 1024>>>(p_bsH, p_boH, nbH);
    k_scan<<<1, 1024>>>(p_bsN, p_boN, nbN);
    k_scan2<<<nbH, 1024>>>(p_cntH, p_boH, p_stH, HH);
    k_scan2<<<nbN, 1024>>>(p_cntN, p_boN, p_stN, NN);
    k_fill<<<(EE + 255) / 256, 256>>>(esrc, edst, p_stH, p_stN, p_cuH, p_cuN, p_csrH, p_csrN);
    k_inv<<<(NN + 255) / 256, 256>>>(p_cntN, p_cntH, p_invn, p_invh);

    const int gN  = (NN + 127) / 128;
    const int gH  = (HH + 127) / 128;
    const int gLN = (NN + 7) / 8;
    const int gAgH = (HH + 7) / 8;
    const int gAgN = (NN + 7) / 8;

    for (int l = 0; l < LL; l++) {
        const float* ba = bn2h + (size_t)l * DD;
        const float* bb = bh2n + (size_t)l * DD;
        const float* c1 = b1 + (size_t)l * FF;
        const float* c2 = b2 + (size_t)l * DD;
        const float* gg1 = g1 + (size_t)l * DD;
        const float* ee1 = be1 + (size_t)l * DD;
        const float* gg2 = g2 + (size_t)l * DD;
        const float* ee2 = be2 + (size_t)l * DD;

        // z = agg_H(hf16 * invn[src])
        k_agg16<<<gAgH, 256>>>(p_hf16, p_csrH, p_stH, p_cntH, p_invn, p_ha, HH);
        // fused: y = (z@Wa*invh+ba)*invh ; w = y@Wb -> fp16
        k_conv<<<gH, 256, smem_convf>>>(
            p_ha, p_wa_hi + (size_t)l * DD * DD, p_wa_lo + (size_t)l * DD * DD,
            p_wb_hi + (size_t)l * DD * DD, p_wb_lo + (size_t)l * DD * DD,
            p_invh, ba, p_wf16, HH);
        // fused: u = agg_N(wf16); h = LN(h + u*invn + bb) -> h fp32 + fp16
        k_agg_ln16<<<gAgN, 256>>>(p_wf16, p_csrN, p_stN, p_cntN, p_invn, bb,
                                  gg1, ee1, p_h, p_hf16, NN);
        // fully fused FFN + residual + LN2 (T never leaves smem)
        k_ffn_ln<<<gN, 256, smem_ffn>>>(
            p_hf16, p_w1_hi + (size_t)l * DD * FF, p_w2_hi + (size_t)l * FF * DD,
            c1, c2, gg2, ee2, p_h, p_hf16, NN);
    }

    // final LN + projection (3-term bf16, exact path)
    k_lnF<<<gLN, 256>>>(p_h, gF, bF, p_b1, NN);
    k_mma<64, 64, 0, 1, 0, 2><<<gN, 256, smem_proj>>>(
        p_b1, nullptr, p_wo_hi, p_wo_lo, bo, (float*)d_out, nullptr, NN, DD);
}

// round 12
// speedup vs baseline: 1.9448x; 1.0609x over previous
#include <cuda_runtime.h>
#include <cuda_bf16.h>
#include <cuda_fp16.h>
#include <cstdint>
#include <math.h>

#define NN 100000
#define HH 20000
#define EE 1600000
#define DD 64
#define FF 256
#define LL 3

typedef unsigned short u16;

// ---------------- helpers ----------------------------------------------------
__device__ __forceinline__ uint32_t smem_u32(const void* p) {
    uint32_t a;
    asm("{ .reg .u64 t; cvta.to.shared.u64 t, %1; cvt.u32.u64 %0, t; }" : "=r"(a) : "l"(p));
    return a;
}
__device__ __forceinline__ void ldsm_x4(uint32_t* r, uint32_t addr) {
    asm volatile("ldmatrix.sync.aligned.m8n8.x4.shared.b16 {%0,%1,%2,%3}, [%4];"
                 : "=r"(r[0]), "=r"(r[1]), "=r"(r[2]), "=r"(r[3]) : "r"(addr));
}
// DT 0 = bf16, 1 = fp16
template<int DT>
__device__ __forceinline__ void mma16816(float* d, const uint32_t* a, const uint32_t* b) {
    if (DT == 0)
        asm volatile("mma.sync.aligned.m16n8k16.row.col.f32.bf16.bf16.f32 "
                     "{%0,%1,%2,%3}, {%4,%5,%6,%7}, {%8,%9}, {%0,%1,%2,%3};"
                     : "+f"(d[0]), "+f"(d[1]), "+f"(d[2]), "+f"(d[3])
                     : "r"(a[0]), "r"(a[1]), "r"(a[2]), "r"(a[3]), "r"(b[0]), "r"(b[1]));
    else
        asm volatile("mma.sync.aligned.m16n8k16.row.col.f32.f16.f16.f32 "
                     "{%0,%1,%2,%3}, {%4,%5,%6,%7}, {%8,%9}, {%0,%1,%2,%3};"
                     : "+f"(d[0]), "+f"(d[1]), "+f"(d[2]), "+f"(d[3])
                     : "r"(a[0]), "r"(a[1]), "r"(a[2]), "r"(a[3]), "r"(b[0]), "r"(b[1]));
}
__device__ __forceinline__ void split2(float a, float b, uint32_t& hi, uint32_t& lo) {
    __nv_bfloat16 ha = __float2bfloat16(a), hb = __float2bfloat16(b);
    float ra = a - __bfloat162float(ha);
    float rb = b - __bfloat162float(hb);
    __nv_bfloat16 la = __float2bfloat16(ra), lb = __float2bfloat16(rb);
    hi = (uint32_t)__bfloat16_as_ushort(ha) | ((uint32_t)__bfloat16_as_ushort(hb) << 16);
    lo = (uint32_t)__bfloat16_as_ushort(la) | ((uint32_t)__bfloat16_as_ushort(lb) << 16);
}
__device__ __forceinline__ uint32_t pack_f16(float lo, float hi) {
    __half2 h = __floats2half2_rn(lo, hi);
    return *(uint32_t*)&h;
}
__device__ __forceinline__ void unpack_f16(uint32_t v, float& lo, float& hi) {
    __half2 h = *(__half2*)&v;
    float2 f = __half22float2(h);
    lo = f.x; hi = f.y;
}
__device__ __forceinline__ void unpack8(const uint4& p, float* f) {
    unpack_f16(p.x, f[0], f[1]);
    unpack_f16(p.y, f[2], f[3]);
    unpack_f16(p.z, f[4], f[5]);
    unpack_f16(p.w, f[6], f[7]);
}

// ---------------- scratch ----------------------------------------------------
__device__ __align__(16) float g_h  [NN * DD];
__device__ __align__(16) u16 g_hf16[NN * DD];
__device__ __align__(16) float g_ha [HH * DD];
__device__ __align__(16) u16 g_wf16[HH * DD];
__device__ __align__(16) u16 g_wa_hi[LL * DD * DD];   // bf16
__device__ __align__(16) u16 g_wa_lo[LL * DD * DD];
__device__ __align__(16) u16 g_wb_hi[LL * DD * DD];   // bf16
__device__ __align__(16) u16 g_wb_lo[LL * DD * DD];
__device__ __align__(16) u16 g_w1_hi[LL * DD * FF];   // fp16
__device__ __align__(16) u16 g_w2_hi[LL * FF * DD];   // fp16
__device__ __align__(16) u16 g_wo_hi[DD * DD];        // bf16
__device__ __align__(16) u16 g_wo_lo[DD * DD];
__device__ float g_invn[NN];
__device__ float g_invh[HH];
__device__ int g_cntH [HH];
__device__ int g_cntN [NN];
__device__ int g_startH[HH];
__device__ int g_startN[NN];
__device__ int g_curH [HH];
__device__ int g_curN [NN];
__device__ int g_csrH [EE];
__device__ int g_csrN [EE];
__device__ int g_bsumN[128];
__device__ int g_boffN[128];
__device__ int g_bsumH[32];
__device__ int g_boffH[32];

// ---------------- combined prep: all weight splits + h fp16 copy -------------
__device__ __forceinline__ void prep_bf16(const float* src, int K, int N, int idx,
                                          u16* hi, u16* lo) {
    int KN = K * N;
    int l = idx / KN;
    int r = idx - l * KN;
    int k = r / N, n = r - k * N;
    float v = src[idx];
    size_t o = (size_t)l * KN + (size_t)n * K + k;
    __nv_bfloat16 h = __float2bfloat16(v);
    float res = v - __bfloat162float(h);
    hi[o] = __bfloat16_as_ushort(h);
    lo[o] = __bfloat16_as_ushort(__float2bfloat16(res));
}
__device__ __forceinline__ void prep_f16(const float* src, int K, int N, int idx,
                                         u16* hi) {
    int KN = K * N;
    int l = idx / KN;
    int r = idx - l * KN;
    int k = r / N, n = r - k * N;
    hi[(size_t)l * KN + (size_t)n * K + k] = __half_as_ushort(__float2half_rn(src[idx]));
}

#define TWA (LL * DD * DD)   // 12288
#define TW1 (LL * DD * FF)   // 49152
#define TWO (DD * DD)        // 4096
#define TF2H (NN * 32)       // 3,200,000
#define TPREP (2 * TWA + 2 * TW1 + TWO + TF2H)

__global__ void k_prep_all(const float* __restrict__ Wn2h, const float* __restrict__ Wh2n,
                           const float* __restrict__ W1, const float* __restrict__ W2,
                           const float* __restrict__ Wo, const float* __restrict__ x,
                           u16* __restrict__ wa_hi, u16* __restrict__ wa_lo,
                           u16* __restrict__ wb_hi, u16* __restrict__ wb_lo,
                           u16* __restrict__ w1_hi, u16* __restrict__ w2_hi,
                           u16* __restrict__ wo_hi, u16* __restrict__ wo_lo,
                           u16* __restrict__ hf16) {
    int idx = blockIdx.x * blockDim.x + threadIdx.x;
    if (idx < TF2H) {
        float2 v = ((const float2*)x)[idx];
        ((uint32_t*)hf16)[idx] = pack_f16(v.x, v.y);
        return;
    }
    idx -= TF2H;
    if (idx < TWA) { prep_bf16(Wn2h, DD, DD, idx, wa_hi, wa_lo); return; }
    idx -= TWA;
    if (idx < TWA) { prep_bf16(Wh2n, DD, DD, idx, wb_hi, wb_lo); return; }
    idx -= TWA;
    if (idx < TW1) { prep_f16(W1, DD, FF, idx, w1_hi); return; }
    idx -= TW1;
    if (idx < TW1) { prep_f16(W2, FF, DD, idx, w2_hi); return; }
    idx -= TW1;
    if (idx < TWO) { prep_bf16(Wo, DD, DD, idx, wo_hi, wo_lo); }
}

// ---------------- CSR build --------------------------------------------------
__global__ void k_zero4(int* __restrict__ a, int na, int* __restrict__ b, int nb,
                        int* __restrict__ c, int nc, int* __restrict__ d, int nd) {
    int i = blockIdx.x * blockDim.x + threadIdx.x;
    int stride = gridDim.x * blockDim.x;
    for (int j = i; j < na; j += stride) a[j] = 0;
    for (int j = i; j < nb; j += stride) b[j] = 0;
    for (int j = i; j < nc; j += stride) c[j] = 0;
    for (int j = i; j < nd; j += stride) d[j] = 0;
}

__global__ void k_hist(const int* __restrict__ src, const int* __restrict__ dst,
                       int* __restrict__ cntN, int* __restrict__ cntH) {
    int e = blockIdx.x * blockDim.x + threadIdx.x;
    if (e < EE) {
        atomicAdd(&cntN[src[e]], 1);
        atomicAdd(&cntH[dst[e]], 1);
    }
}

// both block-sum passes in one launch
__global__ void k_bsum2(const int* __restrict__ cntN, int* __restrict__ bsN, int nbN,
                        const int* __restrict__ cntH, int* __restrict__ bsH) {
    __shared__ int sw[32];
    const int tid = threadIdx.x, lane = tid & 31, warp = tid >> 5;
    const int* cnt; int* bsum; int n; int cblk;
    if ((int)blockIdx.x < nbN) { cnt = cntN; bsum = bsN; n = NN; cblk = blockIdx.x; }
    else { cnt = cntH; bsum = bsH; n = HH; cblk = blockIdx.x - nbN; }
    int i = cblk * 1024 + tid;
    int v = (i < n) ? cnt[i] : 0;
    #pragma unroll
    for (int o = 16; o; o >>= 1) v += __shfl_xor_sync(0xffffffffu, v, o);
    if (lane == 0) sw[warp] = v;
    __syncthreads();
    if (warp == 0) {
        int t = sw[lane];
        #pragma unroll
        for (int o = 16; o; o >>= 1) t += __shfl_xor_sync(0xffffffffu, t, o);
        if (lane == 0) bsum[cblk] = t;
    }
}

// scan both small block-sum arrays (n <= 1024 each) in one launch, 2 blocks
__global__ void k_scanboth(const int* __restrict__ bsN, int* __restrict__ boN, int nN,
                           const int* __restrict__ bsH, int* __restrict__ boH, int nH) {
    __shared__ int shw[33];
    const int tid = threadIdx.x;
    const int lane = tid & 31, warp = tid >> 5;
    const int* cnt = (blockIdx.x == 0) ? bsN : bsH;
    int* start = (blockIdx.x == 0) ? boN : boH;
    int n = (blockIdx.x == 0) ? nN : nH;
    int v = (tid < n) ? cnt[tid] : 0;
    int inc = v;
    #pragma unroll
    for (int o = 1; o < 32; o <<= 1) {
        int t = __shfl_up_sync(0xffffffffu, inc, o);
        if (lane >= o) inc += t;
    }
    if (lane == 31) shw[warp] = inc;
    __syncthreads();
    if (warp == 0) {
        int t = shw[lane];
        int winc = t;
        #pragma unroll
        for (int o = 1; o < 32; o <<= 1) {
            int u = __shfl_up_sync(0xffffffffu, winc, o);
            if (lane >= o) winc += u;
        }
        shw[lane] = winc - t;
    }
    __syncthreads();
    if (tid < n) start[tid] = shw[warp] + inc - v;
}

// apply per-chunk exclusive scan + block offset, AND compute inv-sqrt norms
__global__ void k_scan2inv(const int* __restrict__ cntN, const int* __restrict__ boffN,
                           int* __restrict__ startN, float* __restrict__ invn, int nbN,
                           const int* __restrict__ cntH, const int* __restrict__ boffH,
                           int* __restrict__ startH, float* __restrict__ invh) {
    __shared__ int shw[32];
    const int tid = threadIdx.x, lane = tid & 31, warp = tid >> 5;
    const int* cnt; const int* boff; int* start; float* invv; int n; int cblk;
    if ((int)blockIdx.x < nbN) {
        cnt = cntN; boff = boffN; start = startN; invv = invn; n = NN; cblk = blockIdx.x;
    } else {
        cnt = cntH; boff = boffH; start = startH; invv = invh; n = HH; cblk = blockIdx.x - nbN;
    }
    int i = cblk * 1024 + tid;
    int v = (i < n) ? cnt[i] : 0;
    int inc = v;
    #pragma unroll
    for (int o = 1; o < 32; o <<= 1) {
        int t = __shfl_up_sync(0xffffffffu, inc, o);
        if (lane >= o) inc += t;
    }
    if (lane == 31) shw[warp] = inc;
    __syncthreads();
    if (warp == 0) {
        int t = shw[lane];
        int winc = t;
        #pragma unroll
        for (int o = 1; o < 32; o <<= 1) {
            int u = __shfl_up_sync(0xffffffffu, winc, o);
            if (lane >= o) winc += u;
        }
        shw[lane] = winc - t;
    }
    __syncthreads();
    if (i < n) {
        start[i] = boff[cblk] + shw[warp] + inc - v;
        invv[i] = rsqrtf(fmaxf((float)v, 1.0f));
    }
}

__global__ void k_fill(const int* __restrict__ src, const int* __restrict__ dst,
                       const int* __restrict__ startH, const int* __restrict__ startN,
                       int* __restrict__ curH, int* __restrict__ curN,
                       int* __restrict__ csrH, int* __restrict__ csrN) {
    int e = blockIdx.x * blockDim.x + threadIdx.x;
    if (e < EE) {
        int s = src[e], d = dst[e];
        int p = atomicAdd(&curH[d], 1);
        csrH[startH[d] + p] = s;
        int q = atomicAdd(&curN[s], 1);
        csrN[startN[s] + q] = d;
    }
}

// ------- fp16 gather (scaled), uint4 lanes, MLP 16 ---------------------------
__global__ void k_agg16(const u16* __restrict__ Y, const int* __restrict__ csr,
                        const int* __restrict__ start, const int* __restrict__ cnt,
                        const float* __restrict__ scale, float* __restrict__ out, int M) {
    const int warp = threadIdx.x >> 5;
    const int lane = threadIdx.x & 31;
    const int row = blockIdx.x * (blockDim.x >> 5) + warp;
    if (row >= M) return;
    const int quarter = lane >> 3;
    const int q = lane & 7;
    const int s0 = start[row];
    const int c  = cnt[row];
    const uint4* __restrict__ Y4 = (const uint4*)Y;

    float acc[8];
    #pragma unroll
    for (int k = 0; k < 8; k++) acc[k] = 0.f;
    float t[8];

    int j = quarter;
    for (; j + 12 < c; j += 16) {
        int i0 = __ldg(&csr[s0 + j]);
        int i1 = __ldg(&csr[s0 + j + 4]);
        int i2 = __ldg(&csr[s0 + j + 8]);
        int i3 = __ldg(&csr[s0 + j + 12]);
        uint4 p0 = Y4[(size_t)i0 * 8 + q];
        uint4 p1 = Y4[(size_t)i1 * 8 + q];
        uint4 p2 = Y4[(size_t)i2 * 8 + q];
        uint4 p3 = Y4[(size_t)i3 * 8 + q];
        float f0 = __ldg(&scale[i0]), f1 = __ldg(&scale[i1]);
        float f2 = __ldg(&scale[i2]), f3 = __ldg(&scale[i3]);
        unpack8(p0, t);
        #pragma unroll
        for (int k = 0; k < 8; k++) acc[k] = fmaf(t[k], f0, acc[k]);
        unpack8(p1, t);
        #pragma unroll
        for (int k = 0; k < 8; k++) acc[k] = fmaf(t[k], f1, acc[k]);
        unpack8(p2, t);
        #pragma unroll
        for (int k = 0; k < 8; k++) acc[k] = fmaf(t[k], f2, acc[k]);
        unpack8(p3, t);
        #pragma unroll
        for (int k = 0; k < 8; k++) acc[k] = fmaf(t[k], f3, acc[k]);
    }
    for (; j < c; j += 4) {
        int i0 = __ldg(&csr[s0 + j]);
        uint4 p0 = Y4[(size_t)i0 * 8 + q];
        float f0 = __ldg(&scale[i0]);
        unpack8(p0, t);
        #pragma unroll
        for (int k = 0; k < 8; k++) acc[k] = fmaf(t[k], f0, acc[k]);
    }
    #pragma unroll
    for (int k = 0; k < 8; k++) {
        acc[k] += __shfl_xor_sync(0xffffffffu, acc[k], 8);
        acc[k] += __shfl_xor_sync(0xffffffffu, acc[k], 16);
    }
    if (quarter == 0) {
        float4* o4 = (float4*)&out[(size_t)row * 64 + q * 8];
        o4[0] = make_float4(acc[0], acc[1], acc[2], acc[3]);
        o4[1] = make_float4(acc[4], acc[5], acc[6], acc[7]);
    }
}

// --- fp16 gather (uint4) + residual + bias + LN, writes h fp32 + fp16 --------
__global__ void k_agg_ln16(const u16* __restrict__ Y, const int* __restrict__ csr,
                           const int* __restrict__ start, const int* __restrict__ cnt,
                           const float* __restrict__ invn, const float* __restrict__ bb,
                           const float* __restrict__ g, const float* __restrict__ b,
                           float* __restrict__ h, u16* __restrict__ hf16, int M) {
    const int warp = threadIdx.x >> 5;
    const int lane = threadIdx.x & 31;
    const int row = blockIdx.x * (blockDim.x >> 5) + warp;
    if (row >= M) return;
    const int quarter = lane >> 3;
    const int q = lane & 7;
    const int s0 = start[row];
    const int c  = cnt[row];
    const uint4* __restrict__ Y4 = (const uint4*)Y;

    float acc[8];
    #pragma unroll
    for (int k = 0; k < 8; k++) acc[k] = 0.f;
    float t[8];

    int j = quarter;
    for (; j + 12 < c; j += 16) {
        int i0 = __ldg(&csr[s0 + j]);
        int i1 = __ldg(&csr[s0 + j + 4]);
        int i2 = __ldg(&csr[s0 + j + 8]);
        int i3 = __ldg(&csr[s0 + j + 12]);
        uint4 p0 = Y4[(size_t)i0 * 8 + q];
        uint4 p1 = Y4[(size_t)i1 * 8 + q];
        uint4 p2 = Y4[(size_t)i2 * 8 + q];
        uint4 p3 = Y4[(size_t)i3 * 8 + q];
        unpack8(p0, t);
        #pragma unroll
        for (int k = 0; k < 8; k++) acc[k] += t[k];
        unpack8(p1, t);
        #pragma unroll
        for (int k = 0; k < 8; k++) acc[k] += t[k];
        unpack8(p2, t);
        #pragma unroll
        for (int k = 0; k < 8; k++) acc[k] += t[k];
        unpack8(p3, t);
        #pragma unroll
        for (int k = 0; k < 8; k++) acc[k] += t[k];
    }
    for (; j < c; j += 4) {
        int i0 = __ldg(&csr[s0 + j]);
        uint4 p0 = Y4[(size_t)i0 * 8 + q];
        unpack8(p0, t);
        #pragma unroll
        for (int k = 0; k < 8; k++) acc[k] += t[k];
    }
    #pragma unroll
    for (int k = 0; k < 8; k++) {
        acc[k] += __shfl_xor_sync(0xffffffffu, acc[k], 8);
        acc[k] += __shfl_xor_sync(0xffffffffu, acc[k], 16);
    }

    const float s = invn[row];
    const float4* hrow = (const float4*)&h[(size_t)row * 64 + q * 8];
    float4 h0 = hrow[0], h1 = hrow[1];
    float4 bb0 = *(const float4*)&bb[q * 8];
    float4 bb1 = *(const float4*)&bb[q * 8 + 4];
    float x[8];
    x[0] = fmaf(acc[0], s, h0.x) + bb0.x;
    x[1] = fmaf(acc[1], s, h0.y) + bb0.y;
    x[2] = fmaf(acc[2], s, h0.z) + bb0.z;
    x[3] = fmaf(acc[3], s, h0.w) + bb0.w;
    x[4] = fmaf(acc[4], s, h1.x) + bb1.x;
    x[5] = fmaf(acc[5], s, h1.y) + bb1.y;
    x[6] = fmaf(acc[6], s, h1.z) + bb1.z;
    x[7] = fmaf(acc[7], s, h1.w) + bb1.w;

    float psum = 0.f;
    #pragma unroll
    for (int k = 0; k < 8; k++) psum += x[k];
    psum += __shfl_xor_sync(0xffffffffu, psum, 1);
    psum += __shfl_xor_sync(0xffffffffu, psum, 2);
    psum += __shfl_xor_sync(0xffffffffu, psum, 4);
    float mu = psum * (1.0f / 64.0f);
    float d[8], pvar = 0.f;
    #pragma unroll
    for (int k = 0; k < 8; k++) { d[k] = x[k] - mu; pvar += d[k] * d[k]; }
    pvar += __shfl_xor_sync(0xffffffffu, pvar, 1);
    pvar += __shfl_xor_sync(0xffffffffu, pvar, 2);
    pvar += __shfl_xor_sync(0xffffffffu, pvar, 4);
    float inv = rsqrtf(pvar * (1.0f / 64.0f) + 1e-5f);

    if (quarter == 0) {
        float4 g0 = *(const float4*)&g[q * 8];
        float4 g1 = *(const float4*)&g[q * 8 + 4];
        float4 e0 = *(const float4*)&b[q * 8];
        float4 e1 = *(const float4*)&b[q * 8 + 4];
        float o[8];
        o[0] = fmaf(d[0] * inv, g0.x, e0.x);
        o[1] = fmaf(d[1] * inv, g0.y, e0.y);
        o[2] = fmaf(d[2] * inv, g0.z, e0.z);
        o[3] = fmaf(d[3] * inv, g0.w, e0.w);
        o[4] = fmaf(d[4] * inv, g1.x, e1.x);
        o[5] = fmaf(d[5] * inv, g1.y, e1.y);
        o[6] = fmaf(d[6] * inv, g1.z, e1.z);
        o[7] = fmaf(d[7] * inv, g1.w, e1.w);
        float4* ho = (float4*)&h[(size_t)row * 64 + q * 8];
        ho[0] = make_float4(o[0], o[1], o[2], o[3]);
        ho[1] = make_float4(o[4], o[5], o[6], o[7]);
        uint4 p;
        p.x = pack_f16(o[0], o[1]);
        p.y = pack_f16(o[2], o[3]);
        p.z = pack_f16(o[4], o[5]);
        p.w = pack_f16(o[6], o[7]);
        *(uint4*)&hf16[(size_t)row * 64 + q * 8] = p;
    }
}

// ---------------- fused conv kernel: w = f(z@Wa) @ Wb -> fp16 ----------------
__global__ void __launch_bounds__(256, 2)
k_conv(const float* __restrict__ Z,
       const u16* __restrict__ WaHi_g, const u16* __restrict__ WaLo_g,
       const u16* __restrict__ WbHi_g, const u16* __restrict__ WbLo_g,
       const float* __restrict__ rs, const float* __restrict__ ba,
       u16* __restrict__ Wout16, int M) {
    constexpr int KP = 72;
    extern __shared__ __align__(16) u16 sm[];
    u16* Ahi = sm;
    u16* Alo = Ahi + 128 * KP;
    u16* BaH = Alo + 128 * KP;
    u16* BaL = BaH + 64 * KP;
    u16* BbH = BaL + 64 * KP;
    u16* BbL = BbH + 64 * KP;

    const int tid = threadIdx.x;
    const int wid = tid >> 5, lane = tid & 31;
    const int row0 = blockIdx.x * 128;

    for (int idx = tid; idx < 128 * 32; idx += 256) {
        int r = idx >> 5, kp = idx & 31, k = kp * 2;
        int gr = row0 + r;
        float a0 = 0.f, a1 = 0.f;
        if (gr < M) {
            float2 t = ((const float2*)Z)[(size_t)gr * 32 + kp];
            a0 = t.x; a1 = t.y;
        }
        uint32_t hi, lo; split2(a0, a1, hi, lo);
        *(uint32_t*)&Ahi[r * KP + k] = hi;
        *(uint32_t*)&Alo[r * KP + k] = lo;
    }
    for (int idx = tid; idx < 64 * 8; idx += 256) {
        int n = idx >> 3, k8 = idx & 7;
        *(uint4*)&BaH[n * KP + k8 * 8] = *(const uint4*)&WaHi_g[(size_t)n * 64 + k8 * 8];
        *(uint4*)&BaL[n * KP + k8 * 8] = *(const uint4*)&WaLo_g[(size_t)n * 64 + k8 * 8];
        *(uint4*)&BbH[n * KP + k8 * 8] = *(const uint4*)&WbHi_g[(size_t)n * 64 + k8 * 8];
        *(uint4*)&BbL[n * KP + k8 * 8] = *(const uint4*)&WbLo_g[(size_t)n * 64 + k8 * 8];
    }
    __syncthreads();

    const int wm = wid & 3, wn = wid >> 2;
    const int mrow = wm * 32;
    const int ncol = wn * 32;
    const uint32_t ahi_b = smem_u32(Ahi), alo_b = smem_u32(Alo);
    const int la  = lane & 15;
    const int lka = (lane >> 4) << 3;
    const int lbn = ((lane >> 4) << 3) + (lane & 7);
    const int lbk = ((lane >> 3) & 1) << 3;
    const int qr = lane >> 2;
    const int qc = (lane & 3) * 2;

    float acc[2][4][4];
    {
        const uint32_t bh_b = smem_u32(BaH), bl_b = smem_u32(BaL);
        #pragma unroll
        for (int i = 0; i < 2; i++)
            #pragma unroll
            for (int nf = 0; nf < 4; nf++)
                #pragma unroll
                for (int j = 0; j < 4; j++) acc[i][nf][j] = 0.f;
        #pragma unroll
        for (int kb = 0; kb < 64; kb += 16) {
            uint32_t ah[2][4], al[2][4];
            #pragma unroll
            for (int i = 0; i < 2; i++) {
                uint32_t aoff = (uint32_t)(((mrow + i * 16 + la) * KP + kb + lka) * 2);
                ldsm_x4(ah[i], ahi_b + aoff);
                ldsm_x4(al[i], alo_b + aoff);
            }
            #pragma unroll
            for (int nf = 0; nf < 4; nf += 2) {
                uint32_t boff = (uint32_t)(((ncol + nf * 8 + lbn) * KP + kb + lbk) * 2);
                uint32_t bh[4], bl[4];
                ldsm_x4(bh, bh_b + boff);
                ldsm_x4(bl, bl_b + boff);
                #pragma unroll
                for (int i = 0; i < 2; i++) {
                    mma16816<0>(acc[i][nf],     ah[i], bh);
                    mma16816<0>(acc[i][nf],     ah[i], bl);
                    mma16816<0>(acc[i][nf],     al[i], bh);
                    mma16816<0>(acc[i][nf + 1], ah[i], bh + 2);
                    mma16816<0>(acc[i][nf + 1], ah[i], bl + 2);
                    mma16816<0>(acc[i][nf + 1], al[i], bh + 2);
                }
            }
        }
    }
    __syncthreads();

    #pragma unroll
    for (int i = 0; i < 2; i++) {
        #pragma unroll
        for (int half = 0; half < 2; half++) {
            int rloc = mrow + i * 16 + half * 8 + qr;
            int gr = row0 + rloc;
            float s = (gr < M) ? rs[gr] : 0.f;
            #pragma unroll
            for (int nf = 0; nf < 4; nf++) {
                int c = ncol + nf * 8 + qc;
                float y0 = (acc[i][nf][half * 2 + 0] * s + ba[c]) * s;
                float y1 = (acc[i][nf][half * 2 + 1] * s + ba[c + 1]) * s;
                uint32_t hi, lo; split2(y0, y1, hi, lo);
                *(uint32_t*)&Ahi[rloc * KP + c] = hi;
                *(uint32_t*)&Alo[rloc * KP + c] = lo;
            }
        }
    }
    __syncthreads();

    {
        const uint32_t bh_b = smem_u32(BbH), bl_b = smem_u32(BbL);
        #pragma unroll
        for (int i = 0; i < 2; i++)
            #pragma unroll
            for (int nf = 0; nf < 4; nf++)
                #pragma unroll
                for (int j = 0; j < 4; j++) acc[i][nf][j] = 0.f;
        #pragma unroll
        for (int kb = 0; kb < 64; kb += 16) {
            uint32_t ah[2][4], al[2][4];
            #pragma unroll
            for (int i = 0; i < 2; i++) {
                uint32_t aoff = (uint32_t)(((mrow + i * 16 + la) * KP + kb + lka) * 2);
                ldsm_x4(ah[i], ahi_b + aoff);
                ldsm_x4(al[i], alo_b + aoff);
            }
            #pragma unroll
            for (int nf = 0; nf < 4; nf += 2) {
                uint32_t boff = (uint32_t)(((ncol + nf * 8 + lbn) * KP + kb + lbk) * 2);
                uint32_t bh[4], bl[4];
                ldsm_x4(bh, bh_b + boff);
                ldsm_x4(bl, bl_b + boff);
                #pragma unroll
                for (int i = 0; i < 2; i++) {
                    mma16816<0>(acc[i][nf],     ah[i], bh);
                    mma16816<0>(acc[i][nf],     ah[i], bl);
                    mma16816<0>(acc[i][nf],     al[i], bh);
                    mma16816<0>(acc[i][nf + 1], ah[i], bh + 2);
                    mma16816<0>(acc[i][nf + 1], ah[i], bl + 2);
                    mma16816<0>(acc[i][nf + 1], al[i], bh + 2);
                }
            }
        }
    }
    #pragma unroll
    for (int i = 0; i < 2; i++) {
        #pragma unroll
        for (int half = 0; half < 2; half++) {
            int gr = row0 + mrow + i * 16 + half * 8 + qr;
            if (gr < M) {
                #pragma unroll
                for (int nf = 0; nf < 4; nf++) {
                    int c = ncol + nf * 8 + qc;
                    ((uint32_t*)Wout16)[((size_t)gr * 64 + c) >> 1] =
                        pack_f16(acc[i][nf][half * 2 + 0], acc[i][nf][half * 2 + 1]);
                }
            }
        }
    }
}

// ------ fully fused FFN: h = LN(h + relu(hf16@W1+c1)@W2 + c2), T in smem -----
__global__ void __launch_bounds__(256, 2)
k_ffn_ln(const u16* __restrict__ hf16_in, const u16* __restrict__ W1hi_g,
         const u16* __restrict__ W2hi_g, const float* __restrict__ c1,
         const float* __restrict__ c2, const float* __restrict__ g,
         const float* __restrict__ b, float* __restrict__ h,
         u16* __restrict__ hf16_out, int M) {
    constexpr int KP = 72;
    constexpr int KP2 = 264;
    extern __shared__ __align__(16) u16 sm[];
    u16* As = sm;                  // 128 x 72
    u16* B1 = As + 128 * KP;       // 256 x 72
    u16* B2 = B1 + 256 * KP;       // 64 x 264
    u16* Tb = B2 + 64 * KP2;       // 128 x 72

    const int tid = threadIdx.x;
    const int wid = tid >> 5, lane = tid & 31;
    const int row0 = blockIdx.x * 128;
    const int wm = wid & 3, wn = wid >> 2;
    const int mrow = wm * 32;
    const int ncol = wn * 32;
    const int la  = lane & 15;
    const int lka = (lane >> 4) << 3;
    const int lbn = ((lane >> 4) << 3) + (lane & 7);
    const int lbk = ((lane >> 3) & 1) << 3;
    const int qr = lane >> 2;
    const int qc = (lane & 3) * 2;
    const uint4 z4 = make_uint4(0, 0, 0, 0);

    for (int idx = tid; idx < 128 * 8; idx += 256) {
        int r = idx >> 3, k8 = idx & 7;
        int gr = row0 + r;
        uint4 v = z4;
        if (gr < M) v = *(const uint4*)&hf16_in[(size_t)gr * 64 + k8 * 8];
        *(uint4*)&As[r * KP + k8 * 8] = v;
    }
    for (int idx = tid; idx < 256 * 8; idx += 256) {
        int n = idx >> 3, k8 = idx & 7;
        *(uint4*)&B1[n * KP + k8 * 8] = *(const uint4*)&W1hi_g[(size_t)n * 64 + k8 * 8];
    }
    for (int idx = tid; idx < 64 * 32; idx += 256) {
        int n = idx >> 5, k8 = idx & 31;
        *(uint4*)&B2[n * KP2 + k8 * 8] = *(const uint4*)&W2hi_g[(size_t)n * 256 + k8 * 8];
    }
    __syncthreads();

    const uint32_t as_b = smem_u32(As), b1_b = smem_u32(B1);
    const uint32_t b2_b = smem_u32(B2), tb_b = smem_u32(Tb);

    float uacc[2][4][4];
    #pragma unroll
    for (int i = 0; i < 2; i++)
        #pragma unroll
        for (int nf = 0; nf < 4; nf++)
            #pragma unroll
            for (int j = 0; j < 4; j++) uacc[i][nf][j] = 0.f;

    for (int chunk = 0; chunk < 4; chunk++) {
        const int cbase = chunk * 64;
        float tacc[2][4][4];
        #pragma unroll
        for (int i = 0; i < 2; i++)
            #pragma unroll
            for (int nf = 0; nf < 4; nf++)
                #pragma unroll
                for (int j = 0; j < 4; j++) tacc[i][nf][j] = 0.f;

        #pragma unroll
        for (int kb = 0; kb < 64; kb += 16) {
            uint32_t ah[2][4];
            #pragma unroll
            for (int i = 0; i < 2; i++) {
                uint32_t aoff = (uint32_t)(((mrow + i * 16 + la) * KP + kb + lka) * 2);
                ldsm_x4(ah[i], as_b + aoff);
            }
            #pragma unroll
            for (int nf = 0; nf < 4; nf += 2) {
                uint32_t boff = (uint32_t)(((cbase + ncol + nf * 8 + lbn) * KP + kb + lbk) * 2);
                uint32_t bh[4];
                ldsm_x4(bh, b1_b + boff);
                #pragma unroll
                for (int i = 0; i < 2; i++) {
                    mma16816<1>(tacc[i][nf],     ah[i], bh);
                    mma16816<1>(tacc[i][nf + 1], ah[i], bh + 2);
                }
            }
        }
        __syncthreads();
        #pragma unroll
        for (int i = 0; i < 2; i++) {
            #pragma unroll
            for (int half = 0; half < 2; half++) {
                int rloc = mrow + i * 16 + half * 8 + qr;
                #pragma unroll
                for (int nf = 0; nf < 4; nf++) {
                    int c = ncol + nf * 8 + qc;
                    float t0 = fmaxf(tacc[i][nf][half * 2 + 0] + c1[cbase + c], 0.f);
                    float t1 = fmaxf(tacc[i][nf][half * 2 + 1] + c1[cbase + c + 1], 0.f);
                    *(uint32_t*)&Tb[rloc * KP + c] = pack_f16(t0, t1);
                }
            }
        }
        __syncthreads();
        #pragma unroll
        for (int kb = 0; kb < 64; kb += 16) {
            uint32_t ah[2][4];
            #pragma unroll
            for (int i = 0; i < 2; i++) {
                uint32_t aoff = (uint32_t)(((mrow + i * 16 + la) * KP + kb + lka) * 2);
                ldsm_x4(ah[i], tb_b + aoff);
            }
            #pragma unroll
            for (int nf = 0; nf < 4; nf += 2) {
                uint32_t boff = (uint32_t)(((ncol + nf * 8 + lbn) * KP2 + cbase + kb + lbk) * 2);
                uint32_t bh[4];
                ldsm_x4(bh, b2_b + boff);
                #pragma unroll
                for (int i = 0; i < 2; i++) {
                    mma16816<1>(uacc[i][nf],     ah[i], bh);
                    mma16816<1>(uacc[i][nf + 1], ah[i], bh + 2);
                }
            }
        }
    }

    __syncthreads();
    float* xs = (float*)sm;
    #pragma unroll
    for (int i = 0; i < 2; i++) {
        #pragma unroll
        for (int half = 0; half < 2; half++) {
            int rloc = mrow + i * 16 + half * 8 + qr;
            int gr = row0 + rloc;
            #pragma unroll
            for (int nf = 0; nf < 4; nf++) {
                int c = ncol + nf * 8 + qc;
                float x0 = 0.f, x1 = 0.f;
                if (gr < M) {
                    float2 hres = *(const float2*)&h[(size_t)gr * 64 + c];
                    x0 = uacc[i][nf][half * 2 + 0] + c2[c] + hres.x;
                    x1 = uacc[i][nf][half * 2 + 1] + c2[c + 1] + hres.y;
                }
                xs[rloc * 72 + c]     = x0;
                xs[rloc * 72 + c + 1] = x1;
            }
        }
    }
    __syncthreads();

    const int c0 = lane * 2;
    for (int rr = 0; rr < 16; rr++) {
        int rloc = wid * 16 + rr;
        int gr = row0 + rloc;
        if (gr >= M) continue;
        float x0 = xs[rloc * 72 + c0];
        float x1 = xs[rloc * 72 + c0 + 1];
        float sum = x0 + x1;
        #pragma unroll
        for (int o = 16; o; o >>= 1) sum += __shfl_xor_sync(0xffffffffu, sum, o);
        float mu = sum * (1.0f / 64.0f);
        float d0 = x0 - mu, d1 = x1 - mu;
        float vs = d0 * d0 + d1 * d1;
        #pragma unroll
        for (int o = 16; o; o >>= 1) vs += __shfl_xor_sync(0xffffffffu, vs, o);
        float inv = rsqrtf(vs * (1.0f / 64.0f) + 1e-5f);
        float o0 = fmaf(d0 * inv, g[c0], b[c0]);
        float o1 = fmaf(d1 * inv, g[c0 + 1], b[c0 + 1]);
        *(float2*)&h[(size_t)gr * 64 + c0] = make_float2(o0, o1);
        ((uint32_t*)hf16_out)[((size_t)gr * 64 + c0) >> 1] = pack_f16(o0, o1);
    }
}

// ------- final projection with fused LayerNorm (3-term bf16, exact-ish) ------
__global__ void __launch_bounds__(256, 2)
k_proj_ln(const float* __restrict__ h, const float* __restrict__ gF,
          const float* __restrict__ bF,
          const u16* __restrict__ WoHi_g, const u16* __restrict__ WoLo_g,
          const float* __restrict__ bo, float* __restrict__ out, int M) {
    constexpr int KP = 72;
    extern __shared__ __align__(16) u16 sm[];
    u16* Ahi = sm;
    u16* Alo = Ahi + 128 * KP;
    u16* Bhi = Alo + 128 * KP;
    u16* Blo = Bhi + 64 * KP;

    const int tid = threadIdx.x;
    const int wid = tid >> 5, lane = tid & 31;
    const int row0 = blockIdx.x * 128;

    // B fill
    for (int idx = tid; idx < 64 * 8; idx += 256) {
        int n = idx >> 3, k8 = idx & 7;
        *(uint4*)&Bhi[n * KP + k8 * 8] = *(const uint4*)&WoHi_g[(size_t)n * 64 + k8 * 8];
        *(uint4*)&Blo[n * KP + k8 * 8] = *(const uint4*)&WoLo_g[(size_t)n * 64 + k8 * 8];
    }
    // A fill with LayerNorm fused (warp per row, lane covers cols lane*2, lane*2+1)
    const int c0 = lane * 2;
    for (int rr = 0; rr < 16; rr++) {
        int rloc = wid * 16 + rr;
        int gr = row0 + rloc;
        float x0 = 0.f, x1 = 0.f;
        if (gr < M) {
            float2 t = *(const float2*)&h[(size_t)gr * 64 + c0];
            x0 = t.x; x1 = t.y;
        }
        float sum = x0 + x1;
        #pragma unroll
        for (int o = 16; o; o >>= 1) sum += __shfl_xor_sync(0xffffffffu, sum, o);
        float mu = sum * (1.0f / 64.0f);
        float d0 = x0 - mu, d1 = x1 - mu;
        float vs = d0 * d0 + d1 * d1;
        #pragma unroll
        for (int o = 16; o; o >>= 1) vs += __shfl_xor_sync(0xffffffffu, vs, o);
        float inv = rsqrtf(vs * (1.0f / 64.0f) + 1e-5f);
        float o0 = 0.f, o1 = 0.f;
        if (gr < M) {
            o0 = fmaf(d0 * inv, gF[c0], bF[c0]);
            o1 = fmaf(d1 * inv, gF[c0 + 1], bF[c0 + 1]);
        }
        uint32_t hi, lo; split2(o0, o1, hi, lo);
        *(uint32_t*)&Ahi[rloc * KP + c0] = hi;
        *(uint32_t*)&Alo[rloc * KP + c0] = lo;
    }
    __syncthreads();

    const int wm = wid & 3, wn = wid >> 2;
    const int mrow = wm * 32;
    const int ncol = wn * 32;
    const uint32_t ahi_b = smem_u32(Ahi), alo_b = smem_u32(Alo);
    const uint32_t bhi_b = smem_u32(Bhi), blo_b = smem_u32(Blo);
    const int la  = lane & 15;
    const int lka = (lane >> 4) << 3;
    const int lbn = ((lane >> 4) << 3) + (lane & 7);
    const int lbk = ((lane >> 3) & 1) << 3;

    float acc[2][4][4];
    #pragma unroll
    for (int i = 0; i < 2; i++)
        #pragma unroll
        for (int nf = 0; nf < 4; nf++)
            #pragma unroll
            for (int j = 0; j < 4; j++) acc[i][nf][j] = 0.f;

    #pragma unroll
    for (int kb = 0; kb < 64; kb += 16) {
        uint32_t ah[2][4], al[2][4];
        #pragma unroll
        for (int i = 0; i < 2; i++) {
            uint32_t aoff = (uint32_t)(((mrow + i * 16 + la) * KP + kb + lka) * 2);
            ldsm_x4(ah[i], ahi_b + aoff);
            ldsm_x4(al[i], alo_b + aoff);
        }
        #pragma unroll
        for (int nf = 0; nf < 4; nf += 2) {
            uint32_t boff = (uint32_t)(((ncol + nf * 8 + lbn) * KP + kb + lbk) * 2);
            uint32_t bh[4], bl[4];
            ldsm_x4(bh, bhi_b + boff);
            ldsm_x4(bl, blo_b + boff);
            #pragma unroll
            for (int i = 0; i < 2; i++) {
                mma16816<0>(acc[i][nf],     ah[i], bh);
                mma16816<0>(acc[i][nf],     ah[i], bl);
                mma16816<0>(acc[i][nf],     al[i], bh);
                mma16816<0>(acc[i][nf + 1], ah[i], bh + 2);
                mma16816<0>(acc[i][nf + 1], ah[i], bl + 2);
                mma16816<0>(acc[i][nf + 1], al[i], bh + 2);
            }
        }
    }

    const int qr = lane >> 2;
    const int qc = (lane & 3) * 2;
    #pragma unroll
    for (int i = 0; i < 2; i++) {
        #pragma unroll
        for (int half = 0; half < 2; half++) {
            int gr = row0 + mrow + i * 16 + half * 8 + qr;
            if (gr < M) {
                #pragma unroll
                for (int nf = 0; nf < 4; nf++) {
                    int c = ncol + nf * 8 + qc;
                    float v0 = acc[i][nf][half * 2 + 0] + bo[c];
                    float v1 = acc[i][nf][half * 2 + 1] + bo[c + 1];
                    *(float2*)&out[(size_t)gr * 64 + c] = make_float2(v0, v1);
                }
            }
        }
    }
}

// ---------------- orchestration ----------------------------------------------
extern "C" void kernel_launch(void* const* d_in, const int* in_sizes, int n_in,
                              void* d_out, int out_size) {
    const float* x    = (const float*)d_in[0];
    const int*   esrc = (const int*)d_in[1];
    const int*   edst = (const int*)d_in[2];
    const int wi = (n_in >= 20) ? 4 : 3;
    const float* Wn2h = (const float*)d_in[wi + 0];
    const float* bn2h = (const float*)d_in[wi + 1];
    const float* Wh2n = (const float*)d_in[wi + 2];
    const float* bh2n = (const float*)d_in[wi + 3];
    const float* W1   = (const float*)d_in[wi + 4];
    const float* b1   = (const float*)d_in[wi + 5];
    const float* W2   = (const float*)d_in[wi + 6];
    const float* b2   = (const float*)d_in[wi + 7];
    const float* g1   = (const float*)d_in[wi + 8];
    const float* be1  = (const float*)d_in[wi + 9];
    const float* g2   = (const float*)d_in[wi + 10];
    const float* be2  = (const float*)d_in[wi + 11];
    const float* gF   = (const float*)d_in[wi + 12];
    const float* bF   = (const float*)d_in[wi + 13];
    const float* Wo   = (const float*)d_in[wi + 14];
    const float* bo   = (const float*)d_in[wi + 15];

    float *p_h, *p_ha, *p_invn, *p_invh;
    u16 *p_hf16, *p_wf16;
    u16 *p_wa_hi, *p_wa_lo, *p_wb_hi, *p_wb_lo, *p_w1_hi, *p_w2_hi, *p_wo_hi, *p_wo_lo;
    int *p_cntH, *p_cntN, *p_stH, *p_stN, *p_cuH, *p_cuN, *p_csrH, *p_csrN;
    int *p_bsN, *p_boN, *p_bsH, *p_boH;
    cudaGetSymbolAddress((void**)&p_h,    g_h);
    cudaGetSymbolAddress((void**)&p_hf16, g_hf16);
    cudaGetSymbolAddress((void**)&p_ha,   g_ha);
    cudaGetSymbolAddress((void**)&p_wf16, g_wf16);
    cudaGetSymbolAddress((void**)&p_wa_hi, g_wa_hi);
    cudaGetSymbolAddress((void**)&p_wa_lo, g_wa_lo);
    cudaGetSymbolAddress((void**)&p_wb_hi, g_wb_hi);
    cudaGetSymbolAddress((void**)&p_wb_lo, g_wb_lo);
    cudaGetSymbolAddress((void**)&p_w1_hi, g_w1_hi);
    cudaGetSymbolAddress((void**)&p_w2_hi, g_w2_hi);
    cudaGetSymbolAddress((void**)&p_wo_hi, g_wo_hi);
    cudaGetSymbolAddress((void**)&p_wo_lo, g_wo_lo);
    cudaGetSymbolAddress((void**)&p_invn, g_invn);
    cudaGetSymbolAddress((void**)&p_invh, g_invh);
    cudaGetSymbolAddress((void**)&p_cntH, g_cntH);
    cudaGetSymbolAddress((void**)&p_cntN, g_cntN);
    cudaGetSymbolAddress((void**)&p_stH,  g_startH);
    cudaGetSymbolAddress((void**)&p_stN,  g_startN);
    cudaGetSymbolAddress((void**)&p_cuH,  g_curH);
    cudaGetSymbolAddress((void**)&p_cuN,  g_curN);
    cudaGetSymbolAddress((void**)&p_csrH, g_csrH);
    cudaGetSymbolAddress((void**)&p_csrN, g_csrN);
    cudaGetSymbolAddress((void**)&p_bsN, g_bsumN);
    cudaGetSymbolAddress((void**)&p_boN, g_boffN);
    cudaGetSymbolAddress((void**)&p_bsH, g_bsumH);
    cudaGetSymbolAddress((void**)&p_boH, g_boffH);

    const int smem_convf = (2 * 128 * 72 + 4 * 64 * 72) * 2;                 //  73728
    const int smem_ffn   = (128 * 72 + 256 * 72 + 64 * 264 + 128 * 72) * 2;  // 107520
    const int smem_proj  = (2 * 128 * 72 + 2 * 64 * 72) * 2;                 //  55296
    cudaFuncSetAttribute((const void*)k_conv, cudaFuncAttributeMaxDynamicSharedMemorySize, smem_convf);
    cudaFuncSetAttribute((const void*)k_ffn_ln, cudaFuncAttributeMaxDynamicSharedMemorySize, smem_ffn);
    cudaFuncSetAttribute((const void*)k_proj_ln, cudaFuncAttributeMaxDynamicSharedMemorySize, smem_proj);

    cudaMemcpyAsync(p_h, x, (size_t)NN * DD * sizeof(float), cudaMemcpyDeviceToDevice);

    // ---- one-shot prep: all weight splits + h fp16 copy ----
    k_prep_all<<<(TPREP + 255) / 256, 256>>>(
        Wn2h, Wh2n, W1, W2, Wo, x,
        p_wa_hi, p_wa_lo, p_wb_hi, p_wb_lo, p_w1_hi, p_w2_hi, p_wo_hi, p_wo_lo, p_hf16);

    // ---- build CSR + degree norms (consolidated launches) ----
    const int nbN = (NN + 1023) / 1024;   // 98
    const int nbH = (HH + 1023) / 1024;   // 20
    k_zero4<<<256, 256>>>(p_cntN, NN, p_cntH, HH, p_cuN, NN, p_cuH, HH);
    k_hist<<<(EE + 255) / 256, 256>>>(esrc, edst, p_cntN, p_cntH);
    k_bsum2<<<nbN + nbH, 1024>>>(p_cntN, p_bsN, nbN, p_cntH, p_bsH);
    k_scanboth<<<2, 1024>>>(p_bsN, p_boN, nbN, p_bsH, p_boH, nbH);
    k_scan2inv<<<nbN + nbH, 1024>>>(p_cntN, p_boN, p_stN, p_invn, nbN,
                                    p_cntH, p_boH, p_stH, p_invh);
    k_fill<<<(EE + 255) / 256, 256>>>(esrc, edst, p_stH, p_stN, p_cuH, p_cuN, p_csrH, p_csrN);

    const int gN  = (NN + 127) / 128;
    const int gH  = (HH + 127) / 128;
    const int gAgH = (HH + 7) / 8;
    const int gAgN = (NN + 7) / 8;

    for (int l = 0; l < LL; l++) {
        const float* ba = bn2h + (size_t)l * DD;
        const float* bb = bh2n + (size_t)l * DD;
        const float* c1 = b1 + (size_t)l * FF;
        const float* c2 = b2 + (size_t)l * DD;
        const float* gg1 = g1 + (size_t)l * DD;
        const float* ee1 = be1 + (size_t)l * DD;
        const float* gg2 = g2 + (size_t)l * DD;
        const float* ee2 = be2 + (size_t)l * DD;

        // z = agg_H(hf16 * invn[src])
        k_agg16<<<gAgH, 256>>>(p_hf16, p_csrH, p_stH, p_cntH, p_invn, p_ha, HH);
        // fused: y = (z@Wa*invh+ba)*invh ; w = y@Wb -> fp16
        k_conv<<<gH, 256, smem_convf>>>(
            p_ha, p_wa_hi + (size_t)l * DD * DD, p_wa_lo + (size_t)l * DD * DD,
            p_wb_hi + (size_t)l * DD * DD, p_wb_lo + (size_t)l * DD * DD,
            p_invh, ba, p_wf16, HH);
        // fused: u = agg_N(wf16); h = LN(h + u*invn + bb) -> h fp32 + fp16
        k_agg_ln16<<<gAgN, 256>>>(p_wf16, p_csrN, p_stN, p_cntN, p_invn, bb,
                                  gg1, ee1, p_h, p_hf16, NN);
        // fully fused FFN + residual + LN2 (T never leaves smem)
        k_ffn_ln<<<gN, 256, smem_ffn>>>(
            p_hf16, p_w1_hi + (size_t)l * DD * FF, p_w2_hi + (size_t)l * FF * DD,
            c1, c2, gg2, ee2, p_h, p_hf16, NN);
    }

    // final LN fused into projection
    k_proj_ln<<<gN, 256, smem_proj>>>(p_h, gF, bF, p_wo_hi, p_wo_lo, bo,
                                      (float*)d_out, NN);
}